// round 2
// baseline (speedup 1.0000x reference)
#include <cuda_runtime.h>
#include <cstdint>
#include <cmath>

// ---------------------------------------------------------------------------
// SSA forward. All threshold-feeding arithmetic (GEMM, LayerNorm, LIF membrane)
// is done in fp64 so our pre-threshold values are effectively exact; the only
// spike disagreements left vs the fp32 JAX reference are where the reference's
// OWN rounding crosses a threshold (expected ~0 elements).
// The attention block (binary q,k,v) is exact in fp32: attn = popcount/8 and
// y = attn @ v are dyadic rationals with < 19 mantissa bits.
// ---------------------------------------------------------------------------

#define T_  4
#define B_  64
#define L_  200
#define H_  256
#define M_  (T_*B_*L_)      // 51200
#define BLr (B_*L_)         // 12800
#define NBATCH (T_*B_*2)    // 512 (t,b,head)

// static device scratch (no runtime allocation allowed)
__device__ double   g_xd[(size_t)M_*H_];       // x in double
__device__ double   g_wd[4u*H_*H_];            // qw,kw,vw,pw in double
__device__ double   g_Z [(size_t)M_*H_];       // one branch pre-LN at a time
__device__ double   g_zp[(size_t)M_*H_];       // proj pre-LN
__device__ double   g_s2[(size_t)M_*H_];       // attn-LIF spikes (0/1)
__device__ uint32_t g_qb[NBATCH*L_*4];
__device__ uint32_t g_kb[NBATCH*L_*4];
__device__ float    g_vf[(size_t)NBATCH*L_*128];
__device__ float    g_y [(size_t)NBATCH*L_*128];

// ---------------------------------------------------------------------------
__global__ void f2d_kernel(const float* __restrict__ src, double* __restrict__ dst, int n)
{
    int i = blockIdx.x * blockDim.x + threadIdx.x;
    int stride = gridDim.x * blockDim.x;
    for (; i < n; i += stride) dst[i] = (double)src[i];
}

// ---------------------------------------------------------------------------
// C[M,256] = A[M,256] @ W[256,256]^T (+bias), fp64. 64x64 tile, 4x4/thread.
// ---------------------------------------------------------------------------
__global__ void __launch_bounds__(256) dgemm_kernel(
    const double* __restrict__ A, const double* __restrict__ W,
    const float* __restrict__ bias, double* __restrict__ C)
{
    __shared__ double As[16][68];
    __shared__ double Ws[16][68];
    const int tid  = threadIdx.x;
    const int row0 = blockIdx.x * 64;
    const int col0 = blockIdx.y * 64;
    const int lr = tid >> 2;            // 0..63
    const int lk = (tid & 3) << 2;      // 0,4,8,12
    const int tx = (tid & 15) << 2;     // 0..60
    const int ty = (tid >> 4) << 2;     // 0..60

    double acc[4][4];
    #pragma unroll
    for (int i = 0; i < 4; i++)
        #pragma unroll
        for (int j = 0; j < 4; j++) acc[i][j] = 0.0;

    for (int k0 = 0; k0 < 256; k0 += 16) {
        double2 a0 = *(const double2*)(A + (size_t)(row0 + lr) * 256 + k0 + lk);
        double2 a1 = *(const double2*)(A + (size_t)(row0 + lr) * 256 + k0 + lk + 2);
        double2 w0 = *(const double2*)(W + (size_t)(col0 + lr) * 256 + k0 + lk);
        double2 w1 = *(const double2*)(W + (size_t)(col0 + lr) * 256 + k0 + lk + 2);
        As[lk+0][lr] = a0.x; As[lk+1][lr] = a0.y; As[lk+2][lr] = a1.x; As[lk+3][lr] = a1.y;
        Ws[lk+0][lr] = w0.x; Ws[lk+1][lr] = w0.y; Ws[lk+2][lr] = w1.x; Ws[lk+3][lr] = w1.y;
        __syncthreads();
        #pragma unroll
        for (int kk = 0; kk < 16; kk++) {
            double a[4], w[4];
            #pragma unroll
            for (int i = 0; i < 4; i++) a[i] = As[kk][ty + i];
            #pragma unroll
            for (int j = 0; j < 4; j++) w[j] = Ws[kk][tx + j];
            #pragma unroll
            for (int i = 0; i < 4; i++)
                #pragma unroll
                for (int j = 0; j < 4; j++) acc[i][j] += a[i] * w[j];
        }
        __syncthreads();
    }

    #pragma unroll
    for (int i = 0; i < 4; i++) {
        size_t r = (size_t)(row0 + ty + i) * 256 + col0 + tx;
        #pragma unroll
        for (int j = 0; j < 4; j++) {
            double o = acc[i][j];
            if (bias) o += (double)bias[col0 + tx + j];
            C[r + j] = o;
        }
    }
}

// ---------------------------------------------------------------------------
__device__ __forceinline__ double dblock_sum256(double v, double* red, double* bc)
{
    const int lane = threadIdx.x & 31, warp = threadIdx.x >> 5;
    #pragma unroll
    for (int o = 16; o; o >>= 1) v += __shfl_xor_sync(0xffffffffu, v, o);
    if (lane == 0) red[warp] = v;
    __syncthreads();
    if (warp == 0) {
        double s = (lane < 8) ? red[lane] : 0.0;
        s += __shfl_xor_sync(0xffffffffu, s, 4);
        s += __shfl_xor_sync(0xffffffffu, s, 2);
        s += __shfl_xor_sync(0xffffffffu, s, 1);
        if (lane == 0) *bc = s;
    }
    __syncthreads();
    return *bc;
}

// ---------------------------------------------------------------------------
// LN -> LIF(th=1) over T for one branch (fp64). Pack bits (q/k) or store v fp32.
// block = (b,l), thread = h
// ---------------------------------------------------------------------------
__global__ void __launch_bounds__(256) ln_lif_branch_kernel(
    const double* __restrict__ Z, const float* __restrict__ lw,
    const float* __restrict__ lb, uint32_t* __restrict__ bits,
    float* __restrict__ vf)
{
    __shared__ double red[8];
    __shared__ double bc;
    const int bl = blockIdx.x;
    const int b = bl / L_, l = bl % L_;
    const int h = threadIdx.x;
    const int lane = h & 31, warp = h >> 5;
    const int head = h >> 7, d = h & 127;
    const double wv = (double)lw[h], bv = (double)lb[h];

    double vmem = 0.0;
    for (int t = 0; t < T_; t++) {
        size_t row = (size_t)(t * B_ + b) * L_ + l;
        double xv = Z[row * H_ + h];
        double mean = dblock_sum256(xv, red, &bc) * (1.0 / H_);
        double dv = xv - mean;
        double var = dblock_sum256(dv * dv, red, &bc) * (1.0 / H_);
        double yv = dv / sqrt(var + 1e-5) * wv + bv;
        vmem = vmem + (yv - vmem) * 0.5;
        bool sp = (vmem - 1.0) >= 0.0;
        if (sp) vmem = 0.0;
        if (vf) {
            vf[(((size_t)(t * B_ + b) * 2 + head) * L_ + l) * 128 + d] = sp ? 1.f : 0.f;
        } else {
            uint32_t ball = __ballot_sync(0xffffffffu, sp);
            if (lane == 0)
                bits[(((size_t)(t * B_ + b) * 2 + head) * L_ + l) * 4 + (warp & 3)] = ball;
        }
    }
}

// ---------------------------------------------------------------------------
// attn = popc(q&k)*0.125 ; y = attn @ v  (exact fp32)
// ---------------------------------------------------------------------------
#define ATTN_SMEM ((L_*128 + 8*L_*4)*4 + L_*4*4)   // 131200 bytes

__global__ void __launch_bounds__(256) attn_kernel(
    const uint32_t* __restrict__ qb, const uint32_t* __restrict__ kb,
    const float* __restrict__ vf, float* __restrict__ y)
{
    extern __shared__ char smem_raw[];
    float*    sv    = (float*)smem_raw;           // [200][128]
    uint32_t* skb   = (uint32_t*)(sv + L_ * 128); // [200][4]
    float*    sattn = (float*)(skb + L_ * 4);     // [8][200][4]

    const int batch = blockIdx.x;
    const uint32_t* qb_b = qb + (size_t)batch * L_ * 4;
    const uint32_t* kb_b = kb + (size_t)batch * L_ * 4;
    const float*    v_b  = vf + (size_t)batch * L_ * 128;
    float*          y_b  = y  + (size_t)batch * L_ * 128;

    const int tid = threadIdx.x;
    for (int i = tid; i < L_ * 4; i += 256) skb[i] = kb_b[i];
    for (int i = tid; i < L_ * 32; i += 256) ((float4*)sv)[i] = ((const float4*)v_b)[i];
    __syncthreads();

    const int warp = tid >> 5, lane = tid & 31;
    float* aw = sattn + warp * (L_ * 4);
    const float* svl = sv + lane * 4;

    for (int base = warp * 4; base < L_; base += 32) {
        #pragma unroll
        for (int r = 0; r < 4; r++) {
            const int lrow = base + r;
            uint32_t q0 = qb_b[lrow*4+0], q1 = qb_b[lrow*4+1];
            uint32_t q2 = qb_b[lrow*4+2], q3 = qb_b[lrow*4+3];
            for (int m = lane; m < L_; m += 32) {
                int c = __popc(q0 & skb[m*4+0]) + __popc(q1 & skb[m*4+1])
                      + __popc(q2 & skb[m*4+2]) + __popc(q3 & skb[m*4+3]);
                aw[m*4 + r] = (float)c * 0.125f;
            }
        }
        __syncwarp();
        float4 acc0 = {0,0,0,0}, acc1 = {0,0,0,0}, acc2 = {0,0,0,0}, acc3 = {0,0,0,0};
        #pragma unroll 4
        for (int m = 0; m < L_; m++) {
            float4 a  = *(const float4*)(aw  + m * 4);
            float4 vv = *(const float4*)(svl + m * 128);
            acc0.x += a.x*vv.x; acc0.y += a.x*vv.y; acc0.z += a.x*vv.z; acc0.w += a.x*vv.w;
            acc1.x += a.y*vv.x; acc1.y += a.y*vv.y; acc1.z += a.y*vv.z; acc1.w += a.y*vv.w;
            acc2.x += a.z*vv.x; acc2.y += a.z*vv.y; acc2.z += a.z*vv.z; acc2.w += a.z*vv.w;
            acc3.x += a.w*vv.x; acc3.y += a.w*vv.y; acc3.z += a.w*vv.z; acc3.w += a.w*vv.w;
        }
        *(float4*)(y_b + (size_t)(base + 0) * 128 + lane * 4) = acc0;
        *(float4*)(y_b + (size_t)(base + 1) * 128 + lane * 4) = acc1;
        *(float4*)(y_b + (size_t)(base + 2) * 128 + lane * 4) = acc2;
        *(float4*)(y_b + (size_t)(base + 3) * 128 + lane * 4) = acc3;
        __syncwarp();
    }
}

// ---------------------------------------------------------------------------
// attn LIF (th=0.5) over T; exact in fp32; write double spikes for proj GEMM
// ---------------------------------------------------------------------------
__global__ void __launch_bounds__(256) attn_lif_kernel(
    const float* __restrict__ y, double* __restrict__ s2)
{
    const int bl = blockIdx.x;
    const int b = bl / L_, l = bl % L_;
    const int h = threadIdx.x;
    const int head = h >> 7, d = h & 127;
    float vmem = 0.f;
    #pragma unroll
    for (int t = 0; t < T_; t++) {
        float yv = y[(((size_t)(t * B_ + b) * 2 + head) * L_ + l) * 128 + d];
        vmem = vmem + (yv - vmem) * 0.5f;
        bool sp = (vmem - 0.5f) >= 0.f;
        if (sp) vmem = 0.f;
        s2[((size_t)(t * B_ + b) * L_ + l) * H_ + h] = sp ? 1.0 : 0.0;
    }
}

// ---------------------------------------------------------------------------
// proj LN -> LIF(th=1) -> output spikes (fp64 decisions)
// ---------------------------------------------------------------------------
__global__ void __launch_bounds__(256) proj_ln_lif_kernel(
    const double* __restrict__ Zp, const float* __restrict__ lw,
    const float* __restrict__ lb, float* __restrict__ out)
{
    __shared__ double red[8];
    __shared__ double bc;
    const int bl = blockIdx.x;
    const int b = bl / L_, l = bl % L_;
    const int h = threadIdx.x;
    const double wv = (double)lw[h], bv = (double)lb[h];
    double vmem = 0.0;
    for (int t = 0; t < T_; t++) {
        size_t row = (size_t)(t * B_ + b) * L_ + l;
        double xv = Zp[row * H_ + h];
        double mean = dblock_sum256(xv, red, &bc) * (1.0 / H_);
        double dv = xv - mean;
        double var = dblock_sum256(dv * dv, red, &bc) * (1.0 / H_);
        double yv = dv / sqrt(var + 1e-5) * wv + bv;
        vmem = vmem + (yv - vmem) * 0.5;
        bool sp = (vmem - 1.0) >= 0.0;
        if (sp) vmem = 0.0;
        out[row * H_ + h] = sp ? 1.f : 0.f;
    }
}

// ---------------------------------------------------------------------------
extern "C" void kernel_launch(void* const* d_in, const int* in_sizes, int n_in,
                              void* d_out, int out_size)
{
    const float* x   = (const float*)d_in[0];
    const float* qw  = (const float*)d_in[1];
    const float* qlw = (const float*)d_in[2];
    const float* qlb = (const float*)d_in[3];
    const float* kw  = (const float*)d_in[4];
    const float* klw = (const float*)d_in[5];
    const float* klb = (const float*)d_in[6];
    const float* vw  = (const float*)d_in[7];
    const float* vlw = (const float*)d_in[8];
    const float* vlb = (const float*)d_in[9];
    const float* pw  = (const float*)d_in[10];
    const float* pb  = (const float*)d_in[11];
    const float* plw = (const float*)d_in[12];
    const float* plb = (const float*)d_in[13];
    float* out = (float*)d_out;

    double *xd, *wd, *Z, *zp, *s2;
    float *vf, *yv;
    uint32_t *qbp, *kbp;
    cudaGetSymbolAddress((void**)&xd,  g_xd);
    cudaGetSymbolAddress((void**)&wd,  g_wd);
    cudaGetSymbolAddress((void**)&Z,   g_Z);
    cudaGetSymbolAddress((void**)&zp,  g_zp);
    cudaGetSymbolAddress((void**)&s2,  g_s2);
    cudaGetSymbolAddress((void**)&vf,  g_vf);
    cudaGetSymbolAddress((void**)&yv,  g_y);
    cudaGetSymbolAddress((void**)&qbp, g_qb);
    cudaGetSymbolAddress((void**)&kbp, g_kb);

    // convert inputs to double
    f2d_kernel<<<2048, 256>>>(x, xd, M_ * H_);
    f2d_kernel<<<64, 256>>>(qw, wd + 0ull * H_ * H_, H_ * H_);
    f2d_kernel<<<64, 256>>>(kw, wd + 1ull * H_ * H_, H_ * H_);
    f2d_kernel<<<64, 256>>>(vw, wd + 2ull * H_ * H_, H_ * H_);
    f2d_kernel<<<64, 256>>>(pw, wd + 3ull * H_ * H_, H_ * H_);

    dim3 gg(M_ / 64, 4);  // (800, 4)

    // q branch
    dgemm_kernel<<<gg, 256>>>(xd, wd + 0ull * H_ * H_, nullptr, Z);
    ln_lif_branch_kernel<<<BLr, 256>>>(Z, qlw, qlb, qbp, nullptr);
    // k branch
    dgemm_kernel<<<gg, 256>>>(xd, wd + 1ull * H_ * H_, nullptr, Z);
    ln_lif_branch_kernel<<<BLr, 256>>>(Z, klw, klb, kbp, nullptr);
    // v branch
    dgemm_kernel<<<gg, 256>>>(xd, wd + 2ull * H_ * H_, nullptr, Z);
    ln_lif_branch_kernel<<<BLr, 256>>>(Z, vlw, vlb, nullptr, vf);

    cudaFuncSetAttribute(attn_kernel, cudaFuncAttributeMaxDynamicSharedMemorySize, ATTN_SMEM);
    attn_kernel<<<NBATCH, 256, ATTN_SMEM>>>(qbp, kbp, vf, yv);

    attn_lif_kernel<<<BLr, 256>>>(yv, s2);

    dgemm_kernel<<<gg, 256>>>(s2, wd + 3ull * H_ * H_, pb, zp);

    proj_ln_lif_kernel<<<BLr, 256>>>(zp, plw, plb, out);
}

// round 3
// speedup vs baseline: 4.6447x; 4.6447x over previous
#include <cuda_runtime.h>
#include <cstdint>
#include <cmath>

// ---------------------------------------------------------------------------
// SSA forward, exact-integer GEMM edition.
// GEMMs: inputs quantized (x*2^27, w*2^32 -> int32, exact fp64 quantize),
// accumulated EXACTLY in int64 (IMAD.WIDE), scaled back in fp64.
// Injected error = quantization only (~4e-9 abs) << reference fp32 rounding
// (~1e-7), so spike thresholds match the reference (rel_err 0 as in R2).
// LayerNorm + LIF membranes stay fp64. Attention block (binary q,k,v) is
// exact in fp32 (popcount / dyadic rationals).
// ---------------------------------------------------------------------------

#define T_  4
#define B_  64
#define L_  200
#define H_  256
#define M_  (T_*B_*L_)      // 51200
#define BLr (B_*L_)         // 12800
#define NBATCH (T_*B_*2)    // 512 (t,b,head)

// static device scratch (no runtime allocation allowed)
__device__ int      g_xq[(size_t)M_*H_];       // x quantized (*2^27)
__device__ int      g_wq[4u*H_*H_];            // qw,kw,vw,pw quantized (*2^32)
__device__ int      g_s2[(size_t)M_*H_];       // attn-LIF spikes {0,1} as int
__device__ double   g_Z [(size_t)M_*H_];       // one branch pre-LN at a time
__device__ double   g_zp[(size_t)M_*H_];       // proj pre-LN
__device__ uint32_t g_qb[NBATCH*L_*4];
__device__ uint32_t g_kb[NBATCH*L_*4];
__device__ float    g_vf[(size_t)NBATCH*L_*128];
__device__ float    g_y [(size_t)NBATCH*L_*128];

// ---------------------------------------------------------------------------
// quantize: dst = rint((double)src * scale)  (exact multiply in fp64)
// ---------------------------------------------------------------------------
__global__ void quant_kernel(const float* __restrict__ src, int* __restrict__ dst,
                             double scale, int n)
{
    int i = blockIdx.x * blockDim.x + threadIdx.x;
    int stride = gridDim.x * blockDim.x;
    for (; i < n; i += stride)
        dst[i] = __double2int_rn((double)src[i] * scale);
}

// ---------------------------------------------------------------------------
// C[M,256] = (A[M,256] @ W[256,256]^T) * inv (+bias), exact int64 accumulate.
// 64x64 tile, 4x4 per thread, 256 threads.
// ---------------------------------------------------------------------------
__global__ void __launch_bounds__(256) igemm_kernel(
    const int* __restrict__ A, const int* __restrict__ W,
    const float* __restrict__ bias, double* __restrict__ C, double inv)
{
    __shared__ int As[16][72];
    __shared__ int Ws[16][72];
    const int tid  = threadIdx.x;
    const int row0 = blockIdx.x * 64;
    const int col0 = blockIdx.y * 64;
    const int lr = tid >> 2;            // 0..63
    const int lk = (tid & 3) << 2;      // 0,4,8,12
    const int tx = (tid & 15) << 2;     // 0..60
    const int ty = (tid >> 4) << 2;     // 0..60

    long long acc[4][4];
    #pragma unroll
    for (int i = 0; i < 4; i++)
        #pragma unroll
        for (int j = 0; j < 4; j++) acc[i][j] = 0ll;

    for (int k0 = 0; k0 < 256; k0 += 16) {
        int4 a0 = *(const int4*)(A + (size_t)(row0 + lr) * 256 + k0 + lk);
        int4 w0 = *(const int4*)(W + (size_t)(col0 + lr) * 256 + k0 + lk);
        As[lk+0][lr] = a0.x; As[lk+1][lr] = a0.y; As[lk+2][lr] = a0.z; As[lk+3][lr] = a0.w;
        Ws[lk+0][lr] = w0.x; Ws[lk+1][lr] = w0.y; Ws[lk+2][lr] = w0.z; Ws[lk+3][lr] = w0.w;
        __syncthreads();
        #pragma unroll
        for (int kk = 0; kk < 16; kk++) {
            int a[4], w[4];
            *(int4*)&a[0] = *(const int4*)&As[kk][ty];
            *(int4*)&w[0] = *(const int4*)&Ws[kk][tx];
            #pragma unroll
            for (int i = 0; i < 4; i++)
                #pragma unroll
                for (int j = 0; j < 4; j++)
                    acc[i][j] += (long long)a[i] * w[j];   // IMAD.WIDE, exact
        }
        __syncthreads();
    }

    #pragma unroll
    for (int i = 0; i < 4; i++) {
        size_t r = (size_t)(row0 + ty + i) * 256 + col0 + tx;
        #pragma unroll
        for (int j = 0; j < 4; j++) {
            double o = (double)acc[i][j] * inv;
            if (bias) o += (double)bias[col0 + tx + j];
            C[r + j] = o;
        }
    }
}

// ---------------------------------------------------------------------------
__device__ __forceinline__ double dblock_sum256(double v, double* red, double* bc)
{
    const int lane = threadIdx.x & 31, warp = threadIdx.x >> 5;
    #pragma unroll
    for (int o = 16; o; o >>= 1) v += __shfl_xor_sync(0xffffffffu, v, o);
    if (lane == 0) red[warp] = v;
    __syncthreads();
    if (warp == 0) {
        double s = (lane < 8) ? red[lane] : 0.0;
        s += __shfl_xor_sync(0xffffffffu, s, 4);
        s += __shfl_xor_sync(0xffffffffu, s, 2);
        s += __shfl_xor_sync(0xffffffffu, s, 1);
        if (lane == 0) *bc = s;
    }
    __syncthreads();
    return *bc;
}

// ---------------------------------------------------------------------------
// LN -> LIF(th=1) over T for one branch (fp64). Pack bits (q/k) or store v fp32.
// block = (b,l), thread = h
// ---------------------------------------------------------------------------
__global__ void __launch_bounds__(256) ln_lif_branch_kernel(
    const double* __restrict__ Z, const float* __restrict__ lw,
    const float* __restrict__ lb, uint32_t* __restrict__ bits,
    float* __restrict__ vf)
{
    __shared__ double red[8];
    __shared__ double bc;
    const int bl = blockIdx.x;
    const int b = bl / L_, l = bl % L_;
    const int h = threadIdx.x;
    const int lane = h & 31, warp = h >> 5;
    const int head = h >> 7, d = h & 127;
    const double wv = (double)lw[h], bv = (double)lb[h];

    double vmem = 0.0;
    for (int t = 0; t < T_; t++) {
        size_t row = (size_t)(t * B_ + b) * L_ + l;
        double xv = Z[row * H_ + h];
        double mean = dblock_sum256(xv, red, &bc) * (1.0 / H_);
        double dv = xv - mean;
        double var = dblock_sum256(dv * dv, red, &bc) * (1.0 / H_);
        double yv = dv / sqrt(var + 1e-5) * wv + bv;
        vmem = vmem + (yv - vmem) * 0.5;
        bool sp = (vmem - 1.0) >= 0.0;
        if (sp) vmem = 0.0;
        if (vf) {
            vf[(((size_t)(t * B_ + b) * 2 + head) * L_ + l) * 128 + d] = sp ? 1.f : 0.f;
        } else {
            uint32_t ball = __ballot_sync(0xffffffffu, sp);
            if (lane == 0)
                bits[(((size_t)(t * B_ + b) * 2 + head) * L_ + l) * 4 + (warp & 3)] = ball;
        }
    }
}

// ---------------------------------------------------------------------------
// attn = popc(q&k)*0.125 ; y = attn @ v  (exact fp32)
// ---------------------------------------------------------------------------
#define ATTN_SMEM ((L_*128 + 8*L_*4)*4 + L_*4*4)   // 131200 bytes

__global__ void __launch_bounds__(256) attn_kernel(
    const uint32_t* __restrict__ qb, const uint32_t* __restrict__ kb,
    const float* __restrict__ vf, float* __restrict__ y)
{
    extern __shared__ char smem_raw[];
    float*    sv    = (float*)smem_raw;           // [200][128]
    uint32_t* skb   = (uint32_t*)(sv + L_ * 128); // [200][4]
    float*    sattn = (float*)(skb + L_ * 4);     // [8][200][4]

    const int batch = blockIdx.x;
    const uint32_t* qb_b = qb + (size_t)batch * L_ * 4;
    const uint32_t* kb_b = kb + (size_t)batch * L_ * 4;
    const float*    v_b  = vf + (size_t)batch * L_ * 128;
    float*          y_b  = y  + (size_t)batch * L_ * 128;

    const int tid = threadIdx.x;
    for (int i = tid; i < L_ * 4; i += 256) skb[i] = kb_b[i];
    for (int i = tid; i < L_ * 32; i += 256) ((float4*)sv)[i] = ((const float4*)v_b)[i];
    __syncthreads();

    const int warp = tid >> 5, lane = tid & 31;
    float* aw = sattn + warp * (L_ * 4);
    const float* svl = sv + lane * 4;

    for (int base = warp * 4; base < L_; base += 32) {
        #pragma unroll
        for (int r = 0; r < 4; r++) {
            const int lrow = base + r;
            uint32_t q0 = qb_b[lrow*4+0], q1 = qb_b[lrow*4+1];
            uint32_t q2 = qb_b[lrow*4+2], q3 = qb_b[lrow*4+3];
            for (int m = lane; m < L_; m += 32) {
                int c = __popc(q0 & skb[m*4+0]) + __popc(q1 & skb[m*4+1])
                      + __popc(q2 & skb[m*4+2]) + __popc(q3 & skb[m*4+3]);
                aw[m*4 + r] = (float)c * 0.125f;
            }
        }
        __syncwarp();
        float4 acc0 = {0,0,0,0}, acc1 = {0,0,0,0}, acc2 = {0,0,0,0}, acc3 = {0,0,0,0};
        #pragma unroll 4
        for (int m = 0; m < L_; m++) {
            float4 a  = *(const float4*)(aw  + m * 4);
            float4 vv = *(const float4*)(svl + m * 128);
            acc0.x += a.x*vv.x; acc0.y += a.x*vv.y; acc0.z += a.x*vv.z; acc0.w += a.x*vv.w;
            acc1.x += a.y*vv.x; acc1.y += a.y*vv.y; acc1.z += a.y*vv.z; acc1.w += a.y*vv.w;
            acc2.x += a.z*vv.x; acc2.y += a.z*vv.y; acc2.z += a.z*vv.z; acc2.w += a.z*vv.w;
            acc3.x += a.w*vv.x; acc3.y += a.w*vv.y; acc3.z += a.w*vv.z; acc3.w += a.w*vv.w;
        }
        *(float4*)(y_b + (size_t)(base + 0) * 128 + lane * 4) = acc0;
        *(float4*)(y_b + (size_t)(base + 1) * 128 + lane * 4) = acc1;
        *(float4*)(y_b + (size_t)(base + 2) * 128 + lane * 4) = acc2;
        *(float4*)(y_b + (size_t)(base + 3) * 128 + lane * 4) = acc3;
        __syncwarp();
    }
}

// ---------------------------------------------------------------------------
// attn LIF (th=0.5) over T; exact in fp32; write int {0,1} spikes for proj GEMM
// ---------------------------------------------------------------------------
__global__ void __launch_bounds__(256) attn_lif_kernel(
    const float* __restrict__ y, int* __restrict__ s2)
{
    const int bl = blockIdx.x;
    const int b = bl / L_, l = bl % L_;
    const int h = threadIdx.x;
    const int head = h >> 7, d = h & 127;
    float vmem = 0.f;
    #pragma unroll
    for (int t = 0; t < T_; t++) {
        float yv = y[(((size_t)(t * B_ + b) * 2 + head) * L_ + l) * 128 + d];
        vmem = vmem + (yv - vmem) * 0.5f;
        bool sp = (vmem - 0.5f) >= 0.f;
        if (sp) vmem = 0.f;
        s2[((size_t)(t * B_ + b) * L_ + l) * H_ + h] = sp ? 1 : 0;
    }
}

// ---------------------------------------------------------------------------
// proj LN -> LIF(th=1) -> output spikes (fp64 decisions)
// ---------------------------------------------------------------------------
__global__ void __launch_bounds__(256) proj_ln_lif_kernel(
    const double* __restrict__ Zp, const float* __restrict__ lw,
    const float* __restrict__ lb, float* __restrict__ out)
{
    __shared__ double red[8];
    __shared__ double bc;
    const int bl = blockIdx.x;
    const int b = bl / L_, l = bl % L_;
    const int h = threadIdx.x;
    const double wv = (double)lw[h], bv = (double)lb[h];
    double vmem = 0.0;
    for (int t = 0; t < T_; t++) {
        size_t row = (size_t)(t * B_ + b) * L_ + l;
        double xv = Zp[row * H_ + h];
        double mean = dblock_sum256(xv, red, &bc) * (1.0 / H_);
        double dv = xv - mean;
        double var = dblock_sum256(dv * dv, red, &bc) * (1.0 / H_);
        double yv = dv / sqrt(var + 1e-5) * wv + bv;
        vmem = vmem + (yv - vmem) * 0.5;
        bool sp = (vmem - 1.0) >= 0.0;
        if (sp) vmem = 0.0;
        out[row * H_ + h] = sp ? 1.f : 0.f;
    }
}

// ---------------------------------------------------------------------------
extern "C" void kernel_launch(void* const* d_in, const int* in_sizes, int n_in,
                              void* d_out, int out_size)
{
    const float* x   = (const float*)d_in[0];
    const float* qw  = (const float*)d_in[1];
    const float* qlw = (const float*)d_in[2];
    const float* qlb = (const float*)d_in[3];
    const float* kw  = (const float*)d_in[4];
    const float* klw = (const float*)d_in[5];
    const float* klb = (const float*)d_in[6];
    const float* vw  = (const float*)d_in[7];
    const float* vlw = (const float*)d_in[8];
    const float* vlb = (const float*)d_in[9];
    const float* pw  = (const float*)d_in[10];
    const float* pb  = (const float*)d_in[11];
    const float* plw = (const float*)d_in[12];
    const float* plb = (const float*)d_in[13];
    float* out = (float*)d_out;

    int *xq, *wq, *s2;
    double *Z, *zp;
    float *vf, *yv;
    uint32_t *qbp, *kbp;
    cudaGetSymbolAddress((void**)&xq,  g_xq);
    cudaGetSymbolAddress((void**)&wq,  g_wq);
    cudaGetSymbolAddress((void**)&s2,  g_s2);
    cudaGetSymbolAddress((void**)&Z,   g_Z);
    cudaGetSymbolAddress((void**)&zp,  g_zp);
    cudaGetSymbolAddress((void**)&vf,  g_vf);
    cudaGetSymbolAddress((void**)&yv,  g_y);
    cudaGetSymbolAddress((void**)&qbp, g_qb);
    cudaGetSymbolAddress((void**)&kbp, g_kb);

    const double SX  = 134217728.0;        // 2^27
    const double SW  = 4294967296.0;       // 2^32
    const double INV_QKV  = 1.0 / 576460752303423488.0;  // 2^-59
    const double INV_PROJ = 1.0 / 4294967296.0;          // 2^-32

    // quantize inputs (exact fp64 multiply + round)
    quant_kernel<<<2048, 256>>>(x, xq, SX, M_ * H_);
    quant_kernel<<<64, 256>>>(qw, wq + 0ull * H_ * H_, SW, H_ * H_);
    quant_kernel<<<64, 256>>>(kw, wq + 1ull * H_ * H_, SW, H_ * H_);
    quant_kernel<<<64, 256>>>(vw, wq + 2ull * H_ * H_, SW, H_ * H_);
    quant_kernel<<<64, 256>>>(pw, wq + 3ull * H_ * H_, SW, H_ * H_);

    dim3 gg(M_ / 64, 4);  // (800, 4)

    // q branch
    igemm_kernel<<<gg, 256>>>(xq, wq + 0ull * H_ * H_, nullptr, Z, INV_QKV);
    ln_lif_branch_kernel<<<BLr, 256>>>(Z, qlw, qlb, qbp, nullptr);
    // k branch
    igemm_kernel<<<gg, 256>>>(xq, wq + 1ull * H_ * H_, nullptr, Z, INV_QKV);
    ln_lif_branch_kernel<<<BLr, 256>>>(Z, klw, klb, kbp, nullptr);
    // v branch
    igemm_kernel<<<gg, 256>>>(xq, wq + 2ull * H_ * H_, nullptr, Z, INV_QKV);
    ln_lif_branch_kernel<<<BLr, 256>>>(Z, vlw, vlb, nullptr, vf);

    cudaFuncSetAttribute(attn_kernel, cudaFuncAttributeMaxDynamicSharedMemorySize, ATTN_SMEM);
    attn_kernel<<<NBATCH, 256, ATTN_SMEM>>>(qbp, kbp, vf, yv);

    attn_lif_kernel<<<BLr, 256>>>(yv, s2);

    igemm_kernel<<<gg, 256>>>(s2, wq + 3ull * H_ * H_, pb, zp, INV_PROJ);

    proj_ln_lif_kernel<<<BLr, 256>>>(zp, plw, plb, out);
}

// round 5
// speedup vs baseline: 5.0778x; 1.0933x over previous
#include <cuda_runtime.h>
#include <cstdint>
#include <cmath>

// ---------------------------------------------------------------------------
// SSA forward, exact int8 tensor-core (mma.sync IMMA) edition.
// x,w quantized (x*2^27, w*2^32 -> int, exact fp64 quantize), split into 4
// balanced 8-bit digits (s8, exact). Digit-pair GEMMs run on
// mma.sync.m16n8k32.s8.s8.s32 (baseline PTX, works on compute_103 target).
// s32 accumulation is EXACT (pair sums <= 1.7e7). Diagonals s=i+j share one
// accumulator; per-thread int64 shift-add recombines (exact); final double
// scale adds ~1e-16. Pairs s<2 dropped (<=1e-10; R3 passed with 4e-9 budget).
// LN + LIF membranes fp64, inv_std hoisted per row. Attention block (binary
// q,k,v) exact in fp32 (popcount / dyadic rationals).
// ---------------------------------------------------------------------------

#define T_  4
#define B_  64
#define L_  200
#define H_  256
#define M_  (T_*B_*L_)      // 51200
#define BLr (B_*L_)         // 12800
#define NBATCH (T_*B_*2)    // 512 (t,b,head)

// static device scratch (no runtime allocation allowed)
__device__ __align__(128) int8_t g_asl[4ull*M_*H_];    // x digits [4][M][256]
__device__ __align__(128) int8_t g_wsl[16ull*H_*H_];   // w digits [widx4][sl4][256][256]
__device__ __align__(128) int8_t g_s2[(size_t)M_*H_];  // attn-LIF spikes {0,1}
__device__ double   g_Zq[(size_t)M_*H_];
__device__ double   g_Zk[(size_t)M_*H_];
__device__ double   g_Zv[(size_t)M_*H_];
__device__ double   g_zp[(size_t)M_*H_];
__device__ uint32_t g_qb[NBATCH*L_*4];
__device__ uint32_t g_kb[NBATCH*L_*4];
__device__ float    g_vf[(size_t)NBATCH*L_*128];
__device__ float    g_y [(size_t)NBATCH*L_*128];

// ---------------------------------------------------------------------------
__device__ __forceinline__ void mma_s8(int* c, const unsigned* a, const unsigned* b)
{
    asm volatile(
        "mma.sync.aligned.m16n8k32.row.col.s32.s8.s8.s32 "
        "{%0,%1,%2,%3}, {%4,%5,%6,%7}, {%8,%9}, {%0,%1,%2,%3};"
        : "+r"(c[0]), "+r"(c[1]), "+r"(c[2]), "+r"(c[3])
        : "r"(a[0]), "r"(a[1]), "r"(a[2]), "r"(a[3]), "r"(b[0]), "r"(b[1]));
}

// ===================== digit-slice generation ===============================
__global__ void slice_x_kernel(const float* __restrict__ x, int8_t* __restrict__ asl)
{
    int i = blockIdx.x * blockDim.x + threadIdx.x;
    int stride = gridDim.x * blockDim.x;
    const size_t plane = (size_t)M_ * H_;
    for (; i < M_ * H_; i += stride) {
        int q = __double2int_rn((double)x[i] * 134217728.0);  // 2^27
        #pragma unroll
        for (int s = 0; s < 4; s++) {
            int d = ((q + 128) & 255) - 128;
            q = (q - d) >> 8;
            asl[s * plane + i] = (int8_t)d;
        }
    }
}

__global__ void slice_w_kernel(const float* __restrict__ qw, const float* __restrict__ kw,
                               const float* __restrict__ vw, const float* __restrict__ pw,
                               int8_t* __restrict__ wsl)
{
    int i = blockIdx.x * blockDim.x + threadIdx.x;
    int stride = gridDim.x * blockDim.x;
    for (; i < 4 * H_ * H_; i += stride) {
        int widx = i >> 16, j = i & 65535;
        const float* W = (widx == 0) ? qw : ((widx == 1) ? kw : ((widx == 2) ? vw : pw));
        long long q = __double2ll_rn((double)W[j] * 4294967296.0);  // 2^32
        #pragma unroll
        for (int s = 0; s < 4; s++) {
            int d = (int)(((q + 128) & 255)) - 128;
            q = (q - d) >> 8;
            wsl[(size_t)(widx * 4 + s) * 65536 + j] = (int8_t)d;
        }
    }
}

// ===================== qkv slice GEMM (IMMA) ================================
// grid (12, 400): x = nt (widx=nt>>2, n0=(nt&3)*64), y = mt (m0=mt*128)
// smem: A packed frags 4 planes x 32KB, then W packed frags 4 planes x 16KB
#define QKV_SMEM (4*32768 + 4*16384)   // 196608

__global__ void __launch_bounds__(256) gemm_qkv_kernel(
    const int8_t* __restrict__ asl, const int8_t* __restrict__ wsl,
    double* __restrict__ Zq, double* __restrict__ Zk, double* __restrict__ Zv)
{
    extern __shared__ char smem[];
    const int tid = threadIdx.x;
    const int nt = blockIdx.x, mt = blockIdx.y;
    const int widx = nt >> 2, n0 = (nt & 3) * 64, m0 = mt * 128;

    // ---- load + fragment-pack A planes (each 128x256 s8) ----
    #pragma unroll
    for (int p = 0; p < 4; p++) {
        const int8_t* src = asl + (size_t)p * M_ * H_ + (size_t)m0 * 256;
        char* dstp = smem + p * 32768;
        #pragma unroll
        for (int v = 0; v < 8; v++) {
            int chunk = tid + 256 * v;            // 0..2047
            int row = chunk >> 4, c16 = chunk & 15;
            uint4 val = *(const uint4*)(src + row * 256 + c16 * 16);
            int mc = row >> 4, kc = c16 >> 1;
            int g  = ((c16 & 1) << 1) | ((row >> 3) & 1);
            int T0 = (row & 7) * 4;
            char* base = dstp + ((mc * 8 + kc) * 32) * 16 + g * 4;
            *(unsigned*)(base + (T0 + 0) * 16) = val.x;
            *(unsigned*)(base + (T0 + 1) * 16) = val.y;
            *(unsigned*)(base + (T0 + 2) * 16) = val.z;
            *(unsigned*)(base + (T0 + 3) * 16) = val.w;
        }
    }
    // ---- load + fragment-pack W planes (each 64x256 s8) ----
    #pragma unroll
    for (int p = 0; p < 4; p++) {
        const int8_t* src = wsl + (size_t)(widx * 4 + p) * 65536 + n0 * 256;
        char* dstp = smem + 131072 + p * 16384;
        #pragma unroll
        for (int v = 0; v < 4; v++) {
            int chunk = tid + 256 * v;            // 0..1023
            int row = chunk >> 4, c16 = chunk & 15;
            uint4 val = *(const uint4*)(src + row * 256 + c16 * 16);
            int nc = row >> 3, kc = c16 >> 1;
            int g  = c16 & 1;
            int T0 = (row & 7) * 4;
            char* base = dstp + ((nc * 8 + kc) * 32) * 8 + g * 4;
            *(unsigned*)(base + (T0 + 0) * 8) = val.x;
            *(unsigned*)(base + (T0 + 1) * 8) = val.y;
            *(unsigned*)(base + (T0 + 2) * 8) = val.z;
            *(unsigned*)(base + (T0 + 3) * 8) = val.w;
        }
    }
    __syncthreads();

    const int warp = tid >> 5, lane = tid & 31;
    const int wm = warp >> 1, wn = warp & 1;   // warp tile 32x32

    long long acc[2][4][4];
    #pragma unroll
    for (int mi = 0; mi < 2; mi++)
        #pragma unroll
        for (int nj = 0; nj < 4; nj++)
            #pragma unroll
            for (int r = 0; r < 4; r++) acc[mi][nj][r] = 0ll;

    // digit pairs grouped by diagonal s=i+j (2..6)
    const int PI[13] = {0,1,2, 0,1,2,3, 1,2,3, 2,3, 3};
    const int PJ[13] = {2,1,0, 3,2,1,0, 3,2,1, 3,2, 3};
    const int DS[6]  = {0, 3, 7, 10, 12, 13};

    for (int sd = 0; sd < 5; sd++) {
        int cfr[2][4][4];
        #pragma unroll
        for (int mi = 0; mi < 2; mi++)
            #pragma unroll
            for (int nj = 0; nj < 4; nj++)
                #pragma unroll
                for (int r = 0; r < 4; r++) cfr[mi][nj][r] = 0;

        for (int p = DS[sd]; p < DS[sd + 1]; p++) {
            const char* Ap = smem + PI[p] * 32768;
            const char* Bp = smem + 131072 + PJ[p] * 16384;
            #pragma unroll
            for (int kc = 0; kc < 8; kc++) {
                unsigned a[2][4], b[4][2];
                #pragma unroll
                for (int mi = 0; mi < 2; mi++) {
                    uint4 av = *(const uint4*)(Ap + (((2*wm + mi) * 8 + kc) * 32 + lane) * 16);
                    a[mi][0] = av.x; a[mi][1] = av.y; a[mi][2] = av.z; a[mi][3] = av.w;
                }
                #pragma unroll
                for (int nj = 0; nj < 4; nj++) {
                    uint2 bv = *(const uint2*)(Bp + (((4*wn + nj) * 8 + kc) * 32 + lane) * 8);
                    b[nj][0] = bv.x; b[nj][1] = bv.y;
                }
                #pragma unroll
                for (int mi = 0; mi < 2; mi++)
                    #pragma unroll
                    for (int nj = 0; nj < 4; nj++)
                        mma_s8(cfr[mi][nj], a[mi], b[nj]);
            }
        }
        int sh = 8 * sd;
        #pragma unroll
        for (int mi = 0; mi < 2; mi++)
            #pragma unroll
            for (int nj = 0; nj < 4; nj++)
                #pragma unroll
                for (int r = 0; r < 4; r++)
                    acc[mi][nj][r] += ((long long)cfr[mi][nj][r]) << sh;
    }

    // epilogue: Z = acc * 2^(16-59)
    double* Zout = (widx == 0) ? Zq : ((widx == 1) ? Zk : Zv);
    const double INV = 1.1368683772161603e-13;   // 2^-43
    #pragma unroll
    for (int mi = 0; mi < 2; mi++)
        #pragma unroll
        for (int nj = 0; nj < 4; nj++)
            #pragma unroll
            for (int r = 0; r < 4; r++) {
                int row = m0 + 32*wm + 16*mi + (lane >> 2) + 8*(r >> 1);
                int col = n0 + 32*wn + 8*nj + 2*(lane & 3) + (r & 1);
                Zout[(size_t)row * H_ + col] = (double)acc[mi][nj][r] * INV;
            }
}

// ===================== proj slice GEMM (IMMA) ===============================
// A = s2 {0,1} single s8 plane; 4 pair GEMMs (w digit j), scale 2^(8j-32)
#define PROJ_SMEM (32768 + 4*16384)   // 98304

__global__ void __launch_bounds__(256) gemm_proj_kernel(
    const int8_t* __restrict__ s2, const int8_t* __restrict__ wsl,
    const float* __restrict__ pb, double* __restrict__ Zp)
{
    extern __shared__ char smem[];
    const int tid = threadIdx.x;
    const int nt = blockIdx.x, mt = blockIdx.y;
    const int n0 = nt * 64, m0 = mt * 128;

    {   // A tile 128x256
        const int8_t* src = s2 + (size_t)m0 * 256;
        #pragma unroll
        for (int v = 0; v < 8; v++) {
            int chunk = tid + 256 * v;
            int row = chunk >> 4, c16 = chunk & 15;
            uint4 val = *(const uint4*)(src + row * 256 + c16 * 16);
            int mc = row >> 4, kc = c16 >> 1;
            int g  = ((c16 & 1) << 1) | ((row >> 3) & 1);
            int T0 = (row & 7) * 4;
            char* base = smem + ((mc * 8 + kc) * 32) * 16 + g * 4;
            *(unsigned*)(base + (T0 + 0) * 16) = val.x;
            *(unsigned*)(base + (T0 + 1) * 16) = val.y;
            *(unsigned*)(base + (T0 + 2) * 16) = val.z;
            *(unsigned*)(base + (T0 + 3) * 16) = val.w;
        }
    }
    #pragma unroll
    for (int p = 0; p < 4; p++) {   // pw digit planes (widx=3)
        const int8_t* src = wsl + (size_t)(12 + p) * 65536 + n0 * 256;
        char* dstp = smem + 32768 + p * 16384;
        #pragma unroll
        for (int v = 0; v < 4; v++) {
            int chunk = tid + 256 * v;
            int row = chunk >> 4, c16 = chunk & 15;
            uint4 val = *(const uint4*)(src + row * 256 + c16 * 16);
            int nc = row >> 3, kc = c16 >> 1;
            int g  = c16 & 1;
            int T0 = (row & 7) * 4;
            char* base = dstp + ((nc * 8 + kc) * 32) * 8 + g * 4;
            *(unsigned*)(base + (T0 + 0) * 8) = val.x;
            *(unsigned*)(base + (T0 + 1) * 8) = val.y;
            *(unsigned*)(base + (T0 + 2) * 8) = val.z;
            *(unsigned*)(base + (T0 + 3) * 8) = val.w;
        }
    }
    __syncthreads();

    const int warp = tid >> 5, lane = tid & 31;
    const int wm = warp >> 1, wn = warp & 1;

    long long acc[2][4][4];
    #pragma unroll
    for (int mi = 0; mi < 2; mi++)
        #pragma unroll
        for (int nj = 0; nj < 4; nj++)
            #pragma unroll
            for (int r = 0; r < 4; r++) acc[mi][nj][r] = 0ll;

    for (int j = 0; j < 4; j++) {
        int cfr[2][4][4];
        #pragma unroll
        for (int mi = 0; mi < 2; mi++)
            #pragma unroll
            for (int nj = 0; nj < 4; nj++)
                #pragma unroll
                for (int r = 0; r < 4; r++) cfr[mi][nj][r] = 0;

        const char* Bp = smem + 32768 + j * 16384;
        #pragma unroll
        for (int kc = 0; kc < 8; kc++) {
            unsigned a[2][4], b[4][2];
            #pragma unroll
            for (int mi = 0; mi < 2; mi++) {
                uint4 av = *(const uint4*)(smem + (((2*wm + mi) * 8 + kc) * 32 + lane) * 16);
                a[mi][0] = av.x; a[mi][1] = av.y; a[mi][2] = av.z; a[mi][3] = av.w;
            }
            #pragma unroll
            for (int nj = 0; nj < 4; nj++) {
                uint2 bv = *(const uint2*)(Bp + (((4*wn + nj) * 8 + kc) * 32 + lane) * 8);
                b[nj][0] = bv.x; b[nj][1] = bv.y;
            }
            #pragma unroll
            for (int mi = 0; mi < 2; mi++)
                #pragma unroll
                for (int nj = 0; nj < 4; nj++)
                    mma_s8(cfr[mi][nj], a[mi], b[nj]);
        }
        int sh = 8 * j;
        #pragma unroll
        for (int mi = 0; mi < 2; mi++)
            #pragma unroll
            for (int nj = 0; nj < 4; nj++)
                #pragma unroll
                for (int r = 0; r < 4; r++)
                    acc[mi][nj][r] += ((long long)cfr[mi][nj][r]) << sh;
    }

    const double INV = 2.3283064365386963e-10;   // 2^-32
    #pragma unroll
    for (int mi = 0; mi < 2; mi++)
        #pragma unroll
        for (int nj = 0; nj < 4; nj++)
            #pragma unroll
            for (int r = 0; r < 4; r++) {
                int row = m0 + 32*wm + 16*mi + (lane >> 2) + 8*(r >> 1);
                int col = n0 + 32*wn + 8*nj + 2*(lane & 3) + (r & 1);
                Zp[(size_t)row * H_ + col] = (double)acc[mi][nj][r] * INV + (double)pb[col];
            }
}

// ===================== LN/LIF (fp64 decisions) ==============================
__device__ __forceinline__ double dblock_sum256(double v, double* red, double* bc)
{
    const int lane = threadIdx.x & 31, warp = threadIdx.x >> 5;
    #pragma unroll
    for (int o = 16; o; o >>= 1) v += __shfl_xor_sync(0xffffffffu, v, o);
    if (lane == 0) red[warp] = v;
    __syncthreads();
    if (warp == 0) {
        double s = (lane < 8) ? red[lane] : 0.0;
        s += __shfl_xor_sync(0xffffffffu, s, 4);
        s += __shfl_xor_sync(0xffffffffu, s, 2);
        s += __shfl_xor_sync(0xffffffffu, s, 1);
        if (lane == 0) *bc = s;
    }
    __syncthreads();
    return *bc;
}

__device__ __forceinline__ double dblock_invstd256(double v, double* red, double* bc)
{
    const int lane = threadIdx.x & 31, warp = threadIdx.x >> 5;
    #pragma unroll
    for (int o = 16; o; o >>= 1) v += __shfl_xor_sync(0xffffffffu, v, o);
    if (lane == 0) red[warp] = v;
    __syncthreads();
    if (warp == 0) {
        double s = (lane < 8) ? red[lane] : 0.0;
        s += __shfl_xor_sync(0xffffffffu, s, 4);
        s += __shfl_xor_sync(0xffffffffu, s, 2);
        s += __shfl_xor_sync(0xffffffffu, s, 1);
        if (lane == 0) *bc = 1.0 / sqrt(s * (1.0 / H_) + 1e-5);
    }
    __syncthreads();
    return *bc;
}

__global__ void __launch_bounds__(256) ln_lif_branch_kernel(
    const double* __restrict__ Z, const float* __restrict__ lw,
    const float* __restrict__ lb, uint32_t* __restrict__ bits,
    float* __restrict__ vf)
{
    __shared__ double red[8];
    __shared__ double bc;
    const int bl = blockIdx.x;
    const int b = bl / L_, l = bl % L_;
    const int h = threadIdx.x;
    const int lane = h & 31, warp = h >> 5;
    const int head = h >> 7, d = h & 127;
    const double wv = (double)lw[h], bv = (double)lb[h];

    double vmem = 0.0;
    for (int t = 0; t < T_; t++) {
        size_t row = (size_t)(t * B_ + b) * L_ + l;
        double xv = Z[row * H_ + h];
        double mean = dblock_sum256(xv, red, &bc) * (1.0 / H_);
        double dv = xv - mean;
        double inv_std = dblock_invstd256(dv * dv, red, &bc);
        double yv = dv * inv_std * wv + bv;
        vmem = vmem + (yv - vmem) * 0.5;
        bool sp = (vmem - 1.0) >= 0.0;
        if (sp) vmem = 0.0;
        if (vf) {
            vf[(((size_t)(t * B_ + b) * 2 + head) * L_ + l) * 128 + d] = sp ? 1.f : 0.f;
        } else {
            uint32_t ball = __ballot_sync(0xffffffffu, sp);
            if (lane == 0)
                bits[(((size_t)(t * B_ + b) * 2 + head) * L_ + l) * 4 + (warp & 3)] = ball;
        }
    }
}

// ===================== attention (exact fp32) ===============================
#define ATTN_SMEM ((L_*128 + 8*L_*4)*4 + L_*4*4)   // 131200 bytes

__global__ void __launch_bounds__(256) attn_kernel(
    const uint32_t* __restrict__ qb, const uint32_t* __restrict__ kb,
    const float* __restrict__ vf, float* __restrict__ y)
{
    extern __shared__ char smem_raw[];
    float*    sv    = (float*)smem_raw;           // [200][128]
    uint32_t* skb   = (uint32_t*)(sv + L_ * 128); // [200][4]
    float*    sattn = (float*)(skb + L_ * 4);     // [8][200][4]

    const int batch = blockIdx.x;
    const uint32_t* qb_b = qb + (size_t)batch * L_ * 4;
    const uint32_t* kb_b = kb + (size_t)batch * L_ * 4;
    const float*    v_b  = vf + (size_t)batch * L_ * 128;
    float*          y_b  = y  + (size_t)batch * L_ * 128;

    const int tid = threadIdx.x;
    for (int i = tid; i < L_ * 4; i += 256) skb[i] = kb_b[i];
    for (int i = tid; i < L_ * 32; i += 256) ((float4*)sv)[i] = ((const float4*)v_b)[i];
    __syncthreads();

    const int warp = tid >> 5, lane = tid & 31;
    float* aw = sattn + warp * (L_ * 4);
    const float* svl = sv + lane * 4;

    for (int base = warp * 4; base < L_; base += 32) {
        #pragma unroll
        for (int r = 0; r < 4; r++) {
            const int lrow = base + r;
            uint32_t q0 = qb_b[lrow*4+0], q1 = qb_b[lrow*4+1];
            uint32_t q2 = qb_b[lrow*4+2], q3 = qb_b[lrow*4+3];
            for (int m = lane; m < L_; m += 32) {
                int c = __popc(q0 & skb[m*4+0]) + __popc(q1 & skb[m*4+1])
                      + __popc(q2 & skb[m*4+2]) + __popc(q3 & skb[m*4+3]);
                aw[m*4 + r] = (float)c * 0.125f;
            }
        }
        __syncwarp();
        float4 acc0 = {0,0,0,0}, acc1 = {0,0,0,0}, acc2 = {0,0,0,0}, acc3 = {0,0,0,0};
        #pragma unroll 4
        for (int m = 0; m < L_; m++) {
            float4 a  = *(const float4*)(aw  + m * 4);
            float4 vv = *(const float4*)(svl + m * 128);
            acc0.x += a.x*vv.x; acc0.y += a.x*vv.y; acc0.z += a.x*vv.z; acc0.w += a.x*vv.w;
            acc1.x += a.y*vv.x; acc1.y += a.y*vv.y; acc1.z += a.y*vv.z; acc1.w += a.y*vv.w;
            acc2.x += a.z*vv.x; acc2.y += a.z*vv.y; acc2.z += a.z*vv.z; acc2.w += a.z*vv.w;
            acc3.x += a.w*vv.x; acc3.y += a.w*vv.y; acc3.z += a.w*vv.z; acc3.w += a.w*vv.w;
        }
        *(float4*)(y_b + (size_t)(base + 0) * 128 + lane * 4) = acc0;
        *(float4*)(y_b + (size_t)(base + 1) * 128 + lane * 4) = acc1;
        *(float4*)(y_b + (size_t)(base + 2) * 128 + lane * 4) = acc2;
        *(float4*)(y_b + (size_t)(base + 3) * 128 + lane * 4) = acc3;
        __syncwarp();
    }
}

// ---------------------------------------------------------------------------
// attn LIF (th=0.5) over T; exact fp32; write s8 {0,1} spikes for proj GEMM
// ---------------------------------------------------------------------------
__global__ void __launch_bounds__(256) attn_lif_kernel(
    const float* __restrict__ y, int8_t* __restrict__ s2)
{
    const int bl = blockIdx.x;
    const int b = bl / L_, l = bl % L_;
    const int h = threadIdx.x;
    const int head = h >> 7, d = h & 127;
    float vmem = 0.f;
    #pragma unroll
    for (int t = 0; t < T_; t++) {
        float yv = y[(((size_t)(t * B_ + b) * 2 + head) * L_ + l) * 128 + d];
        vmem = vmem + (yv - vmem) * 0.5f;
        bool sp = (vmem - 0.5f) >= 0.f;
        if (sp) vmem = 0.f;
        s2[((size_t)(t * B_ + b) * L_ + l) * H_ + h] = sp ? 1 : 0;
    }
}

// ---------------------------------------------------------------------------
__global__ void __launch_bounds__(256) proj_ln_lif_kernel(
    const double* __restrict__ Zp, const float* __restrict__ lw,
    const float* __restrict__ lb, float* __restrict__ out)
{
    __shared__ double red[8];
    __shared__ double bc;
    const int bl = blockIdx.x;
    const int b = bl / L_, l = bl % L_;
    const int h = threadIdx.x;
    const double wv = (double)lw[h], bv = (double)lb[h];
    double vmem = 0.0;
    for (int t = 0; t < T_; t++) {
        size_t row = (size_t)(t * B_ + b) * L_ + l;
        double xv = Zp[row * H_ + h];
        double mean = dblock_sum256(xv, red, &bc) * (1.0 / H_);
        double dv = xv - mean;
        double inv_std = dblock_invstd256(dv * dv, red, &bc);
        double yv = dv * inv_std * wv + bv;
        vmem = vmem + (yv - vmem) * 0.5;
        bool sp = (vmem - 1.0) >= 0.0;
        if (sp) vmem = 0.0;
        out[row * H_ + h] = sp ? 1.f : 0.f;
    }
}

// ---------------------------------------------------------------------------
extern "C" void kernel_launch(void* const* d_in, const int* in_sizes, int n_in,
                              void* d_out, int out_size)
{
    const float* x   = (const float*)d_in[0];
    const float* qw  = (const float*)d_in[1];
    const float* qlw = (const float*)d_in[2];
    const float* qlb = (const float*)d_in[3];
    const float* kw  = (const float*)d_in[4];
    const float* klw = (const float*)d_in[5];
    const float* klb = (const float*)d_in[6];
    const float* vw  = (const float*)d_in[7];
    const float* vlw = (const float*)d_in[8];
    const float* vlb = (const float*)d_in[9];
    const float* pw  = (const float*)d_in[10];
    const float* pb  = (const float*)d_in[11];
    const float* plw = (const float*)d_in[12];
    const float* plb = (const float*)d_in[13];
    float* out = (float*)d_out;

    int8_t *asl, *wsl, *s2;
    double *Zq, *Zk, *Zv, *zp;
    float *vf, *yv;
    uint32_t *qbp, *kbp;
    cudaGetSymbolAddress((void**)&asl, g_asl);
    cudaGetSymbolAddress((void**)&wsl, g_wsl);
    cudaGetSymbolAddress((void**)&s2,  g_s2);
    cudaGetSymbolAddress((void**)&Zq,  g_Zq);
    cudaGetSymbolAddress((void**)&Zk,  g_Zk);
    cudaGetSymbolAddress((void**)&Zv,  g_Zv);
    cudaGetSymbolAddress((void**)&zp,  g_zp);
    cudaGetSymbolAddress((void**)&vf,  g_vf);
    cudaGetSymbolAddress((void**)&yv,  g_y);
    cudaGetSymbolAddress((void**)&qbp, g_qb);
    cudaGetSymbolAddress((void**)&kbp, g_kb);

    cudaFuncSetAttribute(gemm_qkv_kernel, cudaFuncAttributeMaxDynamicSharedMemorySize, QKV_SMEM);
    cudaFuncSetAttribute(gemm_proj_kernel, cudaFuncAttributeMaxDynamicSharedMemorySize, PROJ_SMEM);
    cudaFuncSetAttribute(attn_kernel, cudaFuncAttributeMaxDynamicSharedMemorySize, ATTN_SMEM);

    slice_x_kernel<<<4096, 256>>>(x, asl);
    slice_w_kernel<<<256, 256>>>(qw, kw, vw, pw, wsl);

    dim3 gq(12, 400);
    gemm_qkv_kernel<<<gq, 256, QKV_SMEM>>>(asl, wsl, Zq, Zk, Zv);

    ln_lif_branch_kernel<<<BLr, 256>>>(Zq, qlw, qlb, qbp, nullptr);
    ln_lif_branch_kernel<<<BLr, 256>>>(Zk, klw, klb, kbp, nullptr);
    ln_lif_branch_kernel<<<BLr, 256>>>(Zv, vlw, vlb, nullptr, vf);

    attn_kernel<<<NBATCH, 256, ATTN_SMEM>>>(qbp, kbp, vf, yv);

    attn_lif_kernel<<<BLr, 256>>>(yv, s2);

    dim3 gp(4, 400);
    gemm_proj_kernel<<<gp, 256, PROJ_SMEM>>>(s2, wsl, pb, zp);

    proj_ln_lif_kernel<<<BLr, 256>>>(zp, plw, plb, out);
}

// round 6
// speedup vs baseline: 6.5197x; 1.2840x over previous
#include <cuda_runtime.h>
#include <cstdint>
#include <cmath>

// ---------------------------------------------------------------------------
// SSA forward, exact int8 IMMA GEMM + warp-level barrier-free fp64 LN/LIF.
// GEMMs: x*2^27, w*2^32 -> 4 balanced s8 digits; digit-pair GEMMs on
// mma.sync.m16n8k32.s8.s8.s32 (exact); int64 shift-add recombine; double out.
// LN/LIF: one warp per (b,l) row (H=256 = 32 lanes x 8), pure shfl
// reductions in fp64 -> no smem, no __syncthreads, high MLP.
// Attention: binary q,k popcount + fp32 PV (exact dyadic rationals).
// ---------------------------------------------------------------------------

#define T_  4
#define B_  64
#define L_  200
#define H_  256
#define M_  (T_*B_*L_)      // 51200
#define BLr (B_*L_)         // 12800
#define NBATCH (T_*B_*2)    // 512 (t,b,head)

__device__ __align__(128) int8_t g_asl[4ull*M_*H_];    // x digits [4][M][256]
__device__ __align__(128) int8_t g_wsl[16ull*H_*H_];   // w digits [widx4][sl4][256][256]
__device__ __align__(128) int8_t g_s2[(size_t)M_*H_];  // attn-LIF spikes {0,1}
__device__ double   g_Zq[(size_t)M_*H_];
__device__ double   g_Zk[(size_t)M_*H_];
__device__ double   g_Zv[(size_t)M_*H_];
__device__ double   g_zp[(size_t)M_*H_];
__device__ uint32_t g_qb[NBATCH*L_*4];
__device__ uint32_t g_kb[NBATCH*L_*4];
__device__ float    g_vf[(size_t)NBATCH*L_*128];
__device__ float    g_y [(size_t)NBATCH*L_*128];

// ---------------------------------------------------------------------------
__device__ __forceinline__ void mma_s8(int* c, const unsigned* a, const unsigned* b)
{
    asm volatile(
        "mma.sync.aligned.m16n8k32.row.col.s32.s8.s8.s32 "
        "{%0,%1,%2,%3}, {%4,%5,%6,%7}, {%8,%9}, {%0,%1,%2,%3};"
        : "+r"(c[0]), "+r"(c[1]), "+r"(c[2]), "+r"(c[3])
        : "r"(a[0]), "r"(a[1]), "r"(a[2]), "r"(a[3]), "r"(b[0]), "r"(b[1]));
}

// ===================== digit-slice generation ===============================
__global__ void slice_x_kernel(const float* __restrict__ x, int8_t* __restrict__ asl)
{
    int i = blockIdx.x * blockDim.x + threadIdx.x;
    int stride = gridDim.x * blockDim.x;
    const size_t plane = (size_t)M_ * H_;
    for (; i < M_ * H_; i += stride) {
        int q = __double2int_rn((double)x[i] * 134217728.0);  // 2^27
        #pragma unroll
        for (int s = 0; s < 4; s++) {
            int d = ((q + 128) & 255) - 128;
            q = (q - d) >> 8;
            asl[s * plane + i] = (int8_t)d;
        }
    }
}

__global__ void slice_w_kernel(const float* __restrict__ qw, const float* __restrict__ kw,
                               const float* __restrict__ vw, const float* __restrict__ pw,
                               int8_t* __restrict__ wsl)
{
    int i = blockIdx.x * blockDim.x + threadIdx.x;
    int stride = gridDim.x * blockDim.x;
    for (; i < 4 * H_ * H_; i += stride) {
        int widx = i >> 16, j = i & 65535;
        const float* W = (widx == 0) ? qw : ((widx == 1) ? kw : ((widx == 2) ? vw : pw));
        long long q = __double2ll_rn((double)W[j] * 4294967296.0);  // 2^32
        #pragma unroll
        for (int s = 0; s < 4; s++) {
            int d = (int)(((q + 128) & 255)) - 128;
            q = (q - d) >> 8;
            wsl[(size_t)(widx * 4 + s) * 65536 + j] = (int8_t)d;
        }
    }
}

// ===================== qkv slice GEMM (IMMA) ================================
#define QKV_SMEM (4*32768 + 4*16384)   // 196608

__global__ void __launch_bounds__(256) gemm_qkv_kernel(
    const int8_t* __restrict__ asl, const int8_t* __restrict__ wsl,
    double* __restrict__ Zq, double* __restrict__ Zk, double* __restrict__ Zv)
{
    extern __shared__ char smem[];
    const int tid = threadIdx.x;
    const int nt = blockIdx.x, mt = blockIdx.y;
    const int widx = nt >> 2, n0 = (nt & 3) * 64, m0 = mt * 128;

    #pragma unroll
    for (int p = 0; p < 4; p++) {
        const int8_t* src = asl + (size_t)p * M_ * H_ + (size_t)m0 * 256;
        char* dstp = smem + p * 32768;
        #pragma unroll
        for (int v = 0; v < 8; v++) {
            int chunk = tid + 256 * v;
            int row = chunk >> 4, c16 = chunk & 15;
            uint4 val = *(const uint4*)(src + row * 256 + c16 * 16);
            int mc = row >> 4, kc = c16 >> 1;
            int g  = ((c16 & 1) << 1) | ((row >> 3) & 1);
            int T0 = (row & 7) * 4;
            char* base = dstp + ((mc * 8 + kc) * 32) * 16 + g * 4;
            *(unsigned*)(base + (T0 + 0) * 16) = val.x;
            *(unsigned*)(base + (T0 + 1) * 16) = val.y;
            *(unsigned*)(base + (T0 + 2) * 16) = val.z;
            *(unsigned*)(base + (T0 + 3) * 16) = val.w;
        }
    }
    #pragma unroll
    for (int p = 0; p < 4; p++) {
        const int8_t* src = wsl + (size_t)(widx * 4 + p) * 65536 + n0 * 256;
        char* dstp = smem + 131072 + p * 16384;
        #pragma unroll
        for (int v = 0; v < 4; v++) {
            int chunk = tid + 256 * v;
            int row = chunk >> 4, c16 = chunk & 15;
            uint4 val = *(const uint4*)(src + row * 256 + c16 * 16);
            int nc = row >> 3, kc = c16 >> 1;
            int g  = c16 & 1;
            int T0 = (row & 7) * 4;
            char* base = dstp + ((nc * 8 + kc) * 32) * 8 + g * 4;
            *(unsigned*)(base + (T0 + 0) * 8) = val.x;
            *(unsigned*)(base + (T0 + 1) * 8) = val.y;
            *(unsigned*)(base + (T0 + 2) * 8) = val.z;
            *(unsigned*)(base + (T0 + 3) * 8) = val.w;
        }
    }
    __syncthreads();

    const int warp = tid >> 5, lane = tid & 31;
    const int wm = warp >> 1, wn = warp & 1;

    long long acc[2][4][4];
    #pragma unroll
    for (int mi = 0; mi < 2; mi++)
        #pragma unroll
        for (int nj = 0; nj < 4; nj++)
            #pragma unroll
            for (int r = 0; r < 4; r++) acc[mi][nj][r] = 0ll;

    const int PI[13] = {0,1,2, 0,1,2,3, 1,2,3, 2,3, 3};
    const int PJ[13] = {2,1,0, 3,2,1,0, 3,2,1, 3,2, 3};
    const int DS[6]  = {0, 3, 7, 10, 12, 13};

    for (int sd = 0; sd < 5; sd++) {
        int cfr[2][4][4];
        #pragma unroll
        for (int mi = 0; mi < 2; mi++)
            #pragma unroll
            for (int nj = 0; nj < 4; nj++)
                #pragma unroll
                for (int r = 0; r < 4; r++) cfr[mi][nj][r] = 0;

        for (int p = DS[sd]; p < DS[sd + 1]; p++) {
            const char* Ap = smem + PI[p] * 32768;
            const char* Bp = smem + 131072 + PJ[p] * 16384;
            #pragma unroll
            for (int kc = 0; kc < 8; kc++) {
                unsigned a[2][4], b[4][2];
                #pragma unroll
                for (int mi = 0; mi < 2; mi++) {
                    uint4 av = *(const uint4*)(Ap + (((2*wm + mi) * 8 + kc) * 32 + lane) * 16);
                    a[mi][0] = av.x; a[mi][1] = av.y; a[mi][2] = av.z; a[mi][3] = av.w;
                }
                #pragma unroll
                for (int nj = 0; nj < 4; nj++) {
                    uint2 bv = *(const uint2*)(Bp + (((4*wn + nj) * 8 + kc) * 32 + lane) * 8);
                    b[nj][0] = bv.x; b[nj][1] = bv.y;
                }
                #pragma unroll
                for (int mi = 0; mi < 2; mi++)
                    #pragma unroll
                    for (int nj = 0; nj < 4; nj++)
                        mma_s8(cfr[mi][nj], a[mi], b[nj]);
            }
        }
        int sh = 8 * sd;
        #pragma unroll
        for (int mi = 0; mi < 2; mi++)
            #pragma unroll
            for (int nj = 0; nj < 4; nj++)
                #pragma unroll
                for (int r = 0; r < 4; r++)
                    acc[mi][nj][r] += ((long long)cfr[mi][nj][r]) << sh;
    }

    double* Zout = (widx == 0) ? Zq : ((widx == 1) ? Zk : Zv);
    const double INV = 1.1368683772161603e-13;   // 2^-43
    #pragma unroll
    for (int mi = 0; mi < 2; mi++)
        #pragma unroll
        for (int nj = 0; nj < 4; nj++)
            #pragma unroll
            for (int r = 0; r < 4; r++) {
                int row = m0 + 32*wm + 16*mi + (lane >> 2) + 8*(r >> 1);
                int col = n0 + 32*wn + 8*nj + 2*(lane & 3) + (r & 1);
                Zout[(size_t)row * H_ + col] = (double)acc[mi][nj][r] * INV;
            }
}

// ===================== proj slice GEMM (IMMA) ===============================
#define PROJ_SMEM (32768 + 4*16384)   // 98304

__global__ void __launch_bounds__(256) gemm_proj_kernel(
    const int8_t* __restrict__ s2, const int8_t* __restrict__ wsl,
    const float* __restrict__ pb, double* __restrict__ Zp)
{
    extern __shared__ char smem[];
    const int tid = threadIdx.x;
    const int nt = blockIdx.x, mt = blockIdx.y;
    const int n0 = nt * 64, m0 = mt * 128;

    {
        const int8_t* src = s2 + (size_t)m0 * 256;
        #pragma unroll
        for (int v = 0; v < 8; v++) {
            int chunk = tid + 256 * v;
            int row = chunk >> 4, c16 = chunk & 15;
            uint4 val = *(const uint4*)(src + row * 256 + c16 * 16);
            int mc = row >> 4, kc = c16 >> 1;
            int g  = ((c16 & 1) << 1) | ((row >> 3) & 1);
            int T0 = (row & 7) * 4;
            char* base = smem + ((mc * 8 + kc) * 32) * 16 + g * 4;
            *(unsigned*)(base + (T0 + 0) * 16) = val.x;
            *(unsigned*)(base + (T0 + 1) * 16) = val.y;
            *(unsigned*)(base + (T0 + 2) * 16) = val.z;
            *(unsigned*)(base + (T0 + 3) * 16) = val.w;
        }
    }
    #pragma unroll
    for (int p = 0; p < 4; p++) {
        const int8_t* src = wsl + (size_t)(12 + p) * 65536 + n0 * 256;
        char* dstp = smem + 32768 + p * 16384;
        #pragma unroll
        for (int v = 0; v < 4; v++) {
            int chunk = tid + 256 * v;
            int row = chunk >> 4, c16 = chunk & 15;
            uint4 val = *(const uint4*)(src + row * 256 + c16 * 16);
            int nc = row >> 3, kc = c16 >> 1;
            int g  = c16 & 1;
            int T0 = (row & 7) * 4;
            char* base = dstp + ((nc * 8 + kc) * 32) * 8 + g * 4;
            *(unsigned*)(base + (T0 + 0) * 8) = val.x;
            *(unsigned*)(base + (T0 + 1) * 8) = val.y;
            *(unsigned*)(base + (T0 + 2) * 8) = val.z;
            *(unsigned*)(base + (T0 + 3) * 8) = val.w;
        }
    }
    __syncthreads();

    const int warp = tid >> 5, lane = tid & 31;
    const int wm = warp >> 1, wn = warp & 1;

    long long acc[2][4][4];
    #pragma unroll
    for (int mi = 0; mi < 2; mi++)
        #pragma unroll
        for (int nj = 0; nj < 4; nj++)
            #pragma unroll
            for (int r = 0; r < 4; r++) acc[mi][nj][r] = 0ll;

    for (int j = 0; j < 4; j++) {
        int cfr[2][4][4];
        #pragma unroll
        for (int mi = 0; mi < 2; mi++)
            #pragma unroll
            for (int nj = 0; nj < 4; nj++)
                #pragma unroll
                for (int r = 0; r < 4; r++) cfr[mi][nj][r] = 0;

        const char* Bp = smem + 32768 + j * 16384;
        #pragma unroll
        for (int kc = 0; kc < 8; kc++) {
            unsigned a[2][4], b[4][2];
            #pragma unroll
            for (int mi = 0; mi < 2; mi++) {
                uint4 av = *(const uint4*)(smem + (((2*wm + mi) * 8 + kc) * 32 + lane) * 16);
                a[mi][0] = av.x; a[mi][1] = av.y; a[mi][2] = av.z; a[mi][3] = av.w;
            }
            #pragma unroll
            for (int nj = 0; nj < 4; nj++) {
                uint2 bv = *(const uint2*)(Bp + (((4*wn + nj) * 8 + kc) * 32 + lane) * 8);
                b[nj][0] = bv.x; b[nj][1] = bv.y;
            }
            #pragma unroll
            for (int mi = 0; mi < 2; mi++)
                #pragma unroll
                for (int nj = 0; nj < 4; nj++)
                    mma_s8(cfr[mi][nj], a[mi], b[nj]);
        }
        int sh = 8 * j;
        #pragma unroll
        for (int mi = 0; mi < 2; mi++)
            #pragma unroll
            for (int nj = 0; nj < 4; nj++)
                #pragma unroll
                for (int r = 0; r < 4; r++)
                    acc[mi][nj][r] += ((long long)cfr[mi][nj][r]) << sh;
    }

    const double INV = 2.3283064365386963e-10;   // 2^-32
    #pragma unroll
    for (int mi = 0; mi < 2; mi++)
        #pragma unroll
        for (int nj = 0; nj < 4; nj++)
            #pragma unroll
            for (int r = 0; r < 4; r++) {
                int row = m0 + 32*wm + 16*mi + (lane >> 2) + 8*(r >> 1);
                int col = n0 + 32*wn + 8*nj + 2*(lane & 3) + (r & 1);
                Zp[(size_t)row * H_ + col] = (double)acc[mi][nj][r] * INV + (double)pb[col];
            }
}

// ===================== warp-level LN/LIF (fp64, no barriers) ================
__device__ __forceinline__ double warp_sum(double v)
{
    #pragma unroll
    for (int o = 16; o; o >>= 1) v += __shfl_xor_sync(0xffffffffu, v, o);
    return v;
}

// one warp = one (b,l); lane handles h = lane*8 + e (e=0..7)
// branch 0/1 -> pack spike bits; branch 2 -> store fp32 spikes for PV
__global__ void __launch_bounds__(256) ln_lif_qkv_kernel(
    const double* __restrict__ Zq, const double* __restrict__ Zk,
    const double* __restrict__ Zv,
    const float* __restrict__ qlw, const float* __restrict__ qlb,
    const float* __restrict__ klw, const float* __restrict__ klb,
    const float* __restrict__ vlw, const float* __restrict__ vlb,
    uint32_t* __restrict__ qb, uint32_t* __restrict__ kb, float* __restrict__ vf)
{
    const int gw = blockIdx.x * 8 + (threadIdx.x >> 5);
    const int lane = threadIdx.x & 31;
    const int b = gw / L_, l = gw % L_;
    const int h0 = lane * 8;

    #pragma unroll
    for (int br = 0; br < 3; br++) {
        const double* Z = (br == 0) ? Zq : ((br == 1) ? Zk : Zv);
        const float* lwp = (br == 0) ? qlw : ((br == 1) ? klw : vlw);
        const float* lbp = (br == 0) ? qlb : ((br == 1) ? klb : vlb);
        double wv[8], bv[8];
        {
            float4 w0 = *(const float4*)(lwp + h0), w1 = *(const float4*)(lwp + h0 + 4);
            float4 b0 = *(const float4*)(lbp + h0), b1 = *(const float4*)(lbp + h0 + 4);
            wv[0]=w0.x; wv[1]=w0.y; wv[2]=w0.z; wv[3]=w0.w;
            wv[4]=w1.x; wv[5]=w1.y; wv[6]=w1.z; wv[7]=w1.w;
            bv[0]=b0.x; bv[1]=b0.y; bv[2]=b0.z; bv[3]=b0.w;
            bv[4]=b1.x; bv[5]=b1.y; bv[6]=b1.z; bv[7]=b1.w;
        }
        double vmem[8];
        #pragma unroll
        for (int e = 0; e < 8; e++) vmem[e] = 0.0;

        for (int t = 0; t < T_; t++) {
            size_t row = (size_t)(t * B_ + b) * L_ + l;
            const double* zr = Z + row * H_ + h0;
            double z[8];
            #pragma unroll
            for (int e = 0; e < 4; e++) {
                double2 p = ((const double2*)zr)[e];
                z[2*e] = p.x; z[2*e+1] = p.y;
            }
            double s = 0.0;
            #pragma unroll
            for (int e = 0; e < 8; e++) s += z[e];
            double mean = warp_sum(s) * (1.0 / H_);
            double dv[8], sq = 0.0;
            #pragma unroll
            for (int e = 0; e < 8; e++) { dv[e] = z[e] - mean; sq += dv[e] * dv[e]; }
            double inv_std = 1.0 / sqrt(warp_sum(sq) * (1.0 / H_) + 1e-5);

            unsigned byte = 0;
            float spf[8];
            #pragma unroll
            for (int e = 0; e < 8; e++) {
                double yv = dv[e] * inv_std * wv[e] + bv[e];
                vmem[e] = vmem[e] + (yv - vmem[e]) * 0.5;
                bool sp = (vmem[e] - 1.0) >= 0.0;
                if (sp) vmem[e] = 0.0;
                byte |= (sp ? 1u : 0u) << e;
                spf[e] = sp ? 1.f : 0.f;
            }
            if (br < 3 - 1) {
                // assemble 32-bit word per h-group g = lane>>2 (4 lanes x 8 bits)
                unsigned v = byte << (8 * (lane & 3));
                v |= __shfl_xor_sync(0xffffffffu, v, 1);
                v |= __shfl_xor_sync(0xffffffffu, v, 2);
                if ((lane & 3) == 0) {
                    int g = lane >> 2;            // 0..7
                    int head = g >> 2, widx = g & 3;
                    uint32_t* dst = (br == 0) ? qb : kb;
                    dst[(((size_t)(t * B_ + b) * 2 + head) * L_ + l) * 4 + widx] = v;
                }
            } else {
                int head = lane >> 4;
                int d = 8 * (lane & 15);
                float* dst = vf + (((size_t)(t * B_ + b) * 2 + head) * L_ + l) * 128 + d;
                *(float4*)(dst)     = make_float4(spf[0], spf[1], spf[2], spf[3]);
                *(float4*)(dst + 4) = make_float4(spf[4], spf[5], spf[6], spf[7]);
            }
        }
    }
}

// warp-level proj LN -> LIF(1.0) -> output spikes
__global__ void __launch_bounds__(256) proj_ln_lif_kernel(
    const double* __restrict__ Zp, const float* __restrict__ lw,
    const float* __restrict__ lb, float* __restrict__ out)
{
    const int gw = blockIdx.x * 8 + (threadIdx.x >> 5);
    const int lane = threadIdx.x & 31;
    const int b = gw / L_, l = gw % L_;
    const int h0 = lane * 8;

    double wv[8], bv[8];
    {
        float4 w0 = *(const float4*)(lw + h0), w1 = *(const float4*)(lw + h0 + 4);
        float4 b0 = *(const float4*)(lb + h0), b1 = *(const float4*)(lb + h0 + 4);
        wv[0]=w0.x; wv[1]=w0.y; wv[2]=w0.z; wv[3]=w0.w;
        wv[4]=w1.x; wv[5]=w1.y; wv[6]=w1.z; wv[7]=w1.w;
        bv[0]=b0.x; bv[1]=b0.y; bv[2]=b0.z; bv[3]=b0.w;
        bv[4]=b1.x; bv[5]=b1.y; bv[6]=b1.z; bv[7]=b1.w;
    }
    double vmem[8];
    #pragma unroll
    for (int e = 0; e < 8; e++) vmem[e] = 0.0;

    for (int t = 0; t < T_; t++) {
        size_t row = (size_t)(t * B_ + b) * L_ + l;
        const double* zr = Zp + row * H_ + h0;
        double z[8];
        #pragma unroll
        for (int e = 0; e < 4; e++) {
            double2 p = ((const double2*)zr)[e];
            z[2*e] = p.x; z[2*e+1] = p.y;
        }
        double s = 0.0;
        #pragma unroll
        for (int e = 0; e < 8; e++) s += z[e];
        double mean = warp_sum(s) * (1.0 / H_);
        double dv[8], sq = 0.0;
        #pragma unroll
        for (int e = 0; e < 8; e++) { dv[e] = z[e] - mean; sq += dv[e] * dv[e]; }
        double inv_std = 1.0 / sqrt(warp_sum(sq) * (1.0 / H_) + 1e-5);

        float spf[8];
        #pragma unroll
        for (int e = 0; e < 8; e++) {
            double yv = dv[e] * inv_std * wv[e] + bv[e];
            vmem[e] = vmem[e] + (yv - vmem[e]) * 0.5;
            bool sp = (vmem[e] - 1.0) >= 0.0;
            if (sp) vmem[e] = 0.0;
            spf[e] = sp ? 1.f : 0.f;
        }
        float* dst = out + row * H_ + h0;
        *(float4*)(dst)     = make_float4(spf[0], spf[1], spf[2], spf[3]);
        *(float4*)(dst + 4) = make_float4(spf[4], spf[5], spf[6], spf[7]);
    }
}

// ===================== attention (exact fp32) ===============================
#define ATTN_SMEM ((L_*128 + 8*L_*4)*4 + L_*4*4)   // 131200 bytes

__global__ void __launch_bounds__(256) attn_kernel(
    const uint32_t* __restrict__ qb, const uint32_t* __restrict__ kb,
    const float* __restrict__ vf, float* __restrict__ y)
{
    extern __shared__ char smem_raw[];
    float*    sv    = (float*)smem_raw;           // [200][128]
    uint32_t* skb   = (uint32_t*)(sv + L_ * 128); // [200][4]
    float*    sattn = (float*)(skb + L_ * 4);     // [8][200][4]

    const int batch = blockIdx.x;
    const uint32_t* qb_b = qb + (size_t)batch * L_ * 4;
    const uint32_t* kb_b = kb + (size_t)batch * L_ * 4;
    const float*    v_b  = vf + (size_t)batch * L_ * 128;
    float*          y_b  = y  + (size_t)batch * L_ * 128;

    const int tid = threadIdx.x;
    for (int i = tid; i < L_ * 4; i += 256) skb[i] = kb_b[i];
    for (int i = tid; i < L_ * 32; i += 256) ((float4*)sv)[i] = ((const float4*)v_b)[i];
    __syncthreads();

    const int warp = tid >> 5, lane = tid & 31;
    float* aw = sattn + warp * (L_ * 4);
    const float* svl = sv + lane * 4;

    for (int base = warp * 4; base < L_; base += 32) {
        #pragma unroll
        for (int r = 0; r < 4; r++) {
            const int lrow = base + r;
            uint32_t q0 = qb_b[lrow*4+0], q1 = qb_b[lrow*4+1];
            uint32_t q2 = qb_b[lrow*4+2], q3 = qb_b[lrow*4+3];
            for (int m = lane; m < L_; m += 32) {
                int c = __popc(q0 & skb[m*4+0]) + __popc(q1 & skb[m*4+1])
                      + __popc(q2 & skb[m*4+2]) + __popc(q3 & skb[m*4+3]);
                aw[m*4 + r] = (float)c * 0.125f;
            }
        }
        __syncwarp();
        float4 acc0 = {0,0,0,0}, acc1 = {0,0,0,0}, acc2 = {0,0,0,0}, acc3 = {0,0,0,0};
        #pragma unroll 4
        for (int m = 0; m < L_; m++) {
            float4 a  = *(const float4*)(aw  + m * 4);
            float4 vv = *(const float4*)(svl + m * 128);
            acc0.x += a.x*vv.x; acc0.y += a.x*vv.y; acc0.z += a.x*vv.z; acc0.w += a.x*vv.w;
            acc1.x += a.y*vv.x; acc1.y += a.y*vv.y; acc1.z += a.y*vv.z; acc1.w += a.y*vv.w;
            acc2.x += a.z*vv.x; acc2.y += a.z*vv.y; acc2.z += a.z*vv.z; acc2.w += a.z*vv.w;
            acc3.x += a.w*vv.x; acc3.y += a.w*vv.y; acc3.z += a.w*vv.z; acc3.w += a.w*vv.w;
        }
        *(float4*)(y_b + (size_t)(base + 0) * 128 + lane * 4) = acc0;
        *(float4*)(y_b + (size_t)(base + 1) * 128 + lane * 4) = acc1;
        *(float4*)(y_b + (size_t)(base + 2) * 128 + lane * 4) = acc2;
        *(float4*)(y_b + (size_t)(base + 3) * 128 + lane * 4) = acc3;
        __syncwarp();
    }
}

// ---------------------------------------------------------------------------
__global__ void __launch_bounds__(256) attn_lif_kernel(
    const float* __restrict__ y, int8_t* __restrict__ s2)
{
    const int bl = blockIdx.x;
    const int b = bl / L_, l = bl % L_;
    const int h = threadIdx.x;
    const int head = h >> 7, d = h & 127;
    float vmem = 0.f;
    #pragma unroll
    for (int t = 0; t < T_; t++) {
        float yv = y[(((size_t)(t * B_ + b) * 2 + head) * L_ + l) * 128 + d];
        vmem = vmem + (yv - vmem) * 0.5f;
        bool sp = (vmem - 0.5f) >= 0.f;
        if (sp) vmem = 0.f;
        s2[((size_t)(t * B_ + b) * L_ + l) * H_ + h] = sp ? 1 : 0;
    }
}

// ---------------------------------------------------------------------------
extern "C" void kernel_launch(void* const* d_in, const int* in_sizes, int n_in,
                              void* d_out, int out_size)
{
    const float* x   = (const float*)d_in[0];
    const float* qw  = (const float*)d_in[1];
    const float* qlw = (const float*)d_in[2];
    const float* qlb = (const float*)d_in[3];
    const float* kw  = (const float*)d_in[4];
    const float* klw = (const float*)d_in[5];
    const float* klb = (const float*)d_in[6];
    const float* vw  = (const float*)d_in[7];
    const float* vlw = (const float*)d_in[8];
    const float* vlb = (const float*)d_in[9];
    const float* pw  = (const float*)d_in[10];
    const float* pb  = (const float*)d_in[11];
    const float* plw = (const float*)d_in[12];
    const float* plb = (const float*)d_in[13];
    float* out = (float*)d_out;

    int8_t *asl, *wsl, *s2;
    double *Zq, *Zk, *Zv, *zp;
    float *vf, *yv;
    uint32_t *qbp, *kbp;
    cudaGetSymbolAddress((void**)&asl, g_asl);
    cudaGetSymbolAddress((void**)&wsl, g_wsl);
    cudaGetSymbolAddress((void**)&s2,  g_s2);
    cudaGetSymbolAddress((void**)&Zq,  g_Zq);
    cudaGetSymbolAddress((void**)&Zk,  g_Zk);
    cudaGetSymbolAddress((void**)&Zv,  g_Zv);
    cudaGetSymbolAddress((void**)&zp,  g_zp);
    cudaGetSymbolAddress((void**)&vf,  g_vf);
    cudaGetSymbolAddress((void**)&yv,  g_y);
    cudaGetSymbolAddress((void**)&qbp, g_qb);
    cudaGetSymbolAddress((void**)&kbp, g_kb);

    cudaFuncSetAttribute(gemm_qkv_kernel, cudaFuncAttributeMaxDynamicSharedMemorySize, QKV_SMEM);
    cudaFuncSetAttribute(gemm_proj_kernel, cudaFuncAttributeMaxDynamicSharedMemorySize, PROJ_SMEM);
    cudaFuncSetAttribute(attn_kernel, cudaFuncAttributeMaxDynamicSharedMemorySize, ATTN_SMEM);

    slice_x_kernel<<<4096, 256>>>(x, asl);
    slice_w_kernel<<<256, 256>>>(qw, kw, vw, pw, wsl);

    dim3 gq(12, 400);
    gemm_qkv_kernel<<<gq, 256, QKV_SMEM>>>(asl, wsl, Zq, Zk, Zv);

    ln_lif_qkv_kernel<<<BLr / 8, 256>>>(Zq, Zk, Zv, qlw, qlb, klw, klb, vlw, vlb,
                                        qbp, kbp, vf);

    attn_kernel<<<NBATCH, 256, ATTN_SMEM>>>(qbp, kbp, vf, yv);

    attn_lif_kernel<<<BLr, 256>>>(yv, s2);

    dim3 gp(4, 400);
    gemm_proj_kernel<<<gp, 256, PROJ_SMEM>>>(s2, wsl, pb, zp);

    proj_ln_lif_kernel<<<BLr / 8, 256>>>(zp, plw, plb, out);
}

// round 8
// speedup vs baseline: 6.5358x; 1.0025x over previous
#include <cuda_runtime.h>
#include <cstdint>
#include <cmath>

// ---------------------------------------------------------------------------
// SSA forward: exact int8 IMMA GEMM + latency-optimized warp LN/LIF.
// GEMMs: x*2^27, w*2^32 -> 4 balanced s8 digits; digit-pair GEMMs on
// mma.sync.m16n8k32.s8.s8.s32 (exact); int64 shift-add recombine; fp64 out.
// LN/LIF: one warp per (branch,b,l); all T=4 rows loaded up-front (MLP=4);
// single-pass moments (E[z^2]-mean^2) with 8 interleaved shfl chains; LIF
// scan in registers. No smem, no block barriers.
// Attention: binary q,k popcount + fp32 PV (exact dyadic rationals).
// ---------------------------------------------------------------------------

#define T_  4
#define B_  64
#define L_  200
#define H_  256
#define M_  (T_*B_*L_)      // 51200
#define BLr (B_*L_)         // 12800
#define NBATCH (T_*B_*2)    // 512 (t,b,head)

__device__ __align__(128) int8_t g_asl[4ull*M_*H_];
__device__ __align__(128) int8_t g_wsl[16ull*H_*H_];
__device__ __align__(128) int8_t g_s2[(size_t)M_*H_];
__device__ double   g_Zq[(size_t)M_*H_];
__device__ double   g_Zk[(size_t)M_*H_];
__device__ double   g_Zv[(size_t)M_*H_];
__device__ double   g_zp[(size_t)M_*H_];
__device__ uint32_t g_qb[NBATCH*L_*4];
__device__ uint32_t g_kb[NBATCH*L_*4];
__device__ float    g_vf[(size_t)NBATCH*L_*128];
__device__ float    g_y [(size_t)NBATCH*L_*128];

// ---------------------------------------------------------------------------
__device__ __forceinline__ void mma_s8(int* c, const unsigned* a, const unsigned* b)
{
    asm volatile(
        "mma.sync.aligned.m16n8k32.row.col.s32.s8.s8.s32 "
        "{%0,%1,%2,%3}, {%4,%5,%6,%7}, {%8,%9}, {%0,%1,%2,%3};"
        : "+r"(c[0]), "+r"(c[1]), "+r"(c[2]), "+r"(c[3])
        : "r"(a[0]), "r"(a[1]), "r"(a[2]), "r"(a[3]), "r"(b[0]), "r"(b[1]));
}

// ===================== digit-slice generation ===============================
__global__ void slice_x_kernel(const float* __restrict__ x, int8_t* __restrict__ asl)
{
    int i = blockIdx.x * blockDim.x + threadIdx.x;
    int stride = gridDim.x * blockDim.x;
    const size_t plane = (size_t)M_ * H_;
    for (; i < M_ * H_; i += stride) {
        int q = __double2int_rn((double)x[i] * 134217728.0);  // 2^27
        #pragma unroll
        for (int s = 0; s < 4; s++) {
            int d = ((q + 128) & 255) - 128;
            q = (q - d) >> 8;
            asl[s * plane + i] = (int8_t)d;
        }
    }
}

__global__ void slice_w_kernel(const float* __restrict__ qw, const float* __restrict__ kw,
                               const float* __restrict__ vw, const float* __restrict__ pw,
                               int8_t* __restrict__ wsl)
{
    int i = blockIdx.x * blockDim.x + threadIdx.x;
    int stride = gridDim.x * blockDim.x;
    for (; i < 4 * H_ * H_; i += stride) {
        int widx = i >> 16, j = i & 65535;
        const float* W = (widx == 0) ? qw : ((widx == 1) ? kw : ((widx == 2) ? vw : pw));
        long long q = __double2ll_rn((double)W[j] * 4294967296.0);  // 2^32
        #pragma unroll
        for (int s = 0; s < 4; s++) {
            int d = (int)(((q + 128) & 255)) - 128;
            q = (q - d) >> 8;
            wsl[(size_t)(widx * 4 + s) * 65536 + j] = (int8_t)d;
        }
    }
}

// ===================== qkv slice GEMM (IMMA) ================================
#define QKV_SMEM (4*32768 + 4*16384)   // 196608

__global__ void __launch_bounds__(256) gemm_qkv_kernel(
    const int8_t* __restrict__ asl, const int8_t* __restrict__ wsl,
    double* __restrict__ Zq, double* __restrict__ Zk, double* __restrict__ Zv)
{
    extern __shared__ char smem[];
    const int tid = threadIdx.x;
    const int nt = blockIdx.x, mt = blockIdx.y;
    const int widx = nt >> 2, n0 = (nt & 3) * 64, m0 = mt * 128;

    #pragma unroll
    for (int p = 0; p < 4; p++) {
        const int8_t* src = asl + (size_t)p * M_ * H_ + (size_t)m0 * 256;
        char* dstp = smem + p * 32768;
        #pragma unroll
        for (int v = 0; v < 8; v++) {
            int chunk = tid + 256 * v;
            int row = chunk >> 4, c16 = chunk & 15;
            uint4 val = *(const uint4*)(src + row * 256 + c16 * 16);
            int mc = row >> 4, kc = c16 >> 1;
            int g  = ((c16 & 1) << 1) | ((row >> 3) & 1);
            int T0 = (row & 7) * 4;
            char* base = dstp + ((mc * 8 + kc) * 32) * 16 + g * 4;
            *(unsigned*)(base + (T0 + 0) * 16) = val.x;
            *(unsigned*)(base + (T0 + 1) * 16) = val.y;
            *(unsigned*)(base + (T0 + 2) * 16) = val.z;
            *(unsigned*)(base + (T0 + 3) * 16) = val.w;
        }
    }
    #pragma unroll
    for (int p = 0; p < 4; p++) {
        const int8_t* src = wsl + (size_t)(widx * 4 + p) * 65536 + n0 * 256;
        char* dstp = smem + 131072 + p * 16384;
        #pragma unroll
        for (int v = 0; v < 4; v++) {
            int chunk = tid + 256 * v;
            int row = chunk >> 4, c16 = chunk & 15;
            uint4 val = *(const uint4*)(src + row * 256 + c16 * 16);
            int nc = row >> 3, kc = c16 >> 1;
            int g  = c16 & 1;
            int T0 = (row & 7) * 4;
            char* base = dstp + ((nc * 8 + kc) * 32) * 8 + g * 4;
            *(unsigned*)(base + (T0 + 0) * 8) = val.x;
            *(unsigned*)(base + (T0 + 1) * 8) = val.y;
            *(unsigned*)(base + (T0 + 2) * 8) = val.z;
            *(unsigned*)(base + (T0 + 3) * 8) = val.w;
        }
    }
    __syncthreads();

    const int warp = tid >> 5, lane = tid & 31;
    const int wm = warp >> 1, wn = warp & 1;

    long long acc[2][4][4];
    #pragma unroll
    for (int mi = 0; mi < 2; mi++)
        #pragma unroll
        for (int nj = 0; nj < 4; nj++)
            #pragma unroll
            for (int r = 0; r < 4; r++) acc[mi][nj][r] = 0ll;

    const int PI[13] = {0,1,2, 0,1,2,3, 1,2,3, 2,3, 3};
    const int PJ[13] = {2,1,0, 3,2,1,0, 3,2,1, 3,2, 3};
    const int DS[6]  = {0, 3, 7, 10, 12, 13};

    for (int sd = 0; sd < 5; sd++) {
        int cfr[2][4][4];
        #pragma unroll
        for (int mi = 0; mi < 2; mi++)
            #pragma unroll
            for (int nj = 0; nj < 4; nj++)
                #pragma unroll
                for (int r = 0; r < 4; r++) cfr[mi][nj][r] = 0;

        for (int p = DS[sd]; p < DS[sd + 1]; p++) {
            const char* Ap = smem + PI[p] * 32768;
            const char* Bp = smem + 131072 + PJ[p] * 16384;
            #pragma unroll
            for (int kc = 0; kc < 8; kc++) {
                unsigned a[2][4], b[4][2];
                #pragma unroll
                for (int mi = 0; mi < 2; mi++) {
                    uint4 av = *(const uint4*)(Ap + (((2*wm + mi) * 8 + kc) * 32 + lane) * 16);
                    a[mi][0] = av.x; a[mi][1] = av.y; a[mi][2] = av.z; a[mi][3] = av.w;
                }
                #pragma unroll
                for (int nj = 0; nj < 4; nj++) {
                    uint2 bv = *(const uint2*)(Bp + (((4*wn + nj) * 8 + kc) * 32 + lane) * 8);
                    b[nj][0] = bv.x; b[nj][1] = bv.y;
                }
                #pragma unroll
                for (int mi = 0; mi < 2; mi++)
                    #pragma unroll
                    for (int nj = 0; nj < 4; nj++)
                        mma_s8(cfr[mi][nj], a[mi], b[nj]);
            }
        }
        int sh = 8 * sd;
        #pragma unroll
        for (int mi = 0; mi < 2; mi++)
            #pragma unroll
            for (int nj = 0; nj < 4; nj++)
                #pragma unroll
                for (int r = 0; r < 4; r++)
                    acc[mi][nj][r] += ((long long)cfr[mi][nj][r]) << sh;
    }

    double* Zout = (widx == 0) ? Zq : ((widx == 1) ? Zk : Zv);
    const double INV = 1.1368683772161603e-13;   // 2^-43
    #pragma unroll
    for (int mi = 0; mi < 2; mi++)
        #pragma unroll
        for (int nj = 0; nj < 4; nj++)
            #pragma unroll
            for (int r = 0; r < 4; r++) {
                int row = m0 + 32*wm + 16*mi + (lane >> 2) + 8*(r >> 1);
                int col = n0 + 32*wn + 8*nj + 2*(lane & 3) + (r & 1);
                Zout[(size_t)row * H_ + col] = (double)acc[mi][nj][r] * INV;
            }
}

// ===================== proj slice GEMM (IMMA) ===============================
#define PROJ_SMEM (32768 + 4*16384)   // 98304

__global__ void __launch_bounds__(256) gemm_proj_kernel(
    const int8_t* __restrict__ s2, const int8_t* __restrict__ wsl,
    const float* __restrict__ pb, double* __restrict__ Zp)
{
    extern __shared__ char smem[];
    const int tid = threadIdx.x;
    const int nt = blockIdx.x, mt = blockIdx.y;
    const int n0 = nt * 64, m0 = mt * 128;

    {
        const int8_t* src = s2 + (size_t)m0 * 256;
        #pragma unroll
        for (int v = 0; v < 8; v++) {
            int chunk = tid + 256 * v;
            int row = chunk >> 4, c16 = chunk & 15;
            uint4 val = *(const uint4*)(src + row * 256 + c16 * 16);
            int mc = row >> 4, kc = c16 >> 1;
            int g  = ((c16 & 1) << 1) | ((row >> 3) & 1);
            int T0 = (row & 7) * 4;
            char* base = smem + ((mc * 8 + kc) * 32) * 16 + g * 4;
            *(unsigned*)(base + (T0 + 0) * 16) = val.x;
            *(unsigned*)(base + (T0 + 1) * 16) = val.y;
            *(unsigned*)(base + (T0 + 2) * 16) = val.z;
            *(unsigned*)(base + (T0 + 3) * 16) = val.w;
        }
    }
    #pragma unroll
    for (int p = 0; p < 4; p++) {
        const int8_t* src = wsl + (size_t)(12 + p) * 65536 + n0 * 256;
        char* dstp = smem + 32768 + p * 16384;
        #pragma unroll
        for (int v = 0; v < 4; v++) {
            int chunk = tid + 256 * v;
            int row = chunk >> 4, c16 = chunk & 15;
            uint4 val = *(const uint4*)(src + row * 256 + c16 * 16);
            int nc = row >> 3, kc = c16 >> 1;
            int g  = c16 & 1;
            int T0 = (row & 7) * 4;
            char* base = dstp + ((nc * 8 + kc) * 32) * 8 + g * 4;
            *(unsigned*)(base + (T0 + 0) * 8) = val.x;
            *(unsigned*)(base + (T0 + 1) * 8) = val.y;
            *(unsigned*)(base + (T0 + 2) * 8) = val.z;
            *(unsigned*)(base + (T0 + 3) * 8) = val.w;
        }
    }
    __syncthreads();

    const int warp = tid >> 5, lane = tid & 31;
    const int wm = warp >> 1, wn = warp & 1;

    long long acc[2][4][4];
    #pragma unroll
    for (int mi = 0; mi < 2; mi++)
        #pragma unroll
        for (int nj = 0; nj < 4; nj++)
            #pragma unroll
            for (int r = 0; r < 4; r++) acc[mi][nj][r] = 0ll;

    for (int j = 0; j < 4; j++) {
        int cfr[2][4][4];
        #pragma unroll
        for (int mi = 0; mi < 2; mi++)
            #pragma unroll
            for (int nj = 0; nj < 4; nj++)
                #pragma unroll
                for (int r = 0; r < 4; r++) cfr[mi][nj][r] = 0;

        const char* Bp = smem + 32768 + j * 16384;
        #pragma unroll
        for (int kc = 0; kc < 8; kc++) {
            unsigned a[2][4], b[4][2];
            #pragma unroll
            for (int mi = 0; mi < 2; mi++) {
                uint4 av = *(const uint4*)(smem + (((2*wm + mi) * 8 + kc) * 32 + lane) * 16);
                a[mi][0] = av.x; a[mi][1] = av.y; a[mi][2] = av.z; a[mi][3] = av.w;
            }
            #pragma unroll
            for (int nj = 0; nj < 4; nj++) {
                uint2 bv = *(const uint2*)(Bp + (((4*wn + nj) * 8 + kc) * 32 + lane) * 8);
                b[nj][0] = bv.x; b[nj][1] = bv.y;
            }
            #pragma unroll
            for (int mi = 0; mi < 2; mi++)
                #pragma unroll
                for (int nj = 0; nj < 4; nj++)
                    mma_s8(cfr[mi][nj], a[mi], b[nj]);
        }
        int sh = 8 * j;
        #pragma unroll
        for (int mi = 0; mi < 2; mi++)
            #pragma unroll
            for (int nj = 0; nj < 4; nj++)
                #pragma unroll
                for (int r = 0; r < 4; r++)
                    acc[mi][nj][r] += ((long long)cfr[mi][nj][r]) << sh;
    }

    const double INV = 2.3283064365386963e-10;   // 2^-32
    #pragma unroll
    for (int mi = 0; mi < 2; mi++)
        #pragma unroll
        for (int nj = 0; nj < 4; nj++)
            #pragma unroll
            for (int r = 0; r < 4; r++) {
                int row = m0 + 32*wm + 16*mi + (lane >> 2) + 8*(r >> 1);
                int col = n0 + 32*wn + 8*nj + 2*(lane & 3) + (r & 1);
                Zp[(size_t)row * H_ + col] = (double)acc[mi][nj][r] * INV + (double)pb[col];
            }
}

// ===================== warp-level LN/LIF (fp64, latency-optimized) ==========
// one warp = one (branch,b,l); all 4 t rows loaded up-front; single-pass
// moments (E[z^2]-mean^2) with 8 interleaved shfl chains; LIF in registers.
__global__ void __launch_bounds__(256, 2) ln_lif_qkv_kernel(
    const double* __restrict__ Zq, const double* __restrict__ Zk,
    const double* __restrict__ Zv,
    const float* __restrict__ qlw, const float* __restrict__ qlb,
    const float* __restrict__ klw, const float* __restrict__ klb,
    const float* __restrict__ vlw, const float* __restrict__ vlb,
    uint32_t* __restrict__ qb, uint32_t* __restrict__ kb, float* __restrict__ vf)
{
    const int gw = blockIdx.x * 8 + (threadIdx.x >> 5);
    const int lane = threadIdx.x & 31;
    const int br = blockIdx.y;
    const int b = gw / L_, l = gw % L_;
    const int h0 = lane * 8;

    const double* Z = (br == 0) ? Zq : ((br == 1) ? Zk : Zv);
    const float* lwp = (br == 0) ? qlw : ((br == 1) ? klw : vlw);
    const float* lbp = (br == 0) ? qlb : ((br == 1) ? klb : vlb);

    float wv[8], bvv[8];
    {
        float4 w0 = *(const float4*)(lwp + h0), w1 = *(const float4*)(lwp + h0 + 4);
        float4 c0 = *(const float4*)(lbp + h0), c1 = *(const float4*)(lbp + h0 + 4);
        wv[0]=w0.x; wv[1]=w0.y; wv[2]=w0.z; wv[3]=w0.w;
        wv[4]=w1.x; wv[5]=w1.y; wv[6]=w1.z; wv[7]=w1.w;
        bvv[0]=c0.x; bvv[1]=c0.y; bvv[2]=c0.z; bvv[3]=c0.w;
        bvv[4]=c1.x; bvv[5]=c1.y; bvv[6]=c1.z; bvv[7]=c1.w;
    }

    // load all 4 t rows (MLP=4)
    double z[4][8];
    #pragma unroll
    for (int t = 0; t < T_; t++) {
        const double* zr = Z + ((size_t)(t * B_ + b) * L_ + l) * H_ + h0;
        #pragma unroll
        for (int e = 0; e < 4; e++) {
            double2 p = ((const double2*)zr)[e];
            z[t][2*e] = p.x; z[t][2*e+1] = p.y;
        }
    }

    // per-lane partial sums
    double s[4], q2[4];
    #pragma unroll
    for (int t = 0; t < T_; t++) {
        double a = 0.0, c = 0.0;
        #pragma unroll
        for (int e = 0; e < 8; e++) { a += z[t][e]; c += z[t][e] * z[t][e]; }
        s[t] = a; q2[t] = c;
    }
    // interleaved warp reductions (8 independent chains)
    #pragma unroll
    for (int o = 16; o; o >>= 1) {
        #pragma unroll
        for (int t = 0; t < T_; t++) {
            s[t]  += __shfl_xor_sync(0xffffffffu, s[t],  o);
            q2[t] += __shfl_xor_sync(0xffffffffu, q2[t], o);
        }
    }

    double vmem[8];
    #pragma unroll
    for (int e = 0; e < 8; e++) vmem[e] = 0.0;

    #pragma unroll
    for (int t = 0; t < T_; t++) {
        double mean = s[t] * (1.0 / H_);
        double var  = q2[t] * (1.0 / H_) - mean * mean;
        double inv_std = 1.0 / sqrt(var + 1e-5);

        unsigned byte = 0;
        float spf[8];
        #pragma unroll
        for (int e = 0; e < 8; e++) {
            double yv = (z[t][e] - mean) * inv_std * (double)wv[e] + (double)bvv[e];
            vmem[e] = vmem[e] + (yv - vmem[e]) * 0.5;
            bool sp = (vmem[e] - 1.0) >= 0.0;
            if (sp) vmem[e] = 0.0;
            byte |= (sp ? 1u : 0u) << e;
            spf[e] = sp ? 1.f : 0.f;
        }
        if (br < 2) {
            unsigned v = byte << (8 * (lane & 3));
            v |= __shfl_xor_sync(0xffffffffu, v, 1);
            v |= __shfl_xor_sync(0xffffffffu, v, 2);
            if ((lane & 3) == 0) {
                int g = lane >> 2;
                int head = g >> 2, widx = g & 3;
                uint32_t* dst = (br == 0) ? qb : kb;
                dst[(((size_t)(t * B_ + b) * 2 + head) * L_ + l) * 4 + widx] = v;
            }
        } else {
            int head = lane >> 4;
            int d = 8 * (lane & 15);
            float* dst = vf + (((size_t)(t * B_ + b) * 2 + head) * L_ + l) * 128 + d;
            *(float4*)(dst)     = make_float4(spf[0], spf[1], spf[2], spf[3]);
            *(float4*)(dst + 4) = make_float4(spf[4], spf[5], spf[6], spf[7]);
        }
    }
}

// proj LN -> LIF(1.0) -> output spikes, same structure
__global__ void __launch_bounds__(256, 2) proj_ln_lif_kernel(
    const double* __restrict__ Zp, const float* __restrict__ lw,
    const float* __restrict__ lb, float* __restrict__ out)
{
    const int gw = blockIdx.x * 8 + (threadIdx.x >> 5);
    const int lane = threadIdx.x & 31;
    const int b = gw / L_, l = gw % L_;
    const int h0 = lane * 8;

    float wv[8], bvv[8];
    {
        float4 w0 = *(const float4*)(lw + h0), w1 = *(const float4*)(lw + h0 + 4);
        float4 c0 = *(const float4*)(lb + h0), c1 = *(const float4*)(lb + h0 + 4);
        wv[0]=w0.x; wv[1]=w0.y; wv[2]=w0.z; wv[3]=w0.w;
        wv[4]=w1.x; wv[5]=w1.y; wv[6]=w1.z; wv[7]=w1.w;
        bvv[0]=c0.x; bvv[1]=c0.y; bvv[2]=c0.z; bvv[3]=c0.w;
        bvv[4]=c1.x; bvv[5]=c1.y; bvv[6]=c1.z; bvv[7]=c1.w;
    }

    double z[4][8];
    #pragma unroll
    for (int t = 0; t < T_; t++) {
        const double* zr = Zp + ((size_t)(t * B_ + b) * L_ + l) * H_ + h0;
        #pragma unroll
        for (int e = 0; e < 4; e++) {
            double2 p = ((const double2*)zr)[e];
            z[t][2*e] = p.x; z[t][2*e+1] = p.y;
        }
    }

    double s[4], q2[4];
    #pragma unroll
    for (int t = 0; t < T_; t++) {
        double a = 0.0, c = 0.0;
        #pragma unroll
        for (int e = 0; e < 8; e++) { a += z[t][e]; c += z[t][e] * z[t][e]; }
        s[t] = a; q2[t] = c;
    }
    #pragma unroll
    for (int o = 16; o; o >>= 1) {
        #pragma unroll
        for (int t = 0; t < T_; t++) {
            s[t]  += __shfl_xor_sync(0xffffffffu, s[t],  o);
            q2[t] += __shfl_xor_sync(0xffffffffu, q2[t], o);
        }
    }

    double vmem[8];
    #pragma unroll
    for (int e = 0; e < 8; e++) vmem[e] = 0.0;

    #pragma unroll
    for (int t = 0; t < T_; t++) {
        double mean = s[t] * (1.0 / H_);
        double var  = q2[t] * (1.0 / H_) - mean * mean;
        double inv_std = 1.0 / sqrt(var + 1e-5);
        float spf[8];
        #pragma unroll
        for (int e = 0; e < 8; e++) {
            double yv = (z[t][e] - mean) * inv_std * (double)wv[e] + (double)bvv[e];
            vmem[e] = vmem[e] + (yv - vmem[e]) * 0.5;
            bool sp = (vmem[e] - 1.0) >= 0.0;
            if (sp) vmem[e] = 0.0;
            spf[e] = sp ? 1.f : 0.f;
        }
        float* dst = out + ((size_t)(t * B_ + b) * L_ + l) * H_ + h0;
        *(float4*)(dst)     = make_float4(spf[0], spf[1], spf[2], spf[3]);
        *(float4*)(dst + 4) = make_float4(spf[4], spf[5], spf[6], spf[7]);
    }
}

// ===================== attention (exact fp32) ===============================
#define ATTN_SMEM ((L_*128 + 8*L_*4)*4 + L_*4*4)   // 131200 bytes

__global__ void __launch_bounds__(256) attn_kernel(
    const uint32_t* __restrict__ qb, const uint32_t* __restrict__ kb,
    const float* __restrict__ vf, float* __restrict__ y)
{
    extern __shared__ char smem_raw[];
    float*    sv    = (float*)smem_raw;
    uint32_t* skb   = (uint32_t*)(sv + L_ * 128);
    float*    sattn = (float*)(skb + L_ * 4);

    const int batch = blockIdx.x;
    const uint32_t* qb_b = qb + (size_t)batch * L_ * 4;
    const uint32_t* kb_b = kb + (size_t)batch * L_ * 4;
    const float*    v_b  = vf + (size_t)batch * L_ * 128;
    float*          y_b  = y  + (size_t)batch * L_ * 128;

    const int tid = threadIdx.x;
    for (int i = tid; i < L_ * 4; i += 256) skb[i] = kb_b[i];
    for (int i = tid; i < L_ * 32; i += 256) ((float4*)sv)[i] = ((const float4*)v_b)[i];
    __syncthreads();

    const int warp = tid >> 5, lane = tid & 31;
    float* aw = sattn + warp * (L_ * 4);
    const float* svl = sv + lane * 4;

    for (int base = warp * 4; base < L_; base += 32) {
        #pragma unroll
        for (int r = 0; r < 4; r++) {
            const int lrow = base + r;
            uint32_t q0 = qb_b[lrow*4+0], q1 = qb_b[lrow*4+1];
            uint32_t q2 = qb_b[lrow*4+2], q3 = qb_b[lrow*4+3];
            for (int m = lane; m < L_; m += 32) {
                int c = __popc(q0 & skb[m*4+0]) + __popc(q1 & skb[m*4+1])
                      + __popc(q2 & skb[m*4+2]) + __popc(q3 & skb[m*4+3]);
                aw[m*4 + r] = (float)c * 0.125f;
            }
        }
        __syncwarp();
        float4 acc0 = {0,0,0,0}, acc1 = {0,0,0,0}, acc2 = {0,0,0,0}, acc3 = {0,0,0,0};
        #pragma unroll 4
        for (int m = 0; m < L_; m++) {
            float4 a  = *(const float4*)(aw  + m * 4);
            float4 vv = *(const float4*)(svl + m * 128);
            acc0.x += a.x*vv.x; acc0.y += a.x*vv.y; acc0.z += a.x*vv.z; acc0.w += a.x*vv.w;
            acc1.x += a.y*vv.x; acc1.y += a.y*vv.y; acc1.z += a.y*vv.z; acc1.w += a.y*vv.w;
            acc2.x += a.z*vv.x; acc2.y += a.z*vv.y; acc2.z += a.z*vv.z; acc2.w += a.z*vv.w;
            acc3.x += a.w*vv.x; acc3.y += a.w*vv.y; acc3.z += a.w*vv.z; acc3.w += a.w*vv.w;
        }
        *(float4*)(y_b + (size_t)(base + 0) * 128 + lane * 4) = acc0;
        *(float4*)(y_b + (size_t)(base + 1) * 128 + lane * 4) = acc1;
        *(float4*)(y_b + (size_t)(base + 2) * 128 + lane * 4) = acc2;
        *(float4*)(y_b + (size_t)(base + 3) * 128 + lane * 4) = acc3;
        __syncwarp();
    }
}

// ---------------------------------------------------------------------------
__global__ void __launch_bounds__(256) attn_lif_kernel(
    const float* __restrict__ y, int8_t* __restrict__ s2)
{
    const int bl = blockIdx.x;
    const int b = bl / L_, l = bl % L_;
    const int h = threadIdx.x;
    const int head = h >> 7, d = h & 127;
    float yv[4];
    #pragma unroll
    for (int t = 0; t < T_; t++)
        yv[t] = y[(((size_t)(t * B_ + b) * 2 + head) * L_ + l) * 128 + d];
    float vmem = 0.f;
    #pragma unroll
    for (int t = 0; t < T_; t++) {
        vmem = vmem + (yv[t] - vmem) * 0.5f;
        bool sp = (vmem - 0.5f) >= 0.f;
        if (sp) vmem = 0.f;
        s2[((size_t)(t * B_ + b) * L_ + l) * H_ + h] = sp ? 1 : 0;
    }
}

// ---------------------------------------------------------------------------
extern "C" void kernel_launch(void* const* d_in, const int* in_sizes, int n_in,
                              void* d_out, int out_size)
{
    const float* x   = (const float*)d_in[0];
    const float* qw  = (const float*)d_in[1];
    const float* qlw = (const float*)d_in[2];
    const float* qlb = (const float*)d_in[3];
    const float* kw  = (const float*)d_in[4];
    const float* klw = (const float*)d_in[5];
    const float* klb = (const float*)d_in[6];
    const float* vw  = (const float*)d_in[7];
    const float* vlw = (const float*)d_in[8];
    const float* vlb = (const float*)d_in[9];
    const float* pw  = (const float*)d_in[10];
    const float* pb  = (const float*)d_in[11];
    const float* plw = (const float*)d_in[12];
    const float* plb = (const float*)d_in[13];
    float* out = (float*)d_out;

    int8_t *asl, *wsl, *s2;
    double *Zq, *Zk, *Zv, *zp;
    float *vf, *yv;
    uint32_t *qbp, *kbp;
    cudaGetSymbolAddress((void**)&asl, g_asl);
    cudaGetSymbolAddress((void**)&wsl, g_wsl);
    cudaGetSymbolAddress((void**)&s2,  g_s2);
    cudaGetSymbolAddress((void**)&Zq,  g_Zq);
    cudaGetSymbolAddress((void**)&Zk,  g_Zk);
    cudaGetSymbolAddress((void**)&Zv,  g_Zv);
    cudaGetSymbolAddress((void**)&zp,  g_zp);
    cudaGetSymbolAddress((void**)&vf,  g_vf);
    cudaGetSymbolAddress((void**)&yv,  g_y);
    cudaGetSymbolAddress((void**)&qbp, g_qb);
    cudaGetSymbolAddress((void**)&kbp, g_kb);

    cudaFuncSetAttribute(gemm_qkv_kernel, cudaFuncAttributeMaxDynamicSharedMemorySize, QKV_SMEM);
    cudaFuncSetAttribute(gemm_proj_kernel, cudaFuncAttributeMaxDynamicSharedMemorySize, PROJ_SMEM);
    cudaFuncSetAttribute(attn_kernel, cudaFuncAttributeMaxDynamicSharedMemorySize, ATTN_SMEM);

    slice_x_kernel<<<4096, 256>>>(x, asl);
    slice_w_kernel<<<256, 256>>>(qw, kw, vw, pw, wsl);

    dim3 gq(12, 400);
    gemm_qkv_kernel<<<gq, 256, QKV_SMEM>>>(asl, wsl, Zq, Zk, Zv);

    dim3 gl(BLr / 8, 3);
    ln_lif_qkv_kernel<<<gl, 256>>>(Zq, Zk, Zv, qlw, qlb, klw, klb, vlw, vlb,
                                   qbp, kbp, vf);

    attn_kernel<<<NBATCH, 256, ATTN_SMEM>>>(qbp, kbp, vf, yv);

    attn_lif_kernel<<<BLr, 256>>>(yv, s2);

    dim3 gp(4, 400);
    gemm_proj_kernel<<<gp, 256, PROJ_SMEM>>>(s2, wsl, pb, zp);

    proj_ln_lif_kernel<<<BLr / 8, 256>>>(zp, plw, plb, out);
}

// round 11
// speedup vs baseline: 6.8022x; 1.0408x over previous
#include <cuda_runtime.h>
#include <cstdint>
#include <cmath>

// ---------------------------------------------------------------------------
// SSA forward: exact int8 IMMA GEMM + integer-statistics LN/LIF.
// GEMMs: x*2^27, w*2^32 -> 4 balanced s8 digits; digit-pair GEMMs on
// mma.sync.m16n8k32.s8.s8.s32 (exact); int64 shift-add recombine; epilogue
// quantizes Z to int32 at Z*2^27 (<=0.5ulp = 3.7e-9, proven-safe level).
// LN/LIF: warp per (branch,b,l); row sums in EXACT int64 (4-cyc IADD chains,
// not 47-cyc fp64), variance in fp64 from exact ints, one rsqrt per row with
// the 2^27 scale folded in; LIF chain fp64 (exact decisions).
// Attention: binary q,k popcount + fp32 PV (exact dyadic rationals).
// ---------------------------------------------------------------------------

#define T_  4
#define B_  64
#define L_  200
#define H_  256
#define M_  (T_*B_*L_)      // 51200
#define BLr (B_*L_)         // 12800
#define NBATCH (T_*B_*2)    // 512 (t,b,head)

__device__ __align__(128) int8_t g_asl[4ull*M_*H_];
__device__ __align__(128) int8_t g_wsl[16ull*H_*H_];
__device__ __align__(128) int8_t g_s2[(size_t)M_*H_];
__device__ __align__(128) int g_Zq[(size_t)M_*H_];   // Z*2^27 as int32
__device__ __align__(128) int g_Zk[(size_t)M_*H_];
__device__ __align__(128) int g_Zv[(size_t)M_*H_];
__device__ __align__(128) int g_zp[(size_t)M_*H_];
__device__ uint32_t g_qb[NBATCH*L_*4];
__device__ uint32_t g_kb[NBATCH*L_*4];
__device__ float    g_vf[(size_t)NBATCH*L_*128];
__device__ float    g_y [(size_t)NBATCH*L_*128];

// ---------------------------------------------------------------------------
__device__ __forceinline__ void mma_s8(int* c, const unsigned* a, const unsigned* b)
{
    asm volatile(
        "mma.sync.aligned.m16n8k32.row.col.s32.s8.s8.s32 "
        "{%0,%1,%2,%3}, {%4,%5,%6,%7}, {%8,%9}, {%0,%1,%2,%3};"
        : "+r"(c[0]), "+r"(c[1]), "+r"(c[2]), "+r"(c[3])
        : "r"(a[0]), "r"(a[1]), "r"(a[2]), "r"(a[3]), "r"(b[0]), "r"(b[1]));
}

// ===================== digit-slice generation ===============================
__global__ void slice_x_kernel(const float* __restrict__ x, int8_t* __restrict__ asl)
{
    int i = blockIdx.x * blockDim.x + threadIdx.x;
    int stride = gridDim.x * blockDim.x;
    const size_t plane = (size_t)M_ * H_;
    for (; i < M_ * H_; i += stride) {
        int q = __double2int_rn((double)x[i] * 134217728.0);  // 2^27
        #pragma unroll
        for (int s = 0; s < 4; s++) {
            int d = ((q + 128) & 255) - 128;
            q = (q - d) >> 8;
            asl[s * plane + i] = (int8_t)d;
        }
    }
}

__global__ void slice_w_kernel(const float* __restrict__ qw, const float* __restrict__ kw,
                               const float* __restrict__ vw, const float* __restrict__ pw,
                               int8_t* __restrict__ wsl)
{
    int i = blockIdx.x * blockDim.x + threadIdx.x;
    int stride = gridDim.x * blockDim.x;
    for (; i < 4 * H_ * H_; i += stride) {
        int widx = i >> 16, j = i & 65535;
        const float* W = (widx == 0) ? qw : ((widx == 1) ? kw : ((widx == 2) ? vw : pw));
        long long q = __double2ll_rn((double)W[j] * 4294967296.0);  // 2^32
        #pragma unroll
        for (int s = 0; s < 4; s++) {
            int d = (int)(((q + 128) & 255)) - 128;
            q = (q - d) >> 8;
            wsl[(size_t)(widx * 4 + s) * 65536 + j] = (int8_t)d;
        }
    }
}

// ===================== qkv slice GEMM (IMMA) ================================
#define QKV_SMEM (4*32768 + 4*16384)   // 196608

__global__ void __launch_bounds__(256) gemm_qkv_kernel(
    const int8_t* __restrict__ asl, const int8_t* __restrict__ wsl,
    int* __restrict__ Zq, int* __restrict__ Zk, int* __restrict__ Zv)
{
    extern __shared__ char smem[];
    const int tid = threadIdx.x;
    const int nt = blockIdx.x, mt = blockIdx.y;
    const int widx = nt >> 2, n0 = (nt & 3) * 64, m0 = mt * 128;

    #pragma unroll
    for (int p = 0; p < 4; p++) {
        const int8_t* src = asl + (size_t)p * M_ * H_ + (size_t)m0 * 256;
        char* dstp = smem + p * 32768;
        #pragma unroll
        for (int v = 0; v < 8; v++) {
            int chunk = tid + 256 * v;
            int row = chunk >> 4, c16 = chunk & 15;
            uint4 val = *(const uint4*)(src + row * 256 + c16 * 16);
            int mc = row >> 4, kc = c16 >> 1;
            int g  = ((c16 & 1) << 1) | ((row >> 3) & 1);
            int T0 = (row & 7) * 4;
            char* base = dstp + ((mc * 8 + kc) * 32) * 16 + g * 4;
            *(unsigned*)(base + (T0 + 0) * 16) = val.x;
            *(unsigned*)(base + (T0 + 1) * 16) = val.y;
            *(unsigned*)(base + (T0 + 2) * 16) = val.z;
            *(unsigned*)(base + (T0 + 3) * 16) = val.w;
        }
    }
    #pragma unroll
    for (int p = 0; p < 4; p++) {
        const int8_t* src = wsl + (size_t)(widx * 4 + p) * 65536 + n0 * 256;
        char* dstp = smem + 131072 + p * 16384;
        #pragma unroll
        for (int v = 0; v < 4; v++) {
            int chunk = tid + 256 * v;
            int row = chunk >> 4, c16 = chunk & 15;
            uint4 val = *(const uint4*)(src + row * 256 + c16 * 16);
            int nc = row >> 3, kc = c16 >> 1;
            int g  = c16 & 1;
            int T0 = (row & 7) * 4;
            char* base = dstp + ((nc * 8 + kc) * 32) * 8 + g * 4;
            *(unsigned*)(base + (T0 + 0) * 8) = val.x;
            *(unsigned*)(base + (T0 + 1) * 8) = val.y;
            *(unsigned*)(base + (T0 + 2) * 8) = val.z;
            *(unsigned*)(base + (T0 + 3) * 8) = val.w;
        }
    }
    __syncthreads();

    const int warp = tid >> 5, lane = tid & 31;
    const int wm = warp >> 1, wn = warp & 1;

    long long acc[2][4][4];
    #pragma unroll
    for (int mi = 0; mi < 2; mi++)
        #pragma unroll
        for (int nj = 0; nj < 4; nj++)
            #pragma unroll
            for (int r = 0; r < 4; r++) acc[mi][nj][r] = 0ll;

    const int PI[13] = {0,1,2, 0,1,2,3, 1,2,3, 2,3, 3};
    const int PJ[13] = {2,1,0, 3,2,1,0, 3,2,1, 3,2, 3};
    const int DS[6]  = {0, 3, 7, 10, 12, 13};

    for (int sd = 0; sd < 5; sd++) {
        int cfr[2][4][4];
        #pragma unroll
        for (int mi = 0; mi < 2; mi++)
            #pragma unroll
            for (int nj = 0; nj < 4; nj++)
                #pragma unroll
                for (int r = 0; r < 4; r++) cfr[mi][nj][r] = 0;

        for (int p = DS[sd]; p < DS[sd + 1]; p++) {
            const char* Ap = smem + PI[p] * 32768;
            const char* Bp = smem + 131072 + PJ[p] * 16384;
            #pragma unroll
            for (int kc = 0; kc < 8; kc++) {
                unsigned a[2][4], b[4][2];
                #pragma unroll
                for (int mi = 0; mi < 2; mi++) {
                    uint4 av = *(const uint4*)(Ap + (((2*wm + mi) * 8 + kc) * 32 + lane) * 16);
                    a[mi][0] = av.x; a[mi][1] = av.y; a[mi][2] = av.z; a[mi][3] = av.w;
                }
                #pragma unroll
                for (int nj = 0; nj < 4; nj++) {
                    uint2 bv = *(const uint2*)(Bp + (((4*wn + nj) * 8 + kc) * 32 + lane) * 8);
                    b[nj][0] = bv.x; b[nj][1] = bv.y;
                }
                #pragma unroll
                for (int mi = 0; mi < 2; mi++)
                    #pragma unroll
                    for (int nj = 0; nj < 4; nj++)
                        mma_s8(cfr[mi][nj], a[mi], b[nj]);
            }
        }
        int sh = 8 * sd;
        #pragma unroll
        for (int mi = 0; mi < 2; mi++)
            #pragma unroll
            for (int nj = 0; nj < 4; nj++)
                #pragma unroll
                for (int r = 0; r < 4; r++)
                    acc[mi][nj][r] += ((long long)cfr[mi][nj][r]) << sh;
    }

    // epilogue: zint = round(acc * 2^-16)  (Z*2^27 as int32; acc = Z*2^43)
    int* Zout = (widx == 0) ? Zq : ((widx == 1) ? Zk : Zv);
    #pragma unroll
    for (int mi = 0; mi < 2; mi++)
        #pragma unroll
        for (int nj = 0; nj < 4; nj++)
            #pragma unroll
            for (int r = 0; r < 4; r++) {
                int row = m0 + 32*wm + 16*mi + (lane >> 2) + 8*(r >> 1);
                int col = n0 + 32*wn + 8*nj + 2*(lane & 3) + (r & 1);
                Zout[(size_t)row * H_ + col] = (int)((acc[mi][nj][r] + 32768ll) >> 16);
            }
}

// ===================== proj slice GEMM (IMMA) ===============================
#define PROJ_SMEM (32768 + 4*16384)   // 98304

__global__ void __launch_bounds__(256) gemm_proj_kernel(
    const int8_t* __restrict__ s2, const int8_t* __restrict__ wsl,
    int* __restrict__ Zp)
{
    extern __shared__ char smem[];
    const int tid = threadIdx.x;
    const int nt = blockIdx.x, mt = blockIdx.y;
    const int n0 = nt * 64, m0 = mt * 128;

    {
        const int8_t* src = s2 + (size_t)m0 * 256;
        #pragma unroll
        for (int v = 0; v < 8; v++) {
            int chunk = tid + 256 * v;
            int row = chunk >> 4, c16 = chunk & 15;
            uint4 val = *(const uint4*)(src + row * 256 + c16 * 16);
            int mc = row >> 4, kc = c16 >> 1;
            int g  = ((c16 & 1) << 1) | ((row >> 3) & 1);
            int T0 = (row & 7) * 4;
            char* base = smem + ((mc * 8 + kc) * 32) * 16 + g * 4;
            *(unsigned*)(base + (T0 + 0) * 16) = val.x;
            *(unsigned*)(base + (T0 + 1) * 16) = val.y;
            *(unsigned*)(base + (T0 + 2) * 16) = val.z;
            *(unsigned*)(base + (T0 + 3) * 16) = val.w;
        }
    }
    #pragma unroll
    for (int p = 0; p < 4; p++) {
        const int8_t* src = wsl + (size_t)(12 + p) * 65536 + n0 * 256;
        char* dstp = smem + 32768 + p * 16384;
        #pragma unroll
        for (int v = 0; v < 4; v++) {
            int chunk = tid + 256 * v;
            int row = chunk >> 4, c16 = chunk & 15;
            uint4 val = *(const uint4*)(src + row * 256 + c16 * 16);
            int nc = row >> 3, kc = c16 >> 1;
            int g  = c16 & 1;
            int T0 = (row & 7) * 4;
            char* base = dstp + ((nc * 8 + kc) * 32) * 8 + g * 4;
            *(unsigned*)(base + (T0 + 0) * 8) = val.x;
            *(unsigned*)(base + (T0 + 1) * 8) = val.y;
            *(unsigned*)(base + (T0 + 2) * 8) = val.z;
            *(unsigned*)(base + (T0 + 3) * 8) = val.w;
        }
    }
    __syncthreads();

    const int warp = tid >> 5, lane = tid & 31;
    const int wm = warp >> 1, wn = warp & 1;

    long long acc[2][4][4];
    #pragma unroll
    for (int mi = 0; mi < 2; mi++)
        #pragma unroll
        for (int nj = 0; nj < 4; nj++)
            #pragma unroll
            for (int r = 0; r < 4; r++) acc[mi][nj][r] = 0ll;

    for (int j = 0; j < 4; j++) {
        int cfr[2][4][4];
        #pragma unroll
        for (int mi = 0; mi < 2; mi++)
            #pragma unroll
            for (int nj = 0; nj < 4; nj++)
                #pragma unroll
                for (int r = 0; r < 4; r++) cfr[mi][nj][r] = 0;

        const char* Bp = smem + 32768 + j * 16384;
        #pragma unroll
        for (int kc = 0; kc < 8; kc++) {
            unsigned a[2][4], b[4][2];
            #pragma unroll
            for (int mi = 0; mi < 2; mi++) {
                uint4 av = *(const uint4*)(smem + (((2*wm + mi) * 8 + kc) * 32 + lane) * 16);
                a[mi][0] = av.x; a[mi][1] = av.y; a[mi][2] = av.z; a[mi][3] = av.w;
            }
            #pragma unroll
            for (int nj = 0; nj < 4; nj++) {
                uint2 bv = *(const uint2*)(Bp + (((4*wn + nj) * 8 + kc) * 32 + lane) * 8);
                b[nj][0] = bv.x; b[nj][1] = bv.y;
            }
            #pragma unroll
            for (int mi = 0; mi < 2; mi++)
                #pragma unroll
                for (int nj = 0; nj < 4; nj++)
                    mma_s8(cfr[mi][nj], a[mi], b[nj]);
        }
        int sh = 8 * j;
        #pragma unroll
        for (int mi = 0; mi < 2; mi++)
            #pragma unroll
            for (int nj = 0; nj < 4; nj++)
                #pragma unroll
                for (int r = 0; r < 4; r++)
                    acc[mi][nj][r] += ((long long)cfr[mi][nj][r]) << sh;
    }

    // epilogue: zint = round(acc * 2^-5)  (Zgemm*2^27; acc = Zgemm*2^32)
    // pb is added in the LN kernel (fp64), not here.
    #pragma unroll
    for (int mi = 0; mi < 2; mi++)
        #pragma unroll
        for (int nj = 0; nj < 4; nj++)
            #pragma unroll
            for (int r = 0; r < 4; r++) {
                int row = m0 + 32*wm + 16*mi + (lane >> 2) + 8*(r >> 1);
                int col = n0 + 32*wn + 8*nj + 2*(lane & 3) + (r & 1);
                Zp[(size_t)row * H_ + col] = (int)((acc[mi][nj][r] + 16ll) >> 5);
            }
}

// ===================== warp-level LN/LIF (int stats + fp64 decisions) =======
// units: z_u = Z*2^27 (int32, exact). mean_u = sum/256 (fp64 EXACT).
// C = inv_std*2^-27 = 1/sqrt(var_u + 1e-5*2^54);  yv = (z_u-mean_u)*C*w + b.
#define EPS_U 1.8014398509481984e11   // 1e-5 * 2^54

__global__ void __launch_bounds__(256, 3) ln_lif_qkv_kernel(
    const int* __restrict__ Zq, const int* __restrict__ Zk,
    const int* __restrict__ Zv,
    const float* __restrict__ qlw, const float* __restrict__ qlb,
    const float* __restrict__ klw, const float* __restrict__ klb,
    const float* __restrict__ vlw, const float* __restrict__ vlb,
    uint32_t* __restrict__ qb, uint32_t* __restrict__ kb, float* __restrict__ vf)
{
    const int gw = blockIdx.x * 8 + (threadIdx.x >> 5);
    const int lane = threadIdx.x & 31;
    const int br = blockIdx.y;
    const int b = gw / L_, l = gw % L_;
    const int h0 = lane * 8;

    const int* Z = (br == 0) ? Zq : ((br == 1) ? Zk : Zv);
    const float* lwp = (br == 0) ? qlw : ((br == 1) ? klw : vlw);
    const float* lbp = (br == 0) ? qlb : ((br == 1) ? klb : vlb);

    float wv[8], bvv[8];
    {
        float4 w0 = *(const float4*)(lwp + h0), w1 = *(const float4*)(lwp + h0 + 4);
        float4 c0 = *(const float4*)(lbp + h0), c1 = *(const float4*)(lbp + h0 + 4);
        wv[0]=w0.x; wv[1]=w0.y; wv[2]=w0.z; wv[3]=w0.w;
        wv[4]=w1.x; wv[5]=w1.y; wv[6]=w1.z; wv[7]=w1.w;
        bvv[0]=c0.x; bvv[1]=c0.y; bvv[2]=c0.z; bvv[3]=c0.w;
        bvv[4]=c1.x; bvv[5]=c1.y; bvv[6]=c1.z; bvv[7]=c1.w;
    }

    // load all 4 t rows (8 x LDG.128, MLP=8)
    int zi[4][8];
    #pragma unroll
    for (int t = 0; t < T_; t++) {
        const int* zr = Z + ((size_t)(t * B_ + b) * L_ + l) * H_ + h0;
        int4 p0 = ((const int4*)zr)[0];
        int4 p1 = ((const int4*)zr)[1];
        zi[t][0]=p0.x; zi[t][1]=p0.y; zi[t][2]=p0.z; zi[t][3]=p0.w;
        zi[t][4]=p1.x; zi[t][5]=p1.y; zi[t][6]=p1.z; zi[t][7]=p1.w;
    }

    // per-lane partials: exact int64 sums, fp64 sum of squares
    long long s[4];
    double q2[4];
    #pragma unroll
    for (int t = 0; t < T_; t++) {
        long long a = 0;
        double c = 0.0;
        #pragma unroll
        for (int e = 0; e < 8; e++) {
            a += zi[t][e];
            double d = (double)zi[t][e];
            c += d * d;
        }
        s[t] = a; q2[t] = c;
    }
    #pragma unroll
    for (int o = 16; o; o >>= 1) {
        #pragma unroll
        for (int t = 0; t < T_; t++) {
            s[t]  += __shfl_xor_sync(0xffffffffu, s[t],  o);
            q2[t] += __shfl_xor_sync(0xffffffffu, q2[t], o);
        }
    }

    double vmem[8];
    #pragma unroll
    for (int e = 0; e < 8; e++) vmem[e] = 0.0;

    #pragma unroll
    for (int t = 0; t < T_; t++) {
        double mean = (double)s[t] * (1.0 / 256.0);            // exact
        double var_u = q2[t] * (1.0 / 256.0) - mean * mean;
        double C = 1.0 / sqrt(var_u + EPS_U);

        unsigned byte = 0;
        float spf[8];
        #pragma unroll
        for (int e = 0; e < 8; e++) {
            double yv = ((double)zi[t][e] - mean) * C * (double)wv[e] + (double)bvv[e];
            vmem[e] = vmem[e] + (yv - vmem[e]) * 0.5;
            bool sp = (vmem[e] - 1.0) >= 0.0;
            if (sp) vmem[e] = 0.0;
            byte |= (sp ? 1u : 0u) << e;
            spf[e] = sp ? 1.f : 0.f;
        }
        if (br < 2) {
            unsigned v = byte << (8 * (lane & 3));
            v |= __shfl_xor_sync(0xffffffffu, v, 1);
            v |= __shfl_xor_sync(0xffffffffu, v, 2);
            if ((lane & 3) == 0) {
                int g = lane >> 2;
                int head = g >> 2, widx = g & 3;
                uint32_t* dst = (br == 0) ? qb : kb;
                dst[(((size_t)(t * B_ + b) * 2 + head) * L_ + l) * 4 + widx] = v;
            }
        } else {
            int head = lane >> 4;
            int d = 8 * (lane & 15);
            float* dst = vf + (((size_t)(t * B_ + b) * 2 + head) * L_ + l) * 128 + d;
            *(float4*)(dst)     = make_float4(spf[0], spf[1], spf[2], spf[3]);
            *(float4*)(dst + 4) = make_float4(spf[4], spf[5], spf[6], spf[7]);
        }
    }
}

// proj LN -> LIF(1.0) -> output spikes; y_u = zint + pb*2^27 (fp64)
__global__ void __launch_bounds__(256, 3) proj_ln_lif_kernel(
    const int* __restrict__ Zp, const float* __restrict__ pb,
    const float* __restrict__ lw, const float* __restrict__ lb,
    float* __restrict__ out)
{
    const int gw = blockIdx.x * 8 + (threadIdx.x >> 5);
    const int lane = threadIdx.x & 31;
    const int b = gw / L_, l = gw % L_;
    const int h0 = lane * 8;

    float wv[8], bvv[8];
    double pbu[8];
    {
        float4 w0 = *(const float4*)(lw + h0), w1 = *(const float4*)(lw + h0 + 4);
        float4 c0 = *(const float4*)(lb + h0), c1 = *(const float4*)(lb + h0 + 4);
        float4 p0 = *(const float4*)(pb + h0), p1 = *(const float4*)(pb + h0 + 4);
        wv[0]=w0.x; wv[1]=w0.y; wv[2]=w0.z; wv[3]=w0.w;
        wv[4]=w1.x; wv[5]=w1.y; wv[6]=w1.z; wv[7]=w1.w;
        bvv[0]=c0.x; bvv[1]=c0.y; bvv[2]=c0.z; bvv[3]=c0.w;
        bvv[4]=c1.x; bvv[5]=c1.y; bvv[6]=c1.z; bvv[7]=c1.w;
        pbu[0]=(double)p0.x*134217728.0; pbu[1]=(double)p0.y*134217728.0;
        pbu[2]=(double)p0.z*134217728.0; pbu[3]=(double)p0.w*134217728.0;
        pbu[4]=(double)p1.x*134217728.0; pbu[5]=(double)p1.y*134217728.0;
        pbu[6]=(double)p1.z*134217728.0; pbu[7]=(double)p1.w*134217728.0;
    }
    // warp-wide sum of pb (reused for every t)
    double pbsum;
    {
        double a = 0.0;
        #pragma unroll
        for (int e = 0; e < 8; e++) a += pbu[e];
        #pragma unroll
        for (int o = 16; o; o >>= 1) a += __shfl_xor_sync(0xffffffffu, a, o);
        pbsum = a;
    }

    int zi[4][8];
    #pragma unroll
    for (int t = 0; t < T_; t++) {
        const int* zr = Zp + ((size_t)(t * B_ + b) * L_ + l) * H_ + h0;
        int4 p0 = ((const int4*)zr)[0];
        int4 p1 = ((const int4*)zr)[1];
        zi[t][0]=p0.x; zi[t][1]=p0.y; zi[t][2]=p0.z; zi[t][3]=p0.w;
        zi[t][4]=p1.x; zi[t][5]=p1.y; zi[t][6]=p1.z; zi[t][7]=p1.w;
    }

    long long s[4];
    double q2[4];
    #pragma unroll
    for (int t = 0; t < T_; t++) {
        long long a = 0;
        double c = 0.0;
        #pragma unroll
        for (int e = 0; e < 8; e++) {
            a += zi[t][e];
            double yu = (double)zi[t][e] + pbu[e];
            c += yu * yu;
        }
        s[t] = a; q2[t] = c;
    }
    #pragma unroll
    for (int o = 16; o; o >>= 1) {
        #pragma unroll
        for (int t = 0; t < T_; t++) {
            s[t]  += __shfl_xor_sync(0xffffffffu, s[t],  o);
            q2[t] += __shfl_xor_sync(0xffffffffu, q2[t], o);
        }
    }

    double vmem[8];
    #pragma unroll
    for (int e = 0; e < 8; e++) vmem[e] = 0.0;

    #pragma unroll
    for (int t = 0; t < T_; t++) {
        double mean = ((double)s[t] + pbsum) * (1.0 / 256.0);
        double var_u = q2[t] * (1.0 / 256.0) - mean * mean;
        double C = 1.0 / sqrt(var_u + EPS_U);
        float spf[8];
        #pragma unroll
        for (int e = 0; e < 8; e++) {
            double yu = (double)zi[t][e] + pbu[e];
            double yv = (yu - mean) * C * (double)wv[e] + (double)bvv[e];
            vmem[e] = vmem[e] + (yv - vmem[e]) * 0.5;
            bool sp = (vmem[e] - 1.0) >= 0.0;
            if (sp) vmem[e] = 0.0;
            spf[e] = sp ? 1.f : 0.f;
        }
        float* dst = out + ((size_t)(t * B_ + b) * L_ + l) * H_ + h0;
        *(float4*)(dst)     = make_float4(spf[0], spf[1], spf[2], spf[3]);
        *(float4*)(dst + 4) = make_float4(spf[4], spf[5], spf[6], spf[7]);
    }
}

// ===================== attention (exact fp32) ===============================
#define ATTN_SMEM ((L_*128 + 8*L_*4)*4 + L_*4*4)   // 131200 bytes

__global__ void __launch_bounds__(256) attn_kernel(
    const uint32_t* __restrict__ qb, const uint32_t* __restrict__ kb,
    const float* __restrict__ vf, float* __restrict__ y)
{
    extern __shared__ char smem_raw[];
    float*    sv    = (float*)smem_raw;
    uint32_t* skb   = (uint32_t*)(sv + L_ * 128);
    float*    sattn = (float*)(skb + L_ * 4);

    const int batch = blockIdx.x;
    const uint32_t* qb_b = qb + (size_t)batch * L_ * 4;
    const uint32_t* kb_b = kb + (size_t)batch * L_ * 4;
    const float*    v_b  = vf + (size_t)batch * L_ * 128;
    float*          y_b  = y  + (size_t)batch * L_ * 128;

    const int tid = threadIdx.x;
    for (int i = tid; i < L_ * 4; i += 256) skb[i] = kb_b[i];
    for (int i = tid; i < L_ * 32; i += 256) ((float4*)sv)[i] = ((const float4*)v_b)[i];
    __syncthreads();

    const int warp = tid >> 5, lane = tid & 31;
    float* aw = sattn + warp * (L_ * 4);
    const float* svl = sv + lane * 4;

    for (int base = warp * 4; base < L_; base += 32) {
        #pragma unroll
        for (int r = 0; r < 4; r++) {
            const int lrow = base + r;
            uint32_t q0 = qb_b[lrow*4+0], q1 = qb_b[lrow*4+1];
            uint32_t q2 = qb_b[lrow*4+2], q3 = qb_b[lrow*4+3];
            for (int m = lane; m < L_; m += 32) {
                int c = __popc(q0 & skb[m*4+0]) + __popc(q1 & skb[m*4+1])
                      + __popc(q2 & skb[m*4+2]) + __popc(q3 & skb[m*4+3]);
                aw[m*4 + r] = (float)c * 0.125f;
            }
        }
        __syncwarp();
        float4 acc0 = {0,0,0,0}, acc1 = {0,0,0,0}, acc2 = {0,0,0,0}, acc3 = {0,0,0,0};
        #pragma unroll 4
        for (int m = 0; m < L_; m++) {
            float4 a  = *(const float4*)(aw  + m * 4);
            float4 vv = *(const float4*)(svl + m * 128);
            acc0.x += a.x*vv.x; acc0.y += a.x*vv.y; acc0.z += a.x*vv.z; acc0.w += a.x*vv.w;
            acc1.x += a.y*vv.x; acc1.y += a.y*vv.y; acc1.z += a.y*vv.z; acc1.w += a.y*vv.w;
            acc2.x += a.z*vv.x; acc2.y += a.z*vv.y; acc2.z += a.z*vv.z; acc2.w += a.z*vv.w;
            acc3.x += a.w*vv.x; acc3.y += a.w*vv.y; acc3.z += a.w*vv.z; acc3.w += a.w*vv.w;
        }
        *(float4*)(y_b + (size_t)(base + 0) * 128 + lane * 4) = acc0;
        *(float4*)(y_b + (size_t)(base + 1) * 128 + lane * 4) = acc1;
        *(float4*)(y_b + (size_t)(base + 2) * 128 + lane * 4) = acc2;
        *(float4*)(y_b + (size_t)(base + 3) * 128 + lane * 4) = acc3;
        __syncwarp();
    }
}

// ---------------------------------------------------------------------------
__global__ void __launch_bounds__(256) attn_lif_kernel(
    const float* __restrict__ y, int8_t* __restrict__ s2)
{
    const int bl = blockIdx.x;
    const int b = bl / L_, l = bl % L_;
    const int h = threadIdx.x;
    const int head = h >> 7, d = h & 127;
    float yv[4];
    #pragma unroll
    for (int t = 0; t < T_; t++)
        yv[t] = y[(((size_t)(t * B_ + b) * 2 + head) * L_ + l) * 128 + d];
    float vmem = 0.f;
    #pragma unroll
    for (int t = 0; t < T_; t++) {
        vmem = vmem + (yv[t] - vmem) * 0.5f;
        bool sp = (vmem - 0.5f) >= 0.f;
        if (sp) vmem = 0.f;
        s2[((size_t)(t * B_ + b) * L_ + l) * H_ + h] = sp ? 1 : 0;
    }
}

// ---------------------------------------------------------------------------
extern "C" void kernel_launch(void* const* d_in, const int* in_sizes, int n_in,
                              void* d_out, int out_size)
{
    const float* x   = (const float*)d_in[0];
    const float* qw  = (const float*)d_in[1];
    const float* qlw = (const float*)d_in[2];
    const float* qlb = (const float*)d_in[3];
    const float* kw  = (const float*)d_in[4];
    const float* klw = (const float*)d_in[5];
    const float* klb = (const float*)d_in[6];
    const float* vw  = (const float*)d_in[7];
    const float* vlw = (const float*)d_in[8];
    const float* vlb = (const float*)d_in[9];
    const float* pw  = (const float*)d_in[10];
    const float* pb  = (const float*)d_in[11];
    const float* plw = (const float*)d_in[12];
    const float* plb = (const float*)d_in[13];
    float* out = (float*)d_out;

    int8_t *asl, *wsl, *s2;
    int *Zq, *Zk, *Zv, *zp;
    float *vf, *yv;
    uint32_t *qbp, *kbp;
    cudaGetSymbolAddress((void**)&asl, g_asl);
    cudaGetSymbolAddress((void**)&wsl, g_wsl);
    cudaGetSymbolAddress((void**)&s2,  g_s2);
    cudaGetSymbolAddress((void**)&Zq,  g_Zq);
    cudaGetSymbolAddress((void**)&Zk,  g_Zk);
    cudaGetSymbolAddress((void**)&Zv,  g_Zv);
    cudaGetSymbolAddress((void**)&zp,  g_zp);
    cudaGetSymbolAddress((void**)&vf,  g_vf);
    cudaGetSymbolAddress((void**)&yv,  g_y);
    cudaGetSymbolAddress((void**)&qbp, g_qb);
    cudaGetSymbolAddress((void**)&kbp, g_kb);

    cudaFuncSetAttribute(gemm_qkv_kernel, cudaFuncAttributeMaxDynamicSharedMemorySize, QKV_SMEM);
    cudaFuncSetAttribute(gemm_proj_kernel, cudaFuncAttributeMaxDynamicSharedMemorySize, PROJ_SMEM);
    cudaFuncSetAttribute(attn_kernel, cudaFuncAttributeMaxDynamicSharedMemorySize, ATTN_SMEM);

    slice_x_kernel<<<4096, 256>>>(x, asl);
    slice_w_kernel<<<256, 256>>>(qw, kw, vw, pw, wsl);

    dim3 gq(12, 400);
    gemm_qkv_kernel<<<gq, 256, QKV_SMEM>>>(asl, wsl, Zq, Zk, Zv);

    dim3 gl(BLr / 8, 3);
    ln_lif_qkv_kernel<<<gl, 256>>>(Zq, Zk, Zv, qlw, qlb, klw, klb, vlw, vlb,
                                   qbp, kbp, vf);

    attn_kernel<<<NBATCH, 256, ATTN_SMEM>>>(qbp, kbp, vf, yv);

    attn_lif_kernel<<<BLr, 256>>>(yv, s2);

    dim3 gp(4, 400);
    gemm_proj_kernel<<<gp, 256, PROJ_SMEM>>>(s2, wsl, zp);

    proj_ln_lif_kernel<<<BLr / 8, 256>>>(zp, pb, plw, plb, out);
}

// round 13
// speedup vs baseline: 8.7345x; 1.2841x over previous
#include <cuda_runtime.h>
#include <cstdint>
#include <cmath>

// ---------------------------------------------------------------------------
// SSA forward: exact int8 IMMA GEMM + fixed-point LN/LIF (fp64 only for one
// rsqrt per row and one DFMA per (t,e) scale factor).
// GEMMs: x*2^27, w*2^32 -> 4 balanced s8 digits; digit-pair GEMMs on
// mma.sync.m16n8k32.s8.s8.s32 (exact); int64 shift-add recombine; epilogue
// quantizes Z to int32 at Z*2^27 (<=0.5ulp).
// LN/LIF: warp per (branch,b,l). Sums and sum-of-squares in exact int64;
// inv_std via rsqrtf seed + 1 fp64 Newton (err ~1e-13); per-element scale
// G=round(C*w*2^58) via one DFMA (2^52*1.5 magic); yv and the LIF membrane
// recursion entirely in int64 fixed point (Y = yv*2^31). Total injected
// error ~1.2e-8 << the ~1e-7 reference-rounding window (proven safe R3-R11).
// Attention: binary q,k popcount + fp32 PV (exact dyadic rationals).
// ---------------------------------------------------------------------------

#define T_  4
#define B_  64
#define L_  200
#define H_  256
#define M_  (T_*B_*L_)      // 51200
#define BLr (B_*L_)         // 12800
#define NBATCH (T_*B_*2)    // 512 (t,b,head)

__device__ __align__(128) int8_t g_asl[4ull*M_*H_];
__device__ __align__(128) int8_t g_wsl[16ull*H_*H_];
__device__ __align__(128) int8_t g_s2[(size_t)M_*H_];
__device__ __align__(128) int g_Zq[(size_t)M_*H_];   // Z*2^27 as int32
__device__ __align__(128) int g_Zk[(size_t)M_*H_];
__device__ __align__(128) int g_Zv[(size_t)M_*H_];
__device__ __align__(128) int g_zp[(size_t)M_*H_];
__device__ uint32_t g_qb[NBATCH*L_*4];
__device__ uint32_t g_kb[NBATCH*L_*4];
__device__ float    g_vf[(size_t)NBATCH*L_*128];
__device__ float    g_y [(size_t)NBATCH*L_*128];

// ---------------------------------------------------------------------------
__device__ __forceinline__ void mma_s8(int* c, const unsigned* a, const unsigned* b)
{
    asm volatile(
        "mma.sync.aligned.m16n8k32.row.col.s32.s8.s8.s32 "
        "{%0,%1,%2,%3}, {%4,%5,%6,%7}, {%8,%9}, {%0,%1,%2,%3};"
        : "+r"(c[0]), "+r"(c[1]), "+r"(c[2]), "+r"(c[3])
        : "r"(a[0]), "r"(a[1]), "r"(a[2]), "r"(a[3]), "r"(b[0]), "r"(b[1]));
}

// ===================== digit-slice generation ===============================
__global__ void slice_x_kernel(const float* __restrict__ x, int8_t* __restrict__ asl)
{
    int i = blockIdx.x * blockDim.x + threadIdx.x;
    int stride = gridDim.x * blockDim.x;
    const size_t plane = (size_t)M_ * H_;
    for (; i < M_ * H_; i += stride) {
        int q = __double2int_rn((double)x[i] * 134217728.0);  // 2^27
        #pragma unroll
        for (int s = 0; s < 4; s++) {
            int d = ((q + 128) & 255) - 128;
            q = (q - d) >> 8;
            asl[s * plane + i] = (int8_t)d;
        }
    }
}

__global__ void slice_w_kernel(const float* __restrict__ qw, const float* __restrict__ kw,
                               const float* __restrict__ vw, const float* __restrict__ pw,
                               int8_t* __restrict__ wsl)
{
    int i = blockIdx.x * blockDim.x + threadIdx.x;
    int stride = gridDim.x * blockDim.x;
    for (; i < 4 * H_ * H_; i += stride) {
        int widx = i >> 16, j = i & 65535;
        const float* W = (widx == 0) ? qw : ((widx == 1) ? kw : ((widx == 2) ? vw : pw));
        long long q = __double2ll_rn((double)W[j] * 4294967296.0);  // 2^32
        #pragma unroll
        for (int s = 0; s < 4; s++) {
            int d = (int)(((q + 128) & 255)) - 128;
            q = (q - d) >> 8;
            wsl[(size_t)(widx * 4 + s) * 65536 + j] = (int8_t)d;
        }
    }
}

// ===================== qkv slice GEMM (IMMA) ================================
#define QKV_SMEM (4*32768 + 4*16384)   // 196608

__global__ void __launch_bounds__(256) gemm_qkv_kernel(
    const int8_t* __restrict__ asl, const int8_t* __restrict__ wsl,
    int* __restrict__ Zq, int* __restrict__ Zk, int* __restrict__ Zv)
{
    extern __shared__ char smem[];
    const int tid = threadIdx.x;
    const int nt = blockIdx.x, mt = blockIdx.y;
    const int widx = nt >> 2, n0 = (nt & 3) * 64, m0 = mt * 128;

    #pragma unroll
    for (int p = 0; p < 4; p++) {
        const int8_t* src = asl + (size_t)p * M_ * H_ + (size_t)m0 * 256;
        char* dstp = smem + p * 32768;
        #pragma unroll
        for (int v = 0; v < 8; v++) {
            int chunk = tid + 256 * v;
            int row = chunk >> 4, c16 = chunk & 15;
            uint4 val = *(const uint4*)(src + row * 256 + c16 * 16);
            int mc = row >> 4, kc = c16 >> 1;
            int g  = ((c16 & 1) << 1) | ((row >> 3) & 1);
            int T0 = (row & 7) * 4;
            char* base = dstp + ((mc * 8 + kc) * 32) * 16 + g * 4;
            *(unsigned*)(base + (T0 + 0) * 16) = val.x;
            *(unsigned*)(base + (T0 + 1) * 16) = val.y;
            *(unsigned*)(base + (T0 + 2) * 16) = val.z;
            *(unsigned*)(base + (T0 + 3) * 16) = val.w;
        }
    }
    #pragma unroll
    for (int p = 0; p < 4; p++) {
        const int8_t* src = wsl + (size_t)(widx * 4 + p) * 65536 + n0 * 256;
        char* dstp = smem + 131072 + p * 16384;
        #pragma unroll
        for (int v = 0; v < 4; v++) {
            int chunk = tid + 256 * v;
            int row = chunk >> 4, c16 = chunk & 15;
            uint4 val = *(const uint4*)(src + row * 256 + c16 * 16);
            int nc = row >> 3, kc = c16 >> 1;
            int g  = c16 & 1;
            int T0 = (row & 7) * 4;
            char* base = dstp + ((nc * 8 + kc) * 32) * 8 + g * 4;
            *(unsigned*)(base + (T0 + 0) * 8) = val.x;
            *(unsigned*)(base + (T0 + 1) * 8) = val.y;
            *(unsigned*)(base + (T0 + 2) * 8) = val.z;
            *(unsigned*)(base + (T0 + 3) * 8) = val.w;
        }
    }
    __syncthreads();

    const int warp = tid >> 5, lane = tid & 31;
    const int wm = warp >> 1, wn = warp & 1;

    long long acc[2][4][4];
    #pragma unroll
    for (int mi = 0; mi < 2; mi++)
        #pragma unroll
        for (int nj = 0; nj < 4; nj++)
            #pragma unroll
            for (int r = 0; r < 4; r++) acc[mi][nj][r] = 0ll;

    const int PI[13] = {0,1,2, 0,1,2,3, 1,2,3, 2,3, 3};
    const int PJ[13] = {2,1,0, 3,2,1,0, 3,2,1, 3,2, 3};
    const int DS[6]  = {0, 3, 7, 10, 12, 13};

    for (int sd = 0; sd < 5; sd++) {
        int cfr[2][4][4];
        #pragma unroll
        for (int mi = 0; mi < 2; mi++)
            #pragma unroll
            for (int nj = 0; nj < 4; nj++)
                #pragma unroll
                for (int r = 0; r < 4; r++) cfr[mi][nj][r] = 0;

        for (int p = DS[sd]; p < DS[sd + 1]; p++) {
            const char* Ap = smem + PI[p] * 32768;
            const char* Bp = smem + 131072 + PJ[p] * 16384;
            #pragma unroll
            for (int kc = 0; kc < 8; kc++) {
                unsigned a[2][4], b[4][2];
                #pragma unroll
                for (int mi = 0; mi < 2; mi++) {
                    uint4 av = *(const uint4*)(Ap + (((2*wm + mi) * 8 + kc) * 32 + lane) * 16);
                    a[mi][0] = av.x; a[mi][1] = av.y; a[mi][2] = av.z; a[mi][3] = av.w;
                }
                #pragma unroll
                for (int nj = 0; nj < 4; nj++) {
                    uint2 bv = *(const uint2*)(Bp + (((4*wn + nj) * 8 + kc) * 32 + lane) * 8);
                    b[nj][0] = bv.x; b[nj][1] = bv.y;
                }
                #pragma unroll
                for (int mi = 0; mi < 2; mi++)
                    #pragma unroll
                    for (int nj = 0; nj < 4; nj++)
                        mma_s8(cfr[mi][nj], a[mi], b[nj]);
            }
        }
        int sh = 8 * sd;
        #pragma unroll
        for (int mi = 0; mi < 2; mi++)
            #pragma unroll
            for (int nj = 0; nj < 4; nj++)
                #pragma unroll
                for (int r = 0; r < 4; r++)
                    acc[mi][nj][r] += ((long long)cfr[mi][nj][r]) << sh;
    }

    // epilogue: zint = round(acc * 2^-16)
    int* Zout = (widx == 0) ? Zq : ((widx == 1) ? Zk : Zv);
    #pragma unroll
    for (int mi = 0; mi < 2; mi++)
        #pragma unroll
        for (int nj = 0; nj < 4; nj++)
            #pragma unroll
            for (int r = 0; r < 4; r++) {
                int row = m0 + 32*wm + 16*mi + (lane >> 2) + 8*(r >> 1);
                int col = n0 + 32*wn + 8*nj + 2*(lane & 3) + (r & 1);
                Zout[(size_t)row * H_ + col] = (int)((acc[mi][nj][r] + 32768ll) >> 16);
            }
}

// ===================== proj slice GEMM (IMMA) ===============================
#define PROJ_SMEM (32768 + 4*16384)   // 98304

__global__ void __launch_bounds__(256) gemm_proj_kernel(
    const int8_t* __restrict__ s2, const int8_t* __restrict__ wsl,
    int* __restrict__ Zp)
{
    extern __shared__ char smem[];
    const int tid = threadIdx.x;
    const int nt = blockIdx.x, mt = blockIdx.y;
    const int n0 = nt * 64, m0 = mt * 128;

    {
        const int8_t* src = s2 + (size_t)m0 * 256;
        #pragma unroll
        for (int v = 0; v < 8; v++) {
            int chunk = tid + 256 * v;
            int row = chunk >> 4, c16 = chunk & 15;
            uint4 val = *(const uint4*)(src + row * 256 + c16 * 16);
            int mc = row >> 4, kc = c16 >> 1;
            int g  = ((c16 & 1) << 1) | ((row >> 3) & 1);
            int T0 = (row & 7) * 4;
            char* base = smem + ((mc * 8 + kc) * 32) * 16 + g * 4;
            *(unsigned*)(base + (T0 + 0) * 16) = val.x;
            *(unsigned*)(base + (T0 + 1) * 16) = val.y;
            *(unsigned*)(base + (T0 + 2) * 16) = val.z;
            *(unsigned*)(base + (T0 + 3) * 16) = val.w;
        }
    }
    #pragma unroll
    for (int p = 0; p < 4; p++) {
        const int8_t* src = wsl + (size_t)(12 + p) * 65536 + n0 * 256;
        char* dstp = smem + 32768 + p * 16384;
        #pragma unroll
        for (int v = 0; v < 4; v++) {
            int chunk = tid + 256 * v;
            int row = chunk >> 4, c16 = chunk & 15;
            uint4 val = *(const uint4*)(src + row * 256 + c16 * 16);
            int nc = row >> 3, kc = c16 >> 1;
            int g  = c16 & 1;
            int T0 = (row & 7) * 4;
            char* base = dstp + ((nc * 8 + kc) * 32) * 8 + g * 4;
            *(unsigned*)(base + (T0 + 0) * 8) = val.x;
            *(unsigned*)(base + (T0 + 1) * 8) = val.y;
            *(unsigned*)(base + (T0 + 2) * 8) = val.z;
            *(unsigned*)(base + (T0 + 3) * 8) = val.w;
        }
    }
    __syncthreads();

    const int warp = tid >> 5, lane = tid & 31;
    const int wm = warp >> 1, wn = warp & 1;

    long long acc[2][4][4];
    #pragma unroll
    for (int mi = 0; mi < 2; mi++)
        #pragma unroll
        for (int nj = 0; nj < 4; nj++)
            #pragma unroll
            for (int r = 0; r < 4; r++) acc[mi][nj][r] = 0ll;

    for (int j = 0; j < 4; j++) {
        int cfr[2][4][4];
        #pragma unroll
        for (int mi = 0; mi < 2; mi++)
            #pragma unroll
            for (int nj = 0; nj < 4; nj++)
                #pragma unroll
                for (int r = 0; r < 4; r++) cfr[mi][nj][r] = 0;

        const char* Bp = smem + 32768 + j * 16384;
        #pragma unroll
        for (int kc = 0; kc < 8; kc++) {
            unsigned a[2][4], b[4][2];
            #pragma unroll
            for (int mi = 0; mi < 2; mi++) {
                uint4 av = *(const uint4*)(smem + (((2*wm + mi) * 8 + kc) * 32 + lane) * 16);
                a[mi][0] = av.x; a[mi][1] = av.y; a[mi][2] = av.z; a[mi][3] = av.w;
            }
            #pragma unroll
            for (int nj = 0; nj < 4; nj++) {
                uint2 bv = *(const uint2*)(Bp + (((4*wn + nj) * 8 + kc) * 32 + lane) * 8);
                b[nj][0] = bv.x; b[nj][1] = bv.y;
            }
            #pragma unroll
            for (int mi = 0; mi < 2; mi++)
                #pragma unroll
                for (int nj = 0; nj < 4; nj++)
                    mma_s8(cfr[mi][nj], a[mi], b[nj]);
        }
        int sh = 8 * j;
        #pragma unroll
        for (int mi = 0; mi < 2; mi++)
            #pragma unroll
            for (int nj = 0; nj < 4; nj++)
                #pragma unroll
                for (int r = 0; r < 4; r++)
                    acc[mi][nj][r] += ((long long)cfr[mi][nj][r]) << sh;
    }

    #pragma unroll
    for (int mi = 0; mi < 2; mi++)
        #pragma unroll
        for (int nj = 0; nj < 4; nj++)
            #pragma unroll
            for (int r = 0; r < 4; r++) {
                int row = m0 + 32*wm + 16*mi + (lane >> 2) + 8*(r >> 1);
                int col = n0 + 32*wn + 8*nj + 2*(lane & 3) + (r & 1);
                Zp[(size_t)row * H_ + col] = (int)((acc[mi][nj][r] + 16ll) >> 5);
            }
}

// ===================== fixed-point LN/LIF ===================================
// units: z_u = Z*2^27 (int32 exact). C = 1/sqrt(var_u + 1e-5*2^54).
// G[e] = round(C * w[e] * 2^58); dv = z_u - round(mean_u);
// Y = yv*2^31 = (dv*G)>>27 + round(b*2^31). LIF: v=(v+Y)>>1, spike v>=2^31.
#define EPS_U   1.8014398509481984e11      // 1e-5 * 2^54
#define MAGIC   6755399441055744.0          // 2^52 * 1.5
#define MAGICLL 0x4338000000000000LL
#define P2_58   288230376151711744.0        // 2^58
#define P2_31   2147483648.0
#define TH_Y    2147483648LL                // 1.0 * 2^31

__device__ __forceinline__ double newton_rsqrt(double x)
{
    double r = (double)rsqrtf((float)x);
    return r * (1.5 - 0.5 * x * r * r);    // ~1e-13 rel err
}

__global__ void __launch_bounds__(256, 2) ln_lif_qkv_kernel(
    const int* __restrict__ Zq, const int* __restrict__ Zk,
    const int* __restrict__ Zv,
    const float* __restrict__ qlw, const float* __restrict__ qlb,
    const float* __restrict__ klw, const float* __restrict__ klb,
    const float* __restrict__ vlw, const float* __restrict__ vlb,
    uint32_t* __restrict__ qb, uint32_t* __restrict__ kb, float* __restrict__ vf)
{
    const int gw = blockIdx.x * 8 + (threadIdx.x >> 5);
    const int lane = threadIdx.x & 31;
    const int br = blockIdx.y;
    const int b = gw / L_, l = gw % L_;
    const int h0 = lane * 8;

    const int* Z = (br == 0) ? Zq : ((br == 1) ? Zk : Zv);
    const float* lwp = (br == 0) ? qlw : ((br == 1) ? klw : vlw);
    const float* lbp = (br == 0) ? qlb : ((br == 1) ? klb : vlb);

    double w58[8];
    long long bint[8];
    {
        float4 w0 = *(const float4*)(lwp + h0), w1 = *(const float4*)(lwp + h0 + 4);
        float4 c0 = *(const float4*)(lbp + h0), c1 = *(const float4*)(lbp + h0 + 4);
        float wa[8] = {w0.x,w0.y,w0.z,w0.w,w1.x,w1.y,w1.z,w1.w};
        float ba[8] = {c0.x,c0.y,c0.z,c0.w,c1.x,c1.y,c1.z,c1.w};
        #pragma unroll
        for (int e = 0; e < 8; e++) {
            w58[e]  = (double)wa[e] * P2_58;
            bint[e] = __double2ll_rn((double)ba[e] * P2_31);
        }
    }

    int zi[4][8];
    #pragma unroll
    for (int t = 0; t < T_; t++) {
        const int* zr = Z + ((size_t)(t * B_ + b) * L_ + l) * H_ + h0;
        int4 p0 = ((const int4*)zr)[0];
        int4 p1 = ((const int4*)zr)[1];
        zi[t][0]=p0.x; zi[t][1]=p0.y; zi[t][2]=p0.z; zi[t][3]=p0.w;
        zi[t][4]=p1.x; zi[t][5]=p1.y; zi[t][6]=p1.z; zi[t][7]=p1.w;
    }

    // exact integer partials
    long long s[4], sq[4];
    #pragma unroll
    for (int t = 0; t < T_; t++) {
        long long a = 0, c = 0;
        #pragma unroll
        for (int e = 0; e < 8; e++) {
            a += zi[t][e];
            c += (long long)zi[t][e] * zi[t][e];
        }
        s[t] = a; sq[t] = c >> 6;   // pre-shift: no overflow in warp-reduce
    }
    #pragma unroll
    for (int o = 16; o; o >>= 1) {
        #pragma unroll
        for (int t = 0; t < T_; t++) {
            s[t]  += __shfl_xor_sync(0xffffffffu, s[t],  o);
            sq[t] += __shfl_xor_sync(0xffffffffu, sq[t], o);
        }
    }

    long long vm[8];
    #pragma unroll
    for (int e = 0; e < 8; e++) vm[e] = 0ll;

    #pragma unroll
    for (int t = 0; t < T_; t++) {
        int m_q = (int)((s[t] + 128) >> 8);             // round(mean_u)
        double mean = (double)s[t] * (1.0 / 256.0);     // exact
        double var_u = (double)sq[t] * 0.25 - mean * mean;  // sq = sum/64
        double C = newton_rsqrt(var_u + EPS_U);

        unsigned byte = 0;
        float spf[8];
        #pragma unroll
        for (int e = 0; e < 8; e++) {
            long long G = __double_as_longlong(fma(C, w58[e], MAGIC)) - MAGICLL;
            int dv = zi[t][e] - m_q;
            long long Y = (((long long)dv * G) >> 27) + bint[e];
            vm[e] = (vm[e] + Y) >> 1;
            bool sp = vm[e] >= TH_Y;
            if (sp) vm[e] = 0ll;
            byte |= (sp ? 1u : 0u) << e;
            spf[e] = sp ? 1.f : 0.f;
        }
        if (br < 2) {
            unsigned v = byte << (8 * (lane & 3));
            v |= __shfl_xor_sync(0xffffffffu, v, 1);
            v |= __shfl_xor_sync(0xffffffffu, v, 2);
            if ((lane & 3) == 0) {
                int g = lane >> 2;
                int head = g >> 2, widx = g & 3;
                uint32_t* dst = (br == 0) ? qb : kb;
                dst[(((size_t)(t * B_ + b) * 2 + head) * L_ + l) * 4 + widx] = v;
            }
        } else {
            int head = lane >> 4;
            int d = 8 * (lane & 15);
            float* dst = vf + (((size_t)(t * B_ + b) * 2 + head) * L_ + l) * 128 + d;
            *(float4*)(dst)     = make_float4(spf[0], spf[1], spf[2], spf[3]);
            *(float4*)(dst + 4) = make_float4(spf[4], spf[5], spf[6], spf[7]);
        }
    }
}

// proj LN -> LIF(1.0) -> output spikes; pb folded into zi as round(pb*2^27)
__global__ void __launch_bounds__(256, 2) proj_ln_lif_kernel(
    const int* __restrict__ Zp, const float* __restrict__ pb,
    const float* __restrict__ lw, const float* __restrict__ lb,
    float* __restrict__ out)
{
    const int gw = blockIdx.x * 8 + (threadIdx.x >> 5);
    const int lane = threadIdx.x & 31;
    const int b = gw / L_, l = gw % L_;
    const int h0 = lane * 8;

    double w58[8];
    long long bint[8];
    int pbq[8];
    {
        float4 w0 = *(const float4*)(lw + h0), w1 = *(const float4*)(lw + h0 + 4);
        float4 c0 = *(const float4*)(lb + h0), c1 = *(const float4*)(lb + h0 + 4);
        float4 p0 = *(const float4*)(pb + h0), p1 = *(const float4*)(pb + h0 + 4);
        float wa[8] = {w0.x,w0.y,w0.z,w0.w,w1.x,w1.y,w1.z,w1.w};
        float ba[8] = {c0.x,c0.y,c0.z,c0.w,c1.x,c1.y,c1.z,c1.w};
        float pa[8] = {p0.x,p0.y,p0.z,p0.w,p1.x,p1.y,p1.z,p1.w};
        #pragma unroll
        for (int e = 0; e < 8; e++) {
            w58[e]  = (double)wa[e] * P2_58;
            bint[e] = __double2ll_rn((double)ba[e] * P2_31);
            pbq[e]  = __double2int_rn((double)pa[e] * 134217728.0);
        }
    }

    int zi[4][8];
    #pragma unroll
    for (int t = 0; t < T_; t++) {
        const int* zr = Zp + ((size_t)(t * B_ + b) * L_ + l) * H_ + h0;
        int4 p0 = ((const int4*)zr)[0];
        int4 p1 = ((const int4*)zr)[1];
        zi[t][0]=p0.x+pbq[0]; zi[t][1]=p0.y+pbq[1]; zi[t][2]=p0.z+pbq[2]; zi[t][3]=p0.w+pbq[3];
        zi[t][4]=p1.x+pbq[4]; zi[t][5]=p1.y+pbq[5]; zi[t][6]=p1.z+pbq[6]; zi[t][7]=p1.w+pbq[7];
    }

    long long s[4], sq[4];
    #pragma unroll
    for (int t = 0; t < T_; t++) {
        long long a = 0, c = 0;
        #pragma unroll
        for (int e = 0; e < 8; e++) {
            a += zi[t][e];
            c += (long long)zi[t][e] * zi[t][e];
        }
        s[t] = a; sq[t] = c >> 6;
    }
    #pragma unroll
    for (int o = 16; o; o >>= 1) {
        #pragma unroll
        for (int t = 0; t < T_; t++) {
            s[t]  += __shfl_xor_sync(0xffffffffu, s[t],  o);
            sq[t] += __shfl_xor_sync(0xffffffffu, sq[t], o);
        }
    }

    long long vm[8];
    #pragma unroll
    for (int e = 0; e < 8; e++) vm[e] = 0ll;

    #pragma unroll
    for (int t = 0; t < T_; t++) {
        int m_q = (int)((s[t] + 128) >> 8);
        double mean = (double)s[t] * (1.0 / 256.0);
        double var_u = (double)sq[t] * 0.25 - mean * mean;
        double C = newton_rsqrt(var_u + EPS_U);
        float spf[8];
        #pragma unroll
        for (int e = 0; e < 8; e++) {
            long long G = __double_as_longlong(fma(C, w58[e], MAGIC)) - MAGICLL;
            int dv = zi[t][e] - m_q;
            long long Y = (((long long)dv * G) >> 27) + bint[e];
            vm[e] = (vm[e] + Y) >> 1;
            bool sp = vm[e] >= TH_Y;
            if (sp) vm[e] = 0ll;
            spf[e] = sp ? 1.f : 0.f;
        }
        float* dst = out + ((size_t)(t * B_ + b) * L_ + l) * H_ + h0;
        *(float4*)(dst)     = make_float4(spf[0], spf[1], spf[2], spf[3]);
        *(float4*)(dst + 4) = make_float4(spf[4], spf[5], spf[6], spf[7]);
    }
}

// ===================== attention (exact fp32) ===============================
#define ATTN_SMEM ((L_*128 + 8*L_*4)*4 + L_*4*4)   // 131200 bytes

__global__ void __launch_bounds__(256) attn_kernel(
    const uint32_t* __restrict__ qb, const uint32_t* __restrict__ kb,
    const float* __restrict__ vf, float* __restrict__ y)
{
    extern __shared__ char smem_raw[];
    float*    sv    = (float*)smem_raw;
    uint32_t* skb   = (uint32_t*)(sv + L_ * 128);
    float*    sattn = (float*)(skb + L_ * 4);

    const int batch = blockIdx.x;
    const uint32_t* qb_b = qb + (size_t)batch * L_ * 4;
    const uint32_t* kb_b = kb + (size_t)batch * L_ * 4;
    const float*    v_b  = vf + (size_t)batch * L_ * 128;
    float*          y_b  = y  + (size_t)batch * L_ * 128;

    const int tid = threadIdx.x;
    for (int i = tid; i < L_ * 4; i += 256) skb[i] = kb_b[i];
    for (int i = tid; i < L_ * 32; i += 256) ((float4*)sv)[i] = ((const float4*)v_b)[i];
    __syncthreads();

    const int warp = tid >> 5, lane = tid & 31;
    float* aw = sattn + warp * (L_ * 4);
    const float* svl = sv + lane * 4;

    for (int base = warp * 4; base < L_; base += 32) {
        #pragma unroll
        for (int r = 0; r < 4; r++) {
            const int lrow = base + r;
            uint32_t q0 = qb_b[lrow*4+0], q1 = qb_b[lrow*4+1];
            uint32_t q2 = qb_b[lrow*4+2], q3 = qb_b[lrow*4+3];
            for (int m = lane; m < L_; m += 32) {
                int c = __popc(q0 & skb[m*4+0]) + __popc(q1 & skb[m*4+1])
                      + __popc(q2 & skb[m*4+2]) + __popc(q3 & skb[m*4+3]);
                aw[m*4 + r] = (float)c * 0.125f;
            }
        }
        __syncwarp();
        float4 acc0 = {0,0,0,0}, acc1 = {0,0,0,0}, acc2 = {0,0,0,0}, acc3 = {0,0,0,0};
        #pragma unroll 4
        for (int m = 0; m < L_; m++) {
            float4 a  = *(const float4*)(aw  + m * 4);
            float4 vv = *(const float4*)(svl + m * 128);
            acc0.x += a.x*vv.x; acc0.y += a.x*vv.y; acc0.z += a.x*vv.z; acc0.w += a.x*vv.w;
            acc1.x += a.y*vv.x; acc1.y += a.y*vv.y; acc1.z += a.y*vv.z; acc1.w += a.y*vv.w;
            acc2.x += a.z*vv.x; acc2.y += a.z*vv.y; acc2.z += a.z*vv.z; acc2.w += a.z*vv.w;
            acc3.x += a.w*vv.x; acc3.y += a.w*vv.y; acc3.z += a.w*vv.z; acc3.w += a.w*vv.w;
        }
        *(float4*)(y_b + (size_t)(base + 0) * 128 + lane * 4) = acc0;
        *(float4*)(y_b + (size_t)(base + 1) * 128 + lane * 4) = acc1;
        *(float4*)(y_b + (size_t)(base + 2) * 128 + lane * 4) = acc2;
        *(float4*)(y_b + (size_t)(base + 3) * 128 + lane * 4) = acc3;
        __syncwarp();
    }
}

// ---------------------------------------------------------------------------
__global__ void __launch_bounds__(256) attn_lif_kernel(
    const float* __restrict__ y, int8_t* __restrict__ s2)
{
    const int bl = blockIdx.x;
    const int b = bl / L_, l = bl % L_;
    const int h = threadIdx.x;
    const int head = h >> 7, d = h & 127;
    float yv[4];
    #pragma unroll
    for (int t = 0; t < T_; t++)
        yv[t] = y[(((size_t)(t * B_ + b) * 2 + head) * L_ + l) * 128 + d];
    float vmem = 0.f;
    #pragma unroll
    for (int t = 0; t < T_; t++) {
        vmem = vmem + (yv[t] - vmem) * 0.5f;
        bool sp = (vmem - 0.5f) >= 0.f;
        if (sp) vmem = 0.f;
        s2[((size_t)(t * B_ + b) * L_ + l) * H_ + h] = sp ? 1 : 0;
    }
}

// ---------------------------------------------------------------------------
extern "C" void kernel_launch(void* const* d_in, const int* in_sizes, int n_in,
                              void* d_out, int out_size)
{
    const float* x   = (const float*)d_in[0];
    const float* qw  = (const float*)d_in[1];
    const float* qlw = (const float*)d_in[2];
    const float* qlb = (const float*)d_in[3];
    const float* kw  = (const float*)d_in[4];
    const float* klw = (const float*)d_in[5];
    const float* klb = (const float*)d_in[6];
    const float* vw  = (const float*)d_in[7];
    const float* vlw = (const float*)d_in[8];
    const float* vlb = (const float*)d_in[9];
    const float* pw  = (const float*)d_in[10];
    const float* pb  = (const float*)d_in[11];
    const float* plw = (const float*)d_in[12];
    const float* plb = (const float*)d_in[13];
    float* out = (float*)d_out;

    int8_t *asl, *wsl, *s2;
    int *Zq, *Zk, *Zv, *zp;
    float *vf, *yv;
    uint32_t *qbp, *kbp;
    cudaGetSymbolAddress((void**)&asl, g_asl);
    cudaGetSymbolAddress((void**)&wsl, g_wsl);
    cudaGetSymbolAddress((void**)&s2,  g_s2);
    cudaGetSymbolAddress((void**)&Zq,  g_Zq);
    cudaGetSymbolAddress((void**)&Zk,  g_Zk);
    cudaGetSymbolAddress((void**)&Zv,  g_Zv);
    cudaGetSymbolAddress((void**)&zp,  g_zp);
    cudaGetSymbolAddress((void**)&vf,  g_vf);
    cudaGetSymbolAddress((void**)&yv,  g_y);
    cudaGetSymbolAddress((void**)&qbp, g_qb);
    cudaGetSymbolAddress((void**)&kbp, g_kb);

    cudaFuncSetAttribute(gemm_qkv_kernel, cudaFuncAttributeMaxDynamicSharedMemorySize, QKV_SMEM);
    cudaFuncSetAttribute(gemm_proj_kernel, cudaFuncAttributeMaxDynamicSharedMemorySize, PROJ_SMEM);
    cudaFuncSetAttribute(attn_kernel, cudaFuncAttributeMaxDynamicSharedMemorySize, ATTN_SMEM);

    slice_x_kernel<<<4096, 256>>>(x, asl);
    slice_w_kernel<<<256, 256>>>(qw, kw, vw, pw, wsl);

    dim3 gq(12, 400);
    gemm_qkv_kernel<<<gq, 256, QKV_SMEM>>>(asl, wsl, Zq, Zk, Zv);

    dim3 gl(BLr / 8, 3);
    ln_lif_qkv_kernel<<<gl, 256>>>(Zq, Zk, Zv, qlw, qlb, klw, klb, vlw, vlb,
                                   qbp, kbp, vf);

    attn_kernel<<<NBATCH, 256, ATTN_SMEM>>>(qbp, kbp, vf, yv);

    attn_lif_kernel<<<BLr, 256>>>(yv, s2);

    dim3 gp(4, 400);
    gemm_proj_kernel<<<gp, 256, PROJ_SMEM>>>(s2, wsl, zp);

    proj_ln_lif_kernel<<<BLr / 8, 256>>>(zp, pb, plw, plb, out);
}

// round 15
// speedup vs baseline: 9.7131x; 1.1120x over previous
#include <cuda_runtime.h>
#include <cstdint>
#include <cmath>

// ---------------------------------------------------------------------------
// SSA forward: exact int8 IMMA GEMM (2-CTA/SM K-chunked) + fixed-point LN/LIF
// + integer tensor-core attention (u8 IMMA PV, exact).
// Error budget unchanged from R13 (~1.2e-8 << ~1e-7 reference window).
// ---------------------------------------------------------------------------

#define T_  4
#define B_  64
#define L_  200
#define H_  256
#define M_  (T_*B_*L_)      // 51200
#define BLr (B_*L_)         // 12800
#define NBATCH (T_*B_*2)    // 512 (t,b,head)

__device__ __align__(128) int8_t g_asl[4ull*M_*H_];
__device__ __align__(128) int8_t g_wsl[16ull*H_*H_];
__device__ __align__(128) int8_t g_s2[(size_t)M_*H_];
__device__ __align__(128) uint8_t g_vb[(size_t)NBATCH*L_*128];  // v spikes u8
__device__ __align__(128) int g_Zq[(size_t)M_*H_];   // Z*2^27 as int32
__device__ __align__(128) int g_Zk[(size_t)M_*H_];
__device__ __align__(128) int g_Zv[(size_t)M_*H_];
__device__ __align__(128) int g_zp[(size_t)M_*H_];
__device__ uint32_t g_qb[NBATCH*L_*4];
__device__ uint32_t g_kb[NBATCH*L_*4];
__device__ float    g_y [(size_t)NBATCH*L_*128];

// ---------------------------------------------------------------------------
__device__ __forceinline__ void mma_s8(int* c, const unsigned* a, const unsigned* b)
{
    asm volatile(
        "mma.sync.aligned.m16n8k32.row.col.s32.s8.s8.s32 "
        "{%0,%1,%2,%3}, {%4,%5,%6,%7}, {%8,%9}, {%0,%1,%2,%3};"
        : "+r"(c[0]), "+r"(c[1]), "+r"(c[2]), "+r"(c[3])
        : "r"(a[0]), "r"(a[1]), "r"(a[2]), "r"(a[3]), "r"(b[0]), "r"(b[1]));
}
__device__ __forceinline__ void mma_u8(int* c, const unsigned* a, const unsigned* b)
{
    asm volatile(
        "mma.sync.aligned.m16n8k32.row.col.s32.u8.u8.s32 "
        "{%0,%1,%2,%3}, {%4,%5,%6,%7}, {%8,%9}, {%0,%1,%2,%3};"
        : "+r"(c[0]), "+r"(c[1]), "+r"(c[2]), "+r"(c[3])
        : "r"(a[0]), "r"(a[1]), "r"(a[2]), "r"(a[3]), "r"(b[0]), "r"(b[1]));
}

// ===================== digit-slice generation ===============================
__global__ void slice_x_kernel(const float* __restrict__ x, int8_t* __restrict__ asl)
{
    int i = blockIdx.x * blockDim.x + threadIdx.x;
    int stride = gridDim.x * blockDim.x;
    const size_t plane = (size_t)M_ * H_;
    for (; i < M_ * H_; i += stride) {
        int q = __double2int_rn((double)x[i] * 134217728.0);  // 2^27
        #pragma unroll
        for (int s = 0; s < 4; s++) {
            int d = ((q + 128) & 255) - 128;
            q = (q - d) >> 8;
            asl[s * plane + i] = (int8_t)d;
        }
    }
}

__global__ void slice_w_kernel(const float* __restrict__ qw, const float* __restrict__ kw,
                               const float* __restrict__ vw, const float* __restrict__ pw,
                               int8_t* __restrict__ wsl)
{
    int i = blockIdx.x * blockDim.x + threadIdx.x;
    int stride = gridDim.x * blockDim.x;
    for (; i < 4 * H_ * H_; i += stride) {
        int widx = i >> 16, j = i & 65535;
        const float* W = (widx == 0) ? qw : ((widx == 1) ? kw : ((widx == 2) ? vw : pw));
        long long q = __double2ll_rn((double)W[j] * 4294967296.0);  // 2^32
        #pragma unroll
        for (int s = 0; s < 4; s++) {
            int d = (int)(((q + 128) & 255)) - 128;
            q = (q - d) >> 8;
            wsl[(size_t)(widx * 4 + s) * 65536 + j] = (int8_t)d;
        }
    }
}

// ===================== qkv slice GEMM (IMMA, K-chunked, 2 CTA/SM) ===========
// smem: A 4 planes x 16KB (K=128 chunk) + W 4 planes x 8KB = 96KB
#define QKV_SMEM (4*16384 + 4*8192)   // 98304

__global__ void __launch_bounds__(256, 2) gemm_qkv_kernel(
    const int8_t* __restrict__ asl, const int8_t* __restrict__ wsl,
    int* __restrict__ Zq, int* __restrict__ Zk, int* __restrict__ Zv)
{
    extern __shared__ char smem[];
    const int tid = threadIdx.x;
    const int nt = blockIdx.x, mt = blockIdx.y;
    const int widx = nt >> 2, n0 = (nt & 3) * 64, m0 = mt * 128;

    const int warp = tid >> 5, lane = tid & 31;
    const int wm = warp >> 1, wn = warp & 1;

    const int PI[13] = {0,1,2, 0,1,2,3, 1,2,3, 2,3, 3};
    const int PJ[13] = {2,1,0, 3,2,1,0, 3,2,1, 3,2, 3};
    const int DS[6]  = {0, 3, 7, 10, 12, 13};

    long long acc[2][4][4];
    #pragma unroll
    for (int mi = 0; mi < 2; mi++)
        #pragma unroll
        for (int nj = 0; nj < 4; nj++)
            #pragma unroll
            for (int r = 0; r < 4; r++) acc[mi][nj][r] = 0ll;

    for (int c2 = 0; c2 < 2; c2++) {
        if (c2) __syncthreads();
        // A planes: 128 rows x 128 k (chunk), frag-packed
        #pragma unroll
        for (int p = 0; p < 4; p++) {
            const int8_t* src = asl + (size_t)p * M_ * H_ + (size_t)m0 * 256 + c2 * 128;
            char* dstp = smem + p * 16384;
            #pragma unroll
            for (int v = 0; v < 4; v++) {
                int chunk = tid + 256 * v;          // 0..1023
                int row = chunk >> 3, c16 = chunk & 7;
                uint4 val = *(const uint4*)(src + row * 256 + c16 * 16);
                int mc = row >> 4, kc = c16 >> 1;
                int g  = ((c16 & 1) << 1) | ((row >> 3) & 1);
                int T0 = (row & 7) * 4;
                char* base = dstp + (mc * 4 + kc) * 512 + g * 4;
                *(unsigned*)(base + (T0 + 0) * 16) = val.x;
                *(unsigned*)(base + (T0 + 1) * 16) = val.y;
                *(unsigned*)(base + (T0 + 2) * 16) = val.z;
                *(unsigned*)(base + (T0 + 3) * 16) = val.w;
            }
        }
        // W planes: 64 rows x 128 k (chunk)
        #pragma unroll
        for (int p = 0; p < 4; p++) {
            const int8_t* src = wsl + (size_t)(widx * 4 + p) * 65536 + n0 * 256 + c2 * 128;
            char* dstp = smem + 65536 + p * 8192;
            #pragma unroll
            for (int v = 0; v < 2; v++) {
                int chunk = tid + 256 * v;          // 0..511
                int row = chunk >> 3, c16 = chunk & 7;
                uint4 val = *(const uint4*)(src + row * 256 + c16 * 16);
                int nc = row >> 3, kc = c16 >> 1;
                int g  = c16 & 1;
                int T0 = (row & 7) * 4;
                char* base = dstp + (nc * 4 + kc) * 256 + g * 4;
                *(unsigned*)(base + (T0 + 0) * 8) = val.x;
                *(unsigned*)(base + (T0 + 1) * 8) = val.y;
                *(unsigned*)(base + (T0 + 2) * 8) = val.z;
                *(unsigned*)(base + (T0 + 3) * 8) = val.w;
            }
        }
        __syncthreads();

        for (int sd = 0; sd < 5; sd++) {
            int cfr[2][4][4];
            #pragma unroll
            for (int mi = 0; mi < 2; mi++)
                #pragma unroll
                for (int nj = 0; nj < 4; nj++)
                    #pragma unroll
                    for (int r = 0; r < 4; r++) cfr[mi][nj][r] = 0;

            for (int p = DS[sd]; p < DS[sd + 1]; p++) {
                const char* Ap = smem + PI[p] * 16384;
                const char* Bp = smem + 65536 + PJ[p] * 8192;
                #pragma unroll
                for (int kc = 0; kc < 4; kc++) {
                    unsigned a[2][4], b[4][2];
                    #pragma unroll
                    for (int mi = 0; mi < 2; mi++) {
                        uint4 av = *(const uint4*)(Ap + (((2*wm + mi) * 4 + kc) * 32 + lane) * 16);
                        a[mi][0] = av.x; a[mi][1] = av.y; a[mi][2] = av.z; a[mi][3] = av.w;
                    }
                    #pragma unroll
                    for (int nj = 0; nj < 4; nj++) {
                        uint2 bv = *(const uint2*)(Bp + (((4*wn + nj) * 4 + kc) * 32 + lane) * 8);
                        b[nj][0] = bv.x; b[nj][1] = bv.y;
                    }
                    #pragma unroll
                    for (int mi = 0; mi < 2; mi++)
                        #pragma unroll
                        for (int nj = 0; nj < 4; nj++)
                            mma_s8(cfr[mi][nj], a[mi], b[nj]);
                }
            }
            int sh = 8 * sd;
            #pragma unroll
            for (int mi = 0; mi < 2; mi++)
                #pragma unroll
                for (int nj = 0; nj < 4; nj++)
                    #pragma unroll
                    for (int r = 0; r < 4; r++)
                        acc[mi][nj][r] += ((long long)cfr[mi][nj][r]) << sh;
        }
    }

    int* Zout = (widx == 0) ? Zq : ((widx == 1) ? Zk : Zv);
    #pragma unroll
    for (int mi = 0; mi < 2; mi++)
        #pragma unroll
        for (int nj = 0; nj < 4; nj++)
            #pragma unroll
            for (int r = 0; r < 4; r++) {
                int row = m0 + 32*wm + 16*mi + (lane >> 2) + 8*(r >> 1);
                int col = n0 + 32*wn + 8*nj + 2*(lane & 3) + (r & 1);
                Zout[(size_t)row * H_ + col] = (int)((acc[mi][nj][r] + 32768ll) >> 16);
            }
}

// ===================== proj slice GEMM (IMMA) ===============================
#define PROJ_SMEM (32768 + 4*16384)   // 98304 -> 2 CTA/SM

__global__ void __launch_bounds__(256, 2) gemm_proj_kernel(
    const int8_t* __restrict__ s2, const int8_t* __restrict__ wsl,
    int* __restrict__ Zp)
{
    extern __shared__ char smem[];
    const int tid = threadIdx.x;
    const int nt = blockIdx.x, mt = blockIdx.y;
    const int n0 = nt * 64, m0 = mt * 128;

    {
        const int8_t* src = s2 + (size_t)m0 * 256;
        #pragma unroll
        for (int v = 0; v < 8; v++) {
            int chunk = tid + 256 * v;
            int row = chunk >> 4, c16 = chunk & 15;
            uint4 val = *(const uint4*)(src + row * 256 + c16 * 16);
            int mc = row >> 4, kc = c16 >> 1;
            int g  = ((c16 & 1) << 1) | ((row >> 3) & 1);
            int T0 = (row & 7) * 4;
            char* base = smem + (mc * 8 + kc) * 512 + g * 4;
            *(unsigned*)(base + (T0 + 0) * 16) = val.x;
            *(unsigned*)(base + (T0 + 1) * 16) = val.y;
            *(unsigned*)(base + (T0 + 2) * 16) = val.z;
            *(unsigned*)(base + (T0 + 3) * 16) = val.w;
        }
    }
    #pragma unroll
    for (int p = 0; p < 4; p++) {
        const int8_t* src = wsl + (size_t)(12 + p) * 65536 + n0 * 256;
        char* dstp = smem + 32768 + p * 16384;
        #pragma unroll
        for (int v = 0; v < 4; v++) {
            int chunk = tid + 256 * v;
            int row = chunk >> 4, c16 = chunk & 15;
            uint4 val = *(const uint4*)(src + row * 256 + c16 * 16);
            int nc = row >> 3, kc = c16 >> 1;
            int g  = c16 & 1;
            int T0 = (row & 7) * 4;
            char* base = dstp + (nc * 8 + kc) * 256 + g * 4;
            *(unsigned*)(base + (T0 + 0) * 8) = val.x;
            *(unsigned*)(base + (T0 + 1) * 8) = val.y;
            *(unsigned*)(base + (T0 + 2) * 8) = val.z;
            *(unsigned*)(base + (T0 + 3) * 8) = val.w;
        }
    }
    __syncthreads();

    const int warp = tid >> 5, lane = tid & 31;
    const int wm = warp >> 1, wn = warp & 1;

    long long acc[2][4][4];
    #pragma unroll
    for (int mi = 0; mi < 2; mi++)
        #pragma unroll
        for (int nj = 0; nj < 4; nj++)
            #pragma unroll
            for (int r = 0; r < 4; r++) acc[mi][nj][r] = 0ll;

    for (int j = 0; j < 4; j++) {
        int cfr[2][4][4];
        #pragma unroll
        for (int mi = 0; mi < 2; mi++)
            #pragma unroll
            for (int nj = 0; nj < 4; nj++)
                #pragma unroll
                for (int r = 0; r < 4; r++) cfr[mi][nj][r] = 0;

        const char* Bp = smem + 32768 + j * 16384;
        #pragma unroll
        for (int kc = 0; kc < 8; kc++) {
            unsigned a[2][4], b[4][2];
            #pragma unroll
            for (int mi = 0; mi < 2; mi++) {
                uint4 av = *(const uint4*)(smem + (((2*wm + mi) * 8 + kc) * 32 + lane) * 16);
                a[mi][0] = av.x; a[mi][1] = av.y; a[mi][2] = av.z; a[mi][3] = av.w;
            }
            #pragma unroll
            for (int nj = 0; nj < 4; nj++) {
                uint2 bv = *(const uint2*)(Bp + (((4*wn + nj) * 8 + kc) * 32 + lane) * 8);
                b[nj][0] = bv.x; b[nj][1] = bv.y;
            }
            #pragma unroll
            for (int mi = 0; mi < 2; mi++)
                #pragma unroll
                for (int nj = 0; nj < 4; nj++)
                    mma_s8(cfr[mi][nj], a[mi], b[nj]);
        }
        int sh = 8 * j;
        #pragma unroll
        for (int mi = 0; mi < 2; mi++)
            #pragma unroll
            for (int nj = 0; nj < 4; nj++)
                #pragma unroll
                for (int r = 0; r < 4; r++)
                    acc[mi][nj][r] += ((long long)cfr[mi][nj][r]) << sh;
    }

    #pragma unroll
    for (int mi = 0; mi < 2; mi++)
        #pragma unroll
        for (int nj = 0; nj < 4; nj++)
            #pragma unroll
            for (int r = 0; r < 4; r++) {
                int row = m0 + 32*wm + 16*mi + (lane >> 2) + 8*(r >> 1);
                int col = n0 + 32*wn + 8*nj + 2*(lane & 3) + (r & 1);
                Zp[(size_t)row * H_ + col] = (int)((acc[mi][nj][r] + 16ll) >> 5);
            }
}

// ===================== fixed-point LN/LIF ===================================
#define EPS_U   1.8014398509481984e11      // 1e-5 * 2^54
#define MAGIC   6755399441055744.0          // 2^52 * 1.5
#define MAGICLL 0x4338000000000000LL
#define P2_58   288230376151711744.0
#define P2_31   2147483648.0
#define TH_Y    2147483648LL

__device__ __forceinline__ double newton_rsqrt(double x)
{
    double r = (double)rsqrtf((float)x);
    return r * (1.5 - 0.5 * x * r * r);
}

__global__ void __launch_bounds__(256, 2) ln_lif_qkv_kernel(
    const int* __restrict__ Zq, const int* __restrict__ Zk,
    const int* __restrict__ Zv,
    const float* __restrict__ qlw, const float* __restrict__ qlb,
    const float* __restrict__ klw, const float* __restrict__ klb,
    const float* __restrict__ vlw, const float* __restrict__ vlb,
    uint32_t* __restrict__ qb, uint32_t* __restrict__ kb, uint8_t* __restrict__ vb)
{
    const int gw = blockIdx.x * 8 + (threadIdx.x >> 5);
    const int lane = threadIdx.x & 31;
    const int br = blockIdx.y;
    const int b = gw / L_, l = gw % L_;
    const int h0 = lane * 8;

    const int* Z = (br == 0) ? Zq : ((br == 1) ? Zk : Zv);
    const float* lwp = (br == 0) ? qlw : ((br == 1) ? klw : vlw);
    const float* lbp = (br == 0) ? qlb : ((br == 1) ? klb : vlb);

    double w58[8];
    long long bint[8];
    {
        float4 w0 = *(const float4*)(lwp + h0), w1 = *(const float4*)(lwp + h0 + 4);
        float4 c0 = *(const float4*)(lbp + h0), c1 = *(const float4*)(lbp + h0 + 4);
        float wa[8] = {w0.x,w0.y,w0.z,w0.w,w1.x,w1.y,w1.z,w1.w};
        float ba[8] = {c0.x,c0.y,c0.z,c0.w,c1.x,c1.y,c1.z,c1.w};
        #pragma unroll
        for (int e = 0; e < 8; e++) {
            w58[e]  = (double)wa[e] * P2_58;
            bint[e] = __double2ll_rn((double)ba[e] * P2_31);
        }
    }

    int zi[4][8];
    #pragma unroll
    for (int t = 0; t < T_; t++) {
        const int* zr = Z + ((size_t)(t * B_ + b) * L_ + l) * H_ + h0;
        int4 p0 = ((const int4*)zr)[0];
        int4 p1 = ((const int4*)zr)[1];
        zi[t][0]=p0.x; zi[t][1]=p0.y; zi[t][2]=p0.z; zi[t][3]=p0.w;
        zi[t][4]=p1.x; zi[t][5]=p1.y; zi[t][6]=p1.z; zi[t][7]=p1.w;
    }

    long long s[4], sq[4];
    #pragma unroll
    for (int t = 0; t < T_; t++) {
        long long a = 0, c = 0;
        #pragma unroll
        for (int e = 0; e < 8; e++) {
            a += zi[t][e];
            c += (long long)zi[t][e] * zi[t][e];
        }
        s[t] = a; sq[t] = c >> 6;
    }
    #pragma unroll
    for (int o = 16; o; o >>= 1) {
        #pragma unroll
        for (int t = 0; t < T_; t++) {
            s[t]  += __shfl_xor_sync(0xffffffffu, s[t],  o);
            sq[t] += __shfl_xor_sync(0xffffffffu, sq[t], o);
        }
    }

    long long vm[8];
    #pragma unroll
    for (int e = 0; e < 8; e++) vm[e] = 0ll;

    #pragma unroll
    for (int t = 0; t < T_; t++) {
        int m_q = (int)((s[t] + 128) >> 8);
        double mean = (double)s[t] * (1.0 / 256.0);
        double var_u = (double)sq[t] * 0.25 - mean * mean;
        double C = newton_rsqrt(var_u + EPS_U);

        unsigned byte = 0, blo = 0, bhi = 0;
        #pragma unroll
        for (int e = 0; e < 8; e++) {
            long long G = __double_as_longlong(fma(C, w58[e], MAGIC)) - MAGICLL;
            int dv = zi[t][e] - m_q;
            long long Y = (((long long)dv * G) >> 27) + bint[e];
            vm[e] = (vm[e] + Y) >> 1;
            bool sp = vm[e] >= TH_Y;
            if (sp) vm[e] = 0ll;
            byte |= (sp ? 1u : 0u) << e;
            if (e < 4) blo |= (sp ? 1u : 0u) << (8 * e);
            else       bhi |= (sp ? 1u : 0u) << (8 * (e - 4));
        }
        if (br < 2) {
            unsigned v = byte << (8 * (lane & 3));
            v |= __shfl_xor_sync(0xffffffffu, v, 1);
            v |= __shfl_xor_sync(0xffffffffu, v, 2);
            if ((lane & 3) == 0) {
                int g = lane >> 2;
                int head = g >> 2, widx = g & 3;
                uint32_t* dst = (br == 0) ? qb : kb;
                dst[(((size_t)(t * B_ + b) * 2 + head) * L_ + l) * 4 + widx] = v;
            }
        } else {
            int head = lane >> 4;
            int d0 = 8 * (lane & 15);
            uint8_t* dst = vb + ((((size_t)(t * B_ + b) * 2 + head) * L_ + l) * 128 + d0);
            *(uint2*)dst = make_uint2(blo, bhi);
        }
    }
}

__global__ void __launch_bounds__(256, 2) proj_ln_lif_kernel(
    const int* __restrict__ Zp, const float* __restrict__ pb,
    const float* __restrict__ lw, const float* __restrict__ lb,
    float* __restrict__ out)
{
    const int gw = blockIdx.x * 8 + (threadIdx.x >> 5);
    const int lane = threadIdx.x & 31;
    const int b = gw / L_, l = gw % L_;
    const int h0 = lane * 8;

    double w58[8];
    long long bint[8];
    int pbq[8];
    {
        float4 w0 = *(const float4*)(lw + h0), w1 = *(const float4*)(lw + h0 + 4);
        float4 c0 = *(const float4*)(lb + h0), c1 = *(const float4*)(lb + h0 + 4);
        float4 p0 = *(const float4*)(pb + h0), p1 = *(const float4*)(pb + h0 + 4);
        float wa[8] = {w0.x,w0.y,w0.z,w0.w,w1.x,w1.y,w1.z,w1.w};
        float ba[8] = {c0.x,c0.y,c0.z,c0.w,c1.x,c1.y,c1.z,c1.w};
        float pa[8] = {p0.x,p0.y,p0.z,p0.w,p1.x,p1.y,p1.z,p1.w};
        #pragma unroll
        for (int e = 0; e < 8; e++) {
            w58[e]  = (double)wa[e] * P2_58;
            bint[e] = __double2ll_rn((double)ba[e] * P2_31);
            pbq[e]  = __double2int_rn((double)pa[e] * 134217728.0);
        }
    }

    int zi[4][8];
    #pragma unroll
    for (int t = 0; t < T_; t++) {
        const int* zr = Zp + ((size_t)(t * B_ + b) * L_ + l) * H_ + h0;
        int4 p0 = ((const int4*)zr)[0];
        int4 p1 = ((const int4*)zr)[1];
        zi[t][0]=p0.x+pbq[0]; zi[t][1]=p0.y+pbq[1]; zi[t][2]=p0.z+pbq[2]; zi[t][3]=p0.w+pbq[3];
        zi[t][4]=p1.x+pbq[4]; zi[t][5]=p1.y+pbq[5]; zi[t][6]=p1.z+pbq[6]; zi[t][7]=p1.w+pbq[7];
    }

    long long s[4], sq[4];
    #pragma unroll
    for (int t = 0; t < T_; t++) {
        long long a = 0, c = 0;
        #pragma unroll
        for (int e = 0; e < 8; e++) {
            a += zi[t][e];
            c += (long long)zi[t][e] * zi[t][e];
        }
        s[t] = a; sq[t] = c >> 6;
    }
    #pragma unroll
    for (int o = 16; o; o >>= 1) {
        #pragma unroll
        for (int t = 0; t < T_; t++) {
            s[t]  += __shfl_xor_sync(0xffffffffu, s[t],  o);
            sq[t] += __shfl_xor_sync(0xffffffffu, sq[t], o);
        }
    }

    long long vm[8];
    #pragma unroll
    for (int e = 0; e < 8; e++) vm[e] = 0ll;

    #pragma unroll
    for (int t = 0; t < T_; t++) {
        int m_q = (int)((s[t] + 128) >> 8);
        double mean = (double)s[t] * (1.0 / 256.0);
        double var_u = (double)sq[t] * 0.25 - mean * mean;
        double C = newton_rsqrt(var_u + EPS_U);
        float spf[8];
        #pragma unroll
        for (int e = 0; e < 8; e++) {
            long long G = __double_as_longlong(fma(C, w58[e], MAGIC)) - MAGICLL;
            int dv = zi[t][e] - m_q;
            long long Y = (((long long)dv * G) >> 27) + bint[e];
            vm[e] = (vm[e] + Y) >> 1;
            bool sp = vm[e] >= TH_Y;
            if (sp) vm[e] = 0ll;
            spf[e] = sp ? 1.f : 0.f;
        }
        float* dst = out + ((size_t)(t * B_ + b) * L_ + l) * H_ + h0;
        *(float4*)(dst)     = make_float4(spf[0], spf[1], spf[2], spf[3]);
        *(float4*)(dst + 4) = make_float4(spf[4], spf[5], spf[6], spf[7]);
    }
}

// ===================== attention (u8 IMMA, exact) ===========================
// S = popc(q&k) (u8, <=128) packed directly into A-frag smem; v transposed
// into B-frag smem; y_int = S@v via mma.u8 (exact s32); y = y_int * 0.125.
// M=200 (13 m16 tiles, pad 208), N=128 (16 n8), K=200 (pad 224, 7 ksteps).
#define ATT_SA   0                         // 208*224 = 46592
#define ATT_SB   46592                     // 128*224 = 28672
#define ATT_SV   75264                     // 200*128 = 25600 staging
#define ATT_SKB  100864                    // 200*4 u32 = 3200
#define ATTN_SMEM 104064

__global__ void __launch_bounds__(256, 2) attn_kernel(
    const uint32_t* __restrict__ qb, const uint32_t* __restrict__ kb,
    const uint8_t* __restrict__ vb, float* __restrict__ y)
{
    extern __shared__ char smem[];
    char*     sA  = smem + ATT_SA;
    char*     sB  = smem + ATT_SB;
    uint8_t*  sV  = (uint8_t*)(smem + ATT_SV);
    uint32_t* skb = (uint32_t*)(smem + ATT_SKB);

    const int batch = blockIdx.x;
    const uint32_t* qb_b = qb + (size_t)batch * L_ * 4;
    const uint32_t* kb_b = kb + (size_t)batch * L_ * 4;
    const uint8_t*  v_b  = vb + (size_t)batch * L_ * 128;
    float*          y_b  = y  + (size_t)batch * L_ * 128;

    const int tid = threadIdx.x;
    const int warp = tid >> 5, lane = tid & 31;

    // stage v [200][128] u8 and k bitmasks
    for (int i = tid; i < L_ * 8; i += 256)
        ((uint4*)sV)[i] = ((const uint4*)v_b)[i];
    for (int i = tid; i < L_ * 4; i += 256) skb[i] = kb_b[i];
    __syncthreads();

    // transpose-pack v into B-frag: n=d, k=m (pad m>=200 with 0)
    // group index: d in [0,128), mg in [0,56) -> m0 = mg*4
    for (int idx = tid; idx < 128 * 56; idx += 256) {
        int d = idx / 56, mg = idx % 56;
        int m0 = mg * 4;
        unsigned w = 0;
        #pragma unroll
        for (int e = 0; e < 4; e++) {
            int m = m0 + e;
            unsigned bv = (m < L_) ? (unsigned)sV[m * 128 + d] : 0u;
            w |= bv << (8 * e);
        }
        char* addr = sB + ((d >> 3) * 7 + (m0 >> 5)) * 256
                   + ((d & 7) * 4 + ((m0 >> 2) & 3)) * 8
                   + ((m0 >> 4) & 1) * 4;
        *(unsigned*)addr = w;
    }

    // QK popcount -> A-frag packed u8 counts (rows r, k=m)
    for (int r = warp; r < L_; r += 8) {
        uint32_t q0 = qb_b[r*4+0], q1 = qb_b[r*4+1];
        uint32_t q2 = qb_b[r*4+2], q3 = qb_b[r*4+3];
        for (int g = lane; g < 50; g += 32) {
            int m0 = g * 4;
            unsigned w = 0;
            #pragma unroll
            for (int e = 0; e < 4; e++) {
                int m = m0 + e;
                unsigned c = __popc(q0 & skb[m*4+0]) + __popc(q1 & skb[m*4+1])
                           + __popc(q2 & skb[m*4+2]) + __popc(q3 & skb[m*4+3]);
                w |= c << (8 * e);
            }
            char* addr = sA + ((r >> 4) * 7 + (m0 >> 5)) * 512
                       + ((r & 7) * 4 + ((m0 >> 2) & 3)) * 16
                       + (((m0 >> 4) & 1) * 2 + ((r >> 3) & 1)) * 4;
            *(unsigned*)addr = w;
        }
    }
    __syncthreads();

    // PV: y = S @ v via u8 IMMA
    for (int mt = warp; mt < 13; mt += 8) {
        for (int ntile = 0; ntile < 16; ntile++) {
            int acc[4] = {0, 0, 0, 0};
            #pragma unroll
            for (int kc = 0; kc < 7; kc++) {
                unsigned a[4], b[2];
                uint4 av = *(const uint4*)(sA + ((mt * 7 + kc) * 32 + lane) * 16);
                a[0] = av.x; a[1] = av.y; a[2] = av.z; a[3] = av.w;
                uint2 bv = *(const uint2*)(sB + ((ntile * 7 + kc) * 32 + lane) * 8);
                b[0] = bv.x; b[1] = bv.y;
                mma_u8(acc, a, b);
            }
            int r0  = mt * 16 + (lane >> 2);
            int col = ntile * 8 + 2 * (lane & 3);
            #pragma unroll
            for (int rr = 0; rr < 2; rr++) {
                int row = r0 + 8 * rr;
                if (row < L_) {
                    y_b[(size_t)row * 128 + col]     = (float)acc[2*rr]     * 0.125f;
                    y_b[(size_t)row * 128 + col + 1] = (float)acc[2*rr + 1] * 0.125f;
                }
            }
        }
    }
}

// ---------------------------------------------------------------------------
__global__ void __launch_bounds__(256) attn_lif_kernel(
    const float* __restrict__ y, int8_t* __restrict__ s2)
{
    const int bl = blockIdx.x;
    const int b = bl / L_, l = bl % L_;
    const int h = threadIdx.x;
    const int head = h >> 7, d = h & 127;
    float yv[4];
    #pragma unroll
    for (int t = 0; t < T_; t++)
        yv[t] = y[(((size_t)(t * B_ + b) * 2 + head) * L_ + l) * 128 + d];
    float vmem = 0.f;
    #pragma unroll
    for (int t = 0; t < T_; t++) {
        vmem = vmem + (yv[t] - vmem) * 0.5f;
        bool sp = (vmem - 0.5f) >= 0.f;
        if (sp) vmem = 0.f;
        s2[((size_t)(t * B_ + b) * L_ + l) * H_ + h] = sp ? 1 : 0;
    }
}

// ---------------------------------------------------------------------------
extern "C" void kernel_launch(void* const* d_in, const int* in_sizes, int n_in,
                              void* d_out, int out_size)
{
    const float* x   = (const float*)d_in[0];
    const float* qw  = (const float*)d_in[1];
    const float* qlw = (const float*)d_in[2];
    const float* qlb = (const float*)d_in[3];
    const float* kw  = (const float*)d_in[4];
    const float* klw = (const float*)d_in[5];
    const float* klb = (const float*)d_in[6];
    const float* vw  = (const float*)d_in[7];
    const float* vlw = (const float*)d_in[8];
    const float* vlb = (const float*)d_in[9];
    const float* pw  = (const float*)d_in[10];
    const float* pb  = (const float*)d_in[11];
    const float* plw = (const float*)d_in[12];
    const float* plb = (const float*)d_in[13];
    float* out = (float*)d_out;

    int8_t *asl, *wsl, *s2;
    uint8_t *vbp;
    int *Zq, *Zk, *Zv, *zp;
    float *yv;
    uint32_t *qbp, *kbp;
    cudaGetSymbolAddress((void**)&asl, g_asl);
    cudaGetSymbolAddress((void**)&wsl, g_wsl);
    cudaGetSymbolAddress((void**)&s2,  g_s2);
    cudaGetSymbolAddress((void**)&vbp, g_vb);
    cudaGetSymbolAddress((void**)&Zq,  g_Zq);
    cudaGetSymbolAddress((void**)&Zk,  g_Zk);
    cudaGetSymbolAddress((void**)&Zv,  g_Zv);
    cudaGetSymbolAddress((void**)&zp,  g_zp);
    cudaGetSymbolAddress((void**)&yv,  g_y);
    cudaGetSymbolAddress((void**)&qbp, g_qb);
    cudaGetSymbolAddress((void**)&kbp, g_kb);

    cudaFuncSetAttribute(gemm_qkv_kernel, cudaFuncAttributeMaxDynamicSharedMemorySize, QKV_SMEM);
    cudaFuncSetAttribute(gemm_proj_kernel, cudaFuncAttributeMaxDynamicSharedMemorySize, PROJ_SMEM);
    cudaFuncSetAttribute(attn_kernel, cudaFuncAttributeMaxDynamicSharedMemorySize, ATTN_SMEM);

    slice_x_kernel<<<4096, 256>>>(x, asl);
    slice_w_kernel<<<256, 256>>>(qw, kw, vw, pw, wsl);

    dim3 gq(12, 400);
    gemm_qkv_kernel<<<gq, 256, QKV_SMEM>>>(asl, wsl, Zq, Zk, Zv);

    dim3 gl(BLr / 8, 3);
    ln_lif_qkv_kernel<<<gl, 256>>>(Zq, Zk, Zv, qlw, qlb, klw, klb, vlw, vlb,
                                   qbp, kbp, vbp);

    attn_kernel<<<NBATCH, 256, ATTN_SMEM>>>(qbp, kbp, vbp, yv);

    attn_lif_kernel<<<BLr, 256>>>(yv, s2);

    dim3 gp(4, 400);
    gemm_proj_kernel<<<gp, 256, PROJ_SMEM>>>(s2, wsl, zp);

    proj_ln_lif_kernel<<<BLr / 8, 256>>>(zp, pb, plw, plb, out);
}

// round 16
// speedup vs baseline: 11.5605x; 1.1902x over previous
#include <cuda_runtime.h>
#include <cstdint>
#include <cmath>

// ---------------------------------------------------------------------------
// SSA forward: exact int8 IMMA GEMM (digit pairs s>=3) + fixed-point LN/LIF
// + integer tensor-core attention (u8 IMMA PV, exact).
// Error budget: x/w quant ~4e-9 + Z quant 3.7e-9 + dropped digit pairs s<3
// ~1.6e-8 + fixpoint LN ~5e-9  => ~2e-8 RMS, still well under the reference's
// own ~1e-7 fp32 rounding which dominates the spike-flip probability.
// ---------------------------------------------------------------------------

#define T_  4
#define B_  64
#define L_  200
#define H_  256
#define M_  (T_*B_*L_)      // 51200
#define BLr (B_*L_)         // 12800
#define NBATCH (T_*B_*2)    // 512 (t,b,head)

__device__ __align__(128) int8_t g_asl[4ull*M_*H_];
__device__ __align__(128) int8_t g_wsl[16ull*H_*H_];
__device__ __align__(128) int8_t g_s2[(size_t)M_*H_];
__device__ __align__(128) uint8_t g_vb[(size_t)NBATCH*L_*128];
__device__ __align__(128) int g_Zq[(size_t)M_*H_];   // Z*2^27 as int32
__device__ __align__(128) int g_Zk[(size_t)M_*H_];
__device__ __align__(128) int g_Zv[(size_t)M_*H_];
__device__ __align__(128) int g_zp[(size_t)M_*H_];
__device__ uint32_t g_qb[NBATCH*L_*4];
__device__ uint32_t g_kb[NBATCH*L_*4];
__device__ float    g_y [(size_t)NBATCH*L_*128];

// ---------------------------------------------------------------------------
__device__ __forceinline__ void mma_s8(int* c, const unsigned* a, const unsigned* b)
{
    asm volatile(
        "mma.sync.aligned.m16n8k32.row.col.s32.s8.s8.s32 "
        "{%0,%1,%2,%3}, {%4,%5,%6,%7}, {%8,%9}, {%0,%1,%2,%3};"
        : "+r"(c[0]), "+r"(c[1]), "+r"(c[2]), "+r"(c[3])
        : "r"(a[0]), "r"(a[1]), "r"(a[2]), "r"(a[3]), "r"(b[0]), "r"(b[1]));
}
__device__ __forceinline__ void mma_u8(int* c, const unsigned* a, const unsigned* b)
{
    asm volatile(
        "mma.sync.aligned.m16n8k32.row.col.s32.u8.u8.s32 "
        "{%0,%1,%2,%3}, {%4,%5,%6,%7}, {%8,%9}, {%0,%1,%2,%3};"
        : "+r"(c[0]), "+r"(c[1]), "+r"(c[2]), "+r"(c[3])
        : "r"(a[0]), "r"(a[1]), "r"(a[2]), "r"(a[3]), "r"(b[0]), "r"(b[1]));
}

// ===================== digit-slice generation ===============================
// 4 elements per thread iteration; one u32 store per digit plane.
__global__ void slice_x_kernel(const float* __restrict__ x, int8_t* __restrict__ asl)
{
    int i4 = blockIdx.x * blockDim.x + threadIdx.x;
    int stride = gridDim.x * blockDim.x;
    const size_t plane4 = (size_t)M_ * H_ / 4;
    for (; i4 < M_ * H_ / 4; i4 += stride) {
        float4 xv = ((const float4*)x)[i4];
        float vals[4] = {xv.x, xv.y, xv.z, xv.w};
        unsigned out[4] = {0, 0, 0, 0};
        #pragma unroll
        for (int e = 0; e < 4; e++) {
            int q = __double2int_rn((double)vals[e] * 134217728.0);  // 2^27
            #pragma unroll
            for (int s = 0; s < 4; s++) {
                int d = ((q + 128) & 255) - 128;
                q = (q - d) >> 8;
                out[s] |= (unsigned)(d & 255) << (8 * e);
            }
        }
        #pragma unroll
        for (int s = 0; s < 4; s++)
            ((unsigned*)asl)[s * plane4 + i4] = out[s];
    }
}

__global__ void slice_w_kernel(const float* __restrict__ qw, const float* __restrict__ kw,
                               const float* __restrict__ vw, const float* __restrict__ pw,
                               int8_t* __restrict__ wsl)
{
    int i = blockIdx.x * blockDim.x + threadIdx.x;
    int stride = gridDim.x * blockDim.x;
    for (; i < 4 * H_ * H_; i += stride) {
        int widx = i >> 16, j = i & 65535;
        const float* W = (widx == 0) ? qw : ((widx == 1) ? kw : ((widx == 2) ? vw : pw));
        long long q = __double2ll_rn((double)W[j] * 4294967296.0);  // 2^32
        #pragma unroll
        for (int s = 0; s < 4; s++) {
            int d = (int)(((q + 128) & 255)) - 128;
            q = (q - d) >> 8;
            wsl[(size_t)(widx * 4 + s) * 65536 + j] = (int8_t)d;
        }
    }
}

// ===================== qkv slice GEMM (IMMA, s>=3 pairs, 2 CTA/SM) ==========
#define QKV_SMEM (4*16384 + 4*8192)   // 98304

__global__ void __launch_bounds__(256, 2) gemm_qkv_kernel(
    const int8_t* __restrict__ asl, const int8_t* __restrict__ wsl,
    int* __restrict__ Zq, int* __restrict__ Zk, int* __restrict__ Zv)
{
    extern __shared__ char smem[];
    const int tid = threadIdx.x;
    const int nt = blockIdx.x, mt = blockIdx.y;
    const int widx = nt >> 2, n0 = (nt & 3) * 64, m0 = mt * 128;

    const int warp = tid >> 5, lane = tid & 31;
    const int wm = warp >> 1, wn = warp & 1;

    // digit pairs with s=i+j >= 3, grouped by diagonal (s=3..6)
    const int PI[10] = {0,1,2,3, 1,2,3, 2,3, 3};
    const int PJ[10] = {3,2,1,0, 3,2,1, 3,2, 3};
    const int DS[5]  = {0, 4, 7, 9, 10};

    long long acc[2][4][4];
    #pragma unroll
    for (int mi = 0; mi < 2; mi++)
        #pragma unroll
        for (int nj = 0; nj < 4; nj++)
            #pragma unroll
            for (int r = 0; r < 4; r++) acc[mi][nj][r] = 0ll;

    for (int c2 = 0; c2 < 2; c2++) {
        if (c2) __syncthreads();
        #pragma unroll
        for (int p = 0; p < 4; p++) {
            const int8_t* src = asl + (size_t)p * M_ * H_ + (size_t)m0 * 256 + c2 * 128;
            char* dstp = smem + p * 16384;
            #pragma unroll
            for (int v = 0; v < 4; v++) {
                int chunk = tid + 256 * v;
                int row = chunk >> 3, c16 = chunk & 7;
                uint4 val = *(const uint4*)(src + row * 256 + c16 * 16);
                int mc = row >> 4, kc = c16 >> 1;
                int g  = ((c16 & 1) << 1) | ((row >> 3) & 1);
                int T0 = (row & 7) * 4;
                char* base = dstp + (mc * 4 + kc) * 512 + g * 4;
                *(unsigned*)(base + (T0 + 0) * 16) = val.x;
                *(unsigned*)(base + (T0 + 1) * 16) = val.y;
                *(unsigned*)(base + (T0 + 2) * 16) = val.z;
                *(unsigned*)(base + (T0 + 3) * 16) = val.w;
            }
        }
        #pragma unroll
        for (int p = 0; p < 4; p++) {
            const int8_t* src = wsl + (size_t)(widx * 4 + p) * 65536 + n0 * 256 + c2 * 128;
            char* dstp = smem + 65536 + p * 8192;
            #pragma unroll
            for (int v = 0; v < 2; v++) {
                int chunk = tid + 256 * v;
                int row = chunk >> 3, c16 = chunk & 7;
                uint4 val = *(const uint4*)(src + row * 256 + c16 * 16);
                int nc = row >> 3, kc = c16 >> 1;
                int g  = c16 & 1;
                int T0 = (row & 7) * 4;
                char* base = dstp + (nc * 4 + kc) * 256 + g * 4;
                *(unsigned*)(base + (T0 + 0) * 8) = val.x;
                *(unsigned*)(base + (T0 + 1) * 8) = val.y;
                *(unsigned*)(base + (T0 + 2) * 8) = val.z;
                *(unsigned*)(base + (T0 + 3) * 8) = val.w;
            }
        }
        __syncthreads();

        for (int sd = 0; sd < 4; sd++) {
            int cfr[2][4][4];
            #pragma unroll
            for (int mi = 0; mi < 2; mi++)
                #pragma unroll
                for (int nj = 0; nj < 4; nj++)
                    #pragma unroll
                    for (int r = 0; r < 4; r++) cfr[mi][nj][r] = 0;

            for (int p = DS[sd]; p < DS[sd + 1]; p++) {
                const char* Ap = smem + PI[p] * 16384;
                const char* Bp = smem + 65536 + PJ[p] * 8192;
                #pragma unroll
                for (int kc = 0; kc < 4; kc++) {
                    unsigned a[2][4], b[4][2];
                    #pragma unroll
                    for (int mi = 0; mi < 2; mi++) {
                        uint4 av = *(const uint4*)(Ap + (((2*wm + mi) * 4 + kc) * 32 + lane) * 16);
                        a[mi][0] = av.x; a[mi][1] = av.y; a[mi][2] = av.z; a[mi][3] = av.w;
                    }
                    #pragma unroll
                    for (int nj = 0; nj < 4; nj++) {
                        uint2 bv = *(const uint2*)(Bp + (((4*wn + nj) * 4 + kc) * 32 + lane) * 8);
                        b[nj][0] = bv.x; b[nj][1] = bv.y;
                    }
                    #pragma unroll
                    for (int mi = 0; mi < 2; mi++)
                        #pragma unroll
                        for (int nj = 0; nj < 4; nj++)
                            mma_s8(cfr[mi][nj], a[mi], b[nj]);
                }
            }
            int sh = 8 * sd;
            #pragma unroll
            for (int mi = 0; mi < 2; mi++)
                #pragma unroll
                for (int nj = 0; nj < 4; nj++)
                    #pragma unroll
                    for (int r = 0; r < 4; r++)
                        acc[mi][nj][r] += ((long long)cfr[mi][nj][r]) << sh;
        }
    }

    // acc = Z * 2^35 (lowest kept diagonal s=3 at digit scale 2^24; 59-24=35)
    // zint = round(acc * 2^-8)  -> Z*2^27
    int* Zout = (widx == 0) ? Zq : ((widx == 1) ? Zk : Zv);
    #pragma unroll
    for (int mi = 0; mi < 2; mi++)
        #pragma unroll
        for (int nj = 0; nj < 4; nj++)
            #pragma unroll
            for (int r = 0; r < 4; r++) {
                int row = m0 + 32*wm + 16*mi + (lane >> 2) + 8*(r >> 1);
                int col = n0 + 32*wn + 8*nj + 2*(lane & 3) + (r & 1);
                Zout[(size_t)row * H_ + col] = (int)((acc[mi][nj][r] + 128ll) >> 8);
            }
}

// ===================== proj slice GEMM (IMMA) ===============================
#define PROJ_SMEM (32768 + 4*16384)   // 98304

__global__ void __launch_bounds__(256, 2) gemm_proj_kernel(
    const int8_t* __restrict__ s2, const int8_t* __restrict__ wsl,
    int* __restrict__ Zp)
{
    extern __shared__ char smem[];
    const int tid = threadIdx.x;
    const int nt = blockIdx.x, mt = blockIdx.y;
    const int n0 = nt * 64, m0 = mt * 128;

    {
        const int8_t* src = s2 + (size_t)m0 * 256;
        #pragma unroll
        for (int v = 0; v < 8; v++) {
            int chunk = tid + 256 * v;
            int row = chunk >> 4, c16 = chunk & 15;
            uint4 val = *(const uint4*)(src + row * 256 + c16 * 16);
            int mc = row >> 4, kc = c16 >> 1;
            int g  = ((c16 & 1) << 1) | ((row >> 3) & 1);
            int T0 = (row & 7) * 4;
            char* base = smem + (mc * 8 + kc) * 512 + g * 4;
            *(unsigned*)(base + (T0 + 0) * 16) = val.x;
            *(unsigned*)(base + (T0 + 1) * 16) = val.y;
            *(unsigned*)(base + (T0 + 2) * 16) = val.z;
            *(unsigned*)(base + (T0 + 3) * 16) = val.w;
        }
    }
    #pragma unroll
    for (int p = 0; p < 4; p++) {
        const int8_t* src = wsl + (size_t)(12 + p) * 65536 + n0 * 256;
        char* dstp = smem + 32768 + p * 16384;
        #pragma unroll
        for (int v = 0; v < 4; v++) {
            int chunk = tid + 256 * v;
            int row = chunk >> 4, c16 = chunk & 15;
            uint4 val = *(const uint4*)(src + row * 256 + c16 * 16);
            int nc = row >> 3, kc = c16 >> 1;
            int g  = c16 & 1;
            int T0 = (row & 7) * 4;
            char* base = dstp + (nc * 8 + kc) * 256 + g * 4;
            *(unsigned*)(base + (T0 + 0) * 8) = val.x;
            *(unsigned*)(base + (T0 + 1) * 8) = val.y;
            *(unsigned*)(base + (T0 + 2) * 8) = val.z;
            *(unsigned*)(base + (T0 + 3) * 8) = val.w;
        }
    }
    __syncthreads();

    const int warp = tid >> 5, lane = tid & 31;
    const int wm = warp >> 1, wn = warp & 1;

    long long acc[2][4][4];
    #pragma unroll
    for (int mi = 0; mi < 2; mi++)
        #pragma unroll
        for (int nj = 0; nj < 4; nj++)
            #pragma unroll
            for (int r = 0; r < 4; r++) acc[mi][nj][r] = 0ll;

    for (int j = 0; j < 4; j++) {
        int cfr[2][4][4];
        #pragma unroll
        for (int mi = 0; mi < 2; mi++)
            #pragma unroll
            for (int nj = 0; nj < 4; nj++)
                #pragma unroll
                for (int r = 0; r < 4; r++) cfr[mi][nj][r] = 0;

        const char* Bp = smem + 32768 + j * 16384;
        #pragma unroll
        for (int kc = 0; kc < 8; kc++) {
            unsigned a[2][4], b[4][2];
            #pragma unroll
            for (int mi = 0; mi < 2; mi++) {
                uint4 av = *(const uint4*)(smem + (((2*wm + mi) * 8 + kc) * 32 + lane) * 16);
                a[mi][0] = av.x; a[mi][1] = av.y; a[mi][2] = av.z; a[mi][3] = av.w;
            }
            #pragma unroll
            for (int nj = 0; nj < 4; nj++) {
                uint2 bv = *(const uint2*)(Bp + (((4*wn + nj) * 8 + kc) * 32 + lane) * 8);
                b[nj][0] = bv.x; b[nj][1] = bv.y;
            }
            #pragma unroll
            for (int mi = 0; mi < 2; mi++)
                #pragma unroll
                for (int nj = 0; nj < 4; nj++)
                    mma_s8(cfr[mi][nj], a[mi], b[nj]);
        }
        int sh = 8 * j;
        #pragma unroll
        for (int mi = 0; mi < 2; mi++)
            #pragma unroll
            for (int nj = 0; nj < 4; nj++)
                #pragma unroll
                for (int r = 0; r < 4; r++)
                    acc[mi][nj][r] += ((long long)cfr[mi][nj][r]) << sh;
    }

    #pragma unroll
    for (int mi = 0; mi < 2; mi++)
        #pragma unroll
        for (int nj = 0; nj < 4; nj++)
            #pragma unroll
            for (int r = 0; r < 4; r++) {
                int row = m0 + 32*wm + 16*mi + (lane >> 2) + 8*(r >> 1);
                int col = n0 + 32*wn + 8*nj + 2*(lane & 3) + (r & 1);
                Zp[(size_t)row * H_ + col] = (int)((acc[mi][nj][r] + 16ll) >> 5);
            }
}

// ===================== fixed-point LN/LIF ===================================
#define EPS_U   1.8014398509481984e11      // 1e-5 * 2^54
#define MAGIC   6755399441055744.0          // 2^52 * 1.5
#define MAGICLL 0x4338000000000000LL
#define P2_58   288230376151711744.0
#define P2_31   2147483648.0
#define TH_Y    2147483648LL

__device__ __forceinline__ double newton_rsqrt(double x)
{
    double r = (double)rsqrtf((float)x);
    return r * (1.5 - 0.5 * x * r * r);
}

__global__ void __launch_bounds__(256, 2) ln_lif_qkv_kernel(
    const int* __restrict__ Zq, const int* __restrict__ Zk,
    const int* __restrict__ Zv,
    const float* __restrict__ qlw, const float* __restrict__ qlb,
    const float* __restrict__ klw, const float* __restrict__ klb,
    const float* __restrict__ vlw, const float* __restrict__ vlb,
    uint32_t* __restrict__ qb, uint32_t* __restrict__ kb, uint8_t* __restrict__ vb)
{
    const int gw = blockIdx.x * 8 + (threadIdx.x >> 5);
    const int lane = threadIdx.x & 31;
    const int br = blockIdx.y;
    const int b = gw / L_, l = gw % L_;
    const int h0 = lane * 8;

    const int* Z = (br == 0) ? Zq : ((br == 1) ? Zk : Zv);
    const float* lwp = (br == 0) ? qlw : ((br == 1) ? klw : vlw);
    const float* lbp = (br == 0) ? qlb : ((br == 1) ? klb : vlb);

    double w58[8];
    long long bint[8];
    {
        float4 w0 = *(const float4*)(lwp + h0), w1 = *(const float4*)(lwp + h0 + 4);
        float4 c0 = *(const float4*)(lbp + h0), c1 = *(const float4*)(lbp + h0 + 4);
        float wa[8] = {w0.x,w0.y,w0.z,w0.w,w1.x,w1.y,w1.z,w1.w};
        float ba[8] = {c0.x,c0.y,c0.z,c0.w,c1.x,c1.y,c1.z,c1.w};
        #pragma unroll
        for (int e = 0; e < 8; e++) {
            w58[e]  = (double)wa[e] * P2_58;
            bint[e] = __double2ll_rn((double)ba[e] * P2_31);
        }
    }

    int zi[4][8];
    #pragma unroll
    for (int t = 0; t < T_; t++) {
        const int* zr = Z + ((size_t)(t * B_ + b) * L_ + l) * H_ + h0;
        int4 p0 = ((const int4*)zr)[0];
        int4 p1 = ((const int4*)zr)[1];
        zi[t][0]=p0.x; zi[t][1]=p0.y; zi[t][2]=p0.z; zi[t][3]=p0.w;
        zi[t][4]=p1.x; zi[t][5]=p1.y; zi[t][6]=p1.z; zi[t][7]=p1.w;
    }

    long long s[4], sq[4];
    #pragma unroll
    for (int t = 0; t < T_; t++) {
        long long a = 0, c = 0;
        #pragma unroll
        for (int e = 0; e < 8; e++) {
            a += zi[t][e];
            c += (long long)zi[t][e] * zi[t][e];
        }
        s[t] = a; sq[t] = c >> 6;
    }
    #pragma unroll
    for (int o = 16; o; o >>= 1) {
        #pragma unroll
        for (int t = 0; t < T_; t++) {
            s[t]  += __shfl_xor_sync(0xffffffffu, s[t],  o);
            sq[t] += __shfl_xor_sync(0xffffffffu, sq[t], o);
        }
    }

    long long vm[8];
    #pragma unroll
    for (int e = 0; e < 8; e++) vm[e] = 0ll;

    #pragma unroll
    for (int t = 0; t < T_; t++) {
        int m_q = (int)((s[t] + 128) >> 8);
        double mean = (double)s[t] * (1.0 / 256.0);
        double var_u = (double)sq[t] * 0.25 - mean * mean;
        double C = newton_rsqrt(var_u + EPS_U);

        unsigned byte = 0, blo = 0, bhi = 0;
        #pragma unroll
        for (int e = 0; e < 8; e++) {
            long long G = __double_as_longlong(fma(C, w58[e], MAGIC)) - MAGICLL;
            int dv = zi[t][e] - m_q;
            long long Y = (((long long)dv * G) >> 27) + bint[e];
            vm[e] = (vm[e] + Y) >> 1;
            bool sp = vm[e] >= TH_Y;
            if (sp) vm[e] = 0ll;
            byte |= (sp ? 1u : 0u) << e;
            if (e < 4) blo |= (sp ? 1u : 0u) << (8 * e);
            else       bhi |= (sp ? 1u : 0u) << (8 * (e - 4));
        }
        if (br < 2) {
            unsigned v = byte << (8 * (lane & 3));
            v |= __shfl_xor_sync(0xffffffffu, v, 1);
            v |= __shfl_xor_sync(0xffffffffu, v, 2);
            if ((lane & 3) == 0) {
                int g = lane >> 2;
                int head = g >> 2, widx = g & 3;
                uint32_t* dst = (br == 0) ? qb : kb;
                dst[(((size_t)(t * B_ + b) * 2 + head) * L_ + l) * 4 + widx] = v;
            }
        } else {
            int head = lane >> 4;
            int d0 = 8 * (lane & 15);
            uint8_t* dst = vb + ((((size_t)(t * B_ + b) * 2 + head) * L_ + l) * 128 + d0);
            *(uint2*)dst = make_uint2(blo, bhi);
        }
    }
}

__global__ void __launch_bounds__(256, 2) proj_ln_lif_kernel(
    const int* __restrict__ Zp, const float* __restrict__ pb,
    const float* __restrict__ lw, const float* __restrict__ lb,
    float* __restrict__ out)
{
    const int gw = blockIdx.x * 8 + (threadIdx.x >> 5);
    const int lane = threadIdx.x & 31;
    const int b = gw / L_, l = gw % L_;
    const int h0 = lane * 8;

    double w58[8];
    long long bint[8];
    int pbq[8];
    {
        float4 w0 = *(const float4*)(lw + h0), w1 = *(const float4*)(lw + h0 + 4);
        float4 c0 = *(const float4*)(lb + h0), c1 = *(const float4*)(lb + h0 + 4);
        float4 p0 = *(const float4*)(pb + h0), p1 = *(const float4*)(pb + h0 + 4);
        float wa[8] = {w0.x,w0.y,w0.z,w0.w,w1.x,w1.y,w1.z,w1.w};
        float ba[8] = {c0.x,c0.y,c0.z,c0.w,c1.x,c1.y,c1.z,c1.w};
        float pa[8] = {p0.x,p0.y,p0.z,p0.w,p1.x,p1.y,p1.z,p1.w};
        #pragma unroll
        for (int e = 0; e < 8; e++) {
            w58[e]  = (double)wa[e] * P2_58;
            bint[e] = __double2ll_rn((double)ba[e] * P2_31);
            pbq[e]  = __double2int_rn((double)pa[e] * 134217728.0);
        }
    }

    int zi[4][8];
    #pragma unroll
    for (int t = 0; t < T_; t++) {
        const int* zr = Zp + ((size_t)(t * B_ + b) * L_ + l) * H_ + h0;
        int4 p0 = ((const int4*)zr)[0];
        int4 p1 = ((const int4*)zr)[1];
        zi[t][0]=p0.x+pbq[0]; zi[t][1]=p0.y+pbq[1]; zi[t][2]=p0.z+pbq[2]; zi[t][3]=p0.w+pbq[3];
        zi[t][4]=p1.x+pbq[4]; zi[t][5]=p1.y+pbq[5]; zi[t][6]=p1.z+pbq[6]; zi[t][7]=p1.w+pbq[7];
    }

    long long s[4], sq[4];
    #pragma unroll
    for (int t = 0; t < T_; t++) {
        long long a = 0, c = 0;
        #pragma unroll
        for (int e = 0; e < 8; e++) {
            a += zi[t][e];
            c += (long long)zi[t][e] * zi[t][e];
        }
        s[t] = a; sq[t] = c >> 6;
    }
    #pragma unroll
    for (int o = 16; o; o >>= 1) {
        #pragma unroll
        for (int t = 0; t < T_; t++) {
            s[t]  += __shfl_xor_sync(0xffffffffu, s[t],  o);
            sq[t] += __shfl_xor_sync(0xffffffffu, sq[t], o);
        }
    }

    long long vm[8];
    #pragma unroll
    for (int e = 0; e < 8; e++) vm[e] = 0ll;

    #pragma unroll
    for (int t = 0; t < T_; t++) {
        int m_q = (int)((s[t] + 128) >> 8);
        double mean = (double)s[t] * (1.0 / 256.0);
        double var_u = (double)sq[t] * 0.25 - mean * mean;
        double C = newton_rsqrt(var_u + EPS_U);
        float spf[8];
        #pragma unroll
        for (int e = 0; e < 8; e++) {
            long long G = __double_as_longlong(fma(C, w58[e], MAGIC)) - MAGICLL;
            int dv = zi[t][e] - m_q;
            long long Y = (((long long)dv * G) >> 27) + bint[e];
            vm[e] = (vm[e] + Y) >> 1;
            bool sp = vm[e] >= TH_Y;
            if (sp) vm[e] = 0ll;
            spf[e] = sp ? 1.f : 0.f;
        }
        float* dst = out + ((size_t)(t * B_ + b) * L_ + l) * H_ + h0;
        *(float4*)(dst)     = make_float4(spf[0], spf[1], spf[2], spf[3]);
        *(float4*)(dst + 4) = make_float4(spf[4], spf[5], spf[6], spf[7]);
    }
}

// ===================== attention (u8 IMMA, exact) ===========================
#define ATT_SA   0
#define ATT_SB   46592
#define ATT_SV   75264
#define ATT_SKB  100864
#define ATTN_SMEM 104064

__global__ void __launch_bounds__(256, 2) attn_kernel(
    const uint32_t* __restrict__ qb, const uint32_t* __restrict__ kb,
    const uint8_t* __restrict__ vb, float* __restrict__ y)
{
    extern __shared__ char smem[];
    char*     sA  = smem + ATT_SA;
    char*     sB  = smem + ATT_SB;
    uint8_t*  sV  = (uint8_t*)(smem + ATT_SV);
    uint32_t* skb = (uint32_t*)(smem + ATT_SKB);

    const int batch = blockIdx.x;
    const uint32_t* qb_b = qb + (size_t)batch * L_ * 4;
    const uint32_t* kb_b = kb + (size_t)batch * L_ * 4;
    const uint8_t*  v_b  = vb + (size_t)batch * L_ * 128;
    float*          y_b  = y  + (size_t)batch * L_ * 128;

    const int tid = threadIdx.x;
    const int warp = tid >> 5, lane = tid & 31;

    for (int i = tid; i < L_ * 8; i += 256)
        ((uint4*)sV)[i] = ((const uint4*)v_b)[i];
    for (int i = tid; i < L_ * 4; i += 256) skb[i] = kb_b[i];
    __syncthreads();

    for (int idx = tid; idx < 128 * 56; idx += 256) {
        int d = idx / 56, mg = idx % 56;
        int m0 = mg * 4;
        unsigned w = 0;
        #pragma unroll
        for (int e = 0; e < 4; e++) {
            int m = m0 + e;
            unsigned bv = (m < L_) ? (unsigned)sV[m * 128 + d] : 0u;
            w |= bv << (8 * e);
        }
        char* addr = sB + ((d >> 3) * 7 + (m0 >> 5)) * 256
                   + ((d & 7) * 4 + ((m0 >> 2) & 3)) * 8
                   + ((m0 >> 4) & 1) * 4;
        *(unsigned*)addr = w;
    }

    for (int r = warp; r < L_; r += 8) {
        uint32_t q0 = qb_b[r*4+0], q1 = qb_b[r*4+1];
        uint32_t q2 = qb_b[r*4+2], q3 = qb_b[r*4+3];
        for (int g = lane; g < 50; g += 32) {
            int m0 = g * 4;
            unsigned w = 0;
            #pragma unroll
            for (int e = 0; e < 4; e++) {
                int m = m0 + e;
                unsigned c = __popc(q0 & skb[m*4+0]) + __popc(q1 & skb[m*4+1])
                           + __popc(q2 & skb[m*4+2]) + __popc(q3 & skb[m*4+3]);
                w |= c << (8 * e);
            }
            char* addr = sA + ((r >> 4) * 7 + (m0 >> 5)) * 512
                       + ((r & 7) * 4 + ((m0 >> 2) & 3)) * 16
                       + (((m0 >> 4) & 1) * 2 + ((r >> 3) & 1)) * 4;
            *(unsigned*)addr = w;
        }
    }
    __syncthreads();

    for (int mt = warp; mt < 13; mt += 8) {
        for (int ntile = 0; ntile < 16; ntile++) {
            int acc[4] = {0, 0, 0, 0};
            #pragma unroll
            for (int kc = 0; kc < 7; kc++) {
                unsigned a[4], b[2];
                uint4 av = *(const uint4*)(sA + ((mt * 7 + kc) * 32 + lane) * 16);
                a[0] = av.x; a[1] = av.y; a[2] = av.z; a[3] = av.w;
                uint2 bv = *(const uint2*)(sB + ((ntile * 7 + kc) * 32 + lane) * 8);
                b[0] = bv.x; b[1] = bv.y;
                mma_u8(acc, a, b);
            }
            int r0  = mt * 16 + (lane >> 2);
            int col = ntile * 8 + 2 * (lane & 3);
            #pragma unroll
            for (int rr = 0; rr < 2; rr++) {
                int row = r0 + 8 * rr;
                if (row < L_) {
                    y_b[(size_t)row * 128 + col]     = (float)acc[2*rr]     * 0.125f;
                    y_b[(size_t)row * 128 + col + 1] = (float)acc[2*rr + 1] * 0.125f;
                }
            }
        }
    }
}

// ---------------------------------------------------------------------------
__global__ void __launch_bounds__(256) attn_lif_kernel(
    const float* __restrict__ y, int8_t* __restrict__ s2)
{
    const int bl = blockIdx.x;
    const int b = bl / L_, l = bl % L_;
    const int h = threadIdx.x;
    const int head = h >> 7, d = h & 127;
    float yv[4];
    #pragma unroll
    for (int t = 0; t < T_; t++)
        yv[t] = y[(((size_t)(t * B_ + b) * 2 + head) * L_ + l) * 128 + d];
    float vmem = 0.f;
    #pragma unroll
    for (int t = 0; t < T_; t++) {
        vmem = vmem + (yv[t] - vmem) * 0.5f;
        bool sp = (vmem - 0.5f) >= 0.f;
        if (sp) vmem = 0.f;
        s2[((size_t)(t * B_ + b) * L_ + l) * H_ + h] = sp ? 1 : 0;
    }
}

// ---------------------------------------------------------------------------
extern "C" void kernel_launch(void* const* d_in, const int* in_sizes, int n_in,
                              void* d_out, int out_size)
{
    const float* x   = (const float*)d_in[0];
    const float* qw  = (const float*)d_in[1];
    const float* qlw = (const float*)d_in[2];
    const float* qlb = (const float*)d_in[3];
    const float* kw  = (const float*)d_in[4];
    const float* klw = (const float*)d_in[5];
    const float* klb = (const float*)d_in[6];
    const float* vw  = (const float*)d_in[7];
    const float* vlw = (const float*)d_in[8];
    const float* vlb = (const float*)d_in[9];
    const float* pw  = (const float*)d_in[10];
    const float* pb  = (const float*)d_in[11];
    const float* plw = (const float*)d_in[12];
    const float* plb = (const float*)d_in[13];
    float* out = (float*)d_out;

    int8_t *asl, *wsl, *s2;
    uint8_t *vbp;
    int *Zq, *Zk, *Zv, *zp;
    float *yv;
    uint32_t *qbp, *kbp;
    cudaGetSymbolAddress((void**)&asl, g_asl);
    cudaGetSymbolAddress((void**)&wsl, g_wsl);
    cudaGetSymbolAddress((void**)&s2,  g_s2);
    cudaGetSymbolAddress((void**)&vbp, g_vb);
    cudaGetSymbolAddress((void**)&Zq,  g_Zq);
    cudaGetSymbolAddress((void**)&Zk,  g_Zk);
    cudaGetSymbolAddress((void**)&Zv,  g_Zv);
    cudaGetSymbolAddress((void**)&zp,  g_zp);
    cudaGetSymbolAddress((void**)&yv,  g_y);
    cudaGetSymbolAddress((void**)&qbp, g_qb);
    cudaGetSymbolAddress((void**)&kbp, g_kb);

    cudaFuncSetAttribute(gemm_qkv_kernel, cudaFuncAttributeMaxDynamicSharedMemorySize, QKV_SMEM);
    cudaFuncSetAttribute(gemm_proj_kernel, cudaFuncAttributeMaxDynamicSharedMemorySize, PROJ_SMEM);
    cudaFuncSetAttribute(attn_kernel, cudaFuncAttributeMaxDynamicSharedMemorySize, ATTN_SMEM);

    slice_x_kernel<<<4096, 256>>>(x, asl);
    slice_w_kernel<<<256, 256>>>(qw, kw, vw, pw, wsl);

    dim3 gq(12, 400);
    gemm_qkv_kernel<<<gq, 256, QKV_SMEM>>>(asl, wsl, Zq, Zk, Zv);

    dim3 gl(BLr / 8, 3);
    ln_lif_qkv_kernel<<<gl, 256>>>(Zq, Zk, Zv, qlw, qlb, klw, klb, vlw, vlb,
                                   qbp, kbp, vbp);

    attn_kernel<<<NBATCH, 256, ATTN_SMEM>>>(qbp, kbp, vbp, yv);

    attn_lif_kernel<<<BLr, 256>>>(yv, s2);

    dim3 gp(4, 400);
    gemm_proj_kernel<<<gp, 256, PROJ_SMEM>>>(s2, wsl, zp);

    proj_ln_lif_kernel<<<BLr / 8, 256>>>(zp, pb, plw, plb, out);
}

// round 17
// speedup vs baseline: 11.8283x; 1.0232x over previous
#include <cuda_runtime.h>
#include <cstdint>
#include <cmath>

// ---------------------------------------------------------------------------
// SSA forward: exact int8 IMMA GEMM (digit pairs s>=3, XOR-swizzled frag smem)
// + fixed-point LN/LIF + fused integer tensor-core attention (u8 IMMA PV with
// in-register LIF over T, writes s2 directly).
// Error budget unchanged from R16 (~2e-8 RMS << reference ~1e-7 window).
// ---------------------------------------------------------------------------

#define T_  4
#define B_  64
#define L_  200
#define H_  256
#define M_  (T_*B_*L_)      // 51200
#define BLr (B_*L_)         // 12800
#define NBATCH (T_*B_*2)    // 512 (t,b,head)

__device__ __align__(128) int8_t g_asl[4ull*M_*H_];
__device__ __align__(128) int8_t g_wsl[16ull*H_*H_];
__device__ __align__(128) int8_t g_s2[(size_t)M_*H_];
__device__ __align__(128) uint8_t g_vb[(size_t)NBATCH*L_*128];
__device__ __align__(128) int g_Zq[(size_t)M_*H_];   // Z*2^27 as int32
__device__ __align__(128) int g_Zk[(size_t)M_*H_];
__device__ __align__(128) int g_Zv[(size_t)M_*H_];
__device__ __align__(128) int g_zp[(size_t)M_*H_];
__device__ uint32_t g_qb[NBATCH*L_*4];
__device__ uint32_t g_kb[NBATCH*L_*4];

// ---------------------------------------------------------------------------
__device__ __forceinline__ void mma_s8(int* c, const unsigned* a, const unsigned* b)
{
    asm volatile(
        "mma.sync.aligned.m16n8k32.row.col.s32.s8.s8.s32 "
        "{%0,%1,%2,%3}, {%4,%5,%6,%7}, {%8,%9}, {%0,%1,%2,%3};"
        : "+r"(c[0]), "+r"(c[1]), "+r"(c[2]), "+r"(c[3])
        : "r"(a[0]), "r"(a[1]), "r"(a[2]), "r"(a[3]), "r"(b[0]), "r"(b[1]));
}
__device__ __forceinline__ void mma_u8(int* c, const unsigned* a, const unsigned* b)
{
    asm volatile(
        "mma.sync.aligned.m16n8k32.row.col.s32.u8.u8.s32 "
        "{%0,%1,%2,%3}, {%4,%5,%6,%7}, {%8,%9}, {%0,%1,%2,%3};"
        : "+r"(c[0]), "+r"(c[1]), "+r"(c[2]), "+r"(c[3])
        : "r"(a[0]), "r"(a[1]), "r"(a[2]), "r"(a[3]), "r"(b[0]), "r"(b[1]));
}

// bank swizzle: XOR bits [5:4] with (tile & 3); uniform per MMA-load instr.
#define XS(raw, tile) ((raw) ^ (((tile) & 3) << 4))

// ===================== digit-slice generation ===============================
__global__ void slice_x_kernel(const float* __restrict__ x, int8_t* __restrict__ asl)
{
    int i4 = blockIdx.x * blockDim.x + threadIdx.x;
    int stride = gridDim.x * blockDim.x;
    const size_t plane4 = (size_t)M_ * H_ / 4;
    for (; i4 < M_ * H_ / 4; i4 += stride) {
        float4 xv = ((const float4*)x)[i4];
        float vals[4] = {xv.x, xv.y, xv.z, xv.w};
        unsigned out[4] = {0, 0, 0, 0};
        #pragma unroll
        for (int e = 0; e < 4; e++) {
            int q = __double2int_rn((double)vals[e] * 134217728.0);  // 2^27
            #pragma unroll
            for (int s = 0; s < 4; s++) {
                int d = ((q + 128) & 255) - 128;
                q = (q - d) >> 8;
                out[s] |= (unsigned)(d & 255) << (8 * e);
            }
        }
        #pragma unroll
        for (int s = 0; s < 4; s++)
            ((unsigned*)asl)[s * plane4 + i4] = out[s];
    }
}

__global__ void slice_w_kernel(const float* __restrict__ qw, const float* __restrict__ kw,
                               const float* __restrict__ vw, const float* __restrict__ pw,
                               int8_t* __restrict__ wsl)
{
    int i = blockIdx.x * blockDim.x + threadIdx.x;
    int stride = gridDim.x * blockDim.x;
    for (; i < 4 * H_ * H_; i += stride) {
        int widx = i >> 16, j = i & 65535;
        const float* W = (widx == 0) ? qw : ((widx == 1) ? kw : ((widx == 2) ? vw : pw));
        long long q = __double2ll_rn((double)W[j] * 4294967296.0);  // 2^32
        #pragma unroll
        for (int s = 0; s < 4; s++) {
            int d = (int)(((q + 128) & 255)) - 128;
            q = (q - d) >> 8;
            wsl[(size_t)(widx * 4 + s) * 65536 + j] = (int8_t)d;
        }
    }
}

// ===================== qkv slice GEMM (IMMA, s>=3 pairs, 2 CTA/SM) ==========
#define QKV_SMEM (4*16384 + 4*8192)   // 98304

__global__ void __launch_bounds__(256, 2) gemm_qkv_kernel(
    const int8_t* __restrict__ asl, const int8_t* __restrict__ wsl,
    int* __restrict__ Zq, int* __restrict__ Zk, int* __restrict__ Zv)
{
    extern __shared__ char smem[];
    const int tid = threadIdx.x;
    const int nt = blockIdx.x, mt = blockIdx.y;
    const int widx = nt >> 2, n0 = (nt & 3) * 64, m0 = mt * 128;

    const int warp = tid >> 5, lane = tid & 31;
    const int wm = warp >> 1, wn = warp & 1;

    const int PI[10] = {0,1,2,3, 1,2,3, 2,3, 3};
    const int PJ[10] = {3,2,1,0, 3,2,1, 3,2, 3};
    const int DS[5]  = {0, 4, 7, 9, 10};

    long long acc[2][4][4];
    #pragma unroll
    for (int mi = 0; mi < 2; mi++)
        #pragma unroll
        for (int nj = 0; nj < 4; nj++)
            #pragma unroll
            for (int r = 0; r < 4; r++) acc[mi][nj][r] = 0ll;

    for (int c2 = 0; c2 < 2; c2++) {
        if (c2) __syncthreads();
        #pragma unroll
        for (int p = 0; p < 4; p++) {
            const int8_t* src = asl + (size_t)p * M_ * H_ + (size_t)m0 * 256 + c2 * 128;
            char* dstp = smem + p * 16384;
            #pragma unroll
            for (int v = 0; v < 4; v++) {
                int chunk = tid + 256 * v;
                int row = chunk >> 3, c16 = chunk & 7;
                uint4 val = *(const uint4*)(src + row * 256 + c16 * 16);
                int mc = row >> 4, kc = c16 >> 1;
                int tile = mc * 4 + kc;
                int g  = ((c16 & 1) << 1) | ((row >> 3) & 1);
                int T0 = (row & 7) * 4;
                int base = tile * 512 + g * 4;
                *(unsigned*)(dstp + XS(base + (T0 + 0) * 16, tile)) = val.x;
                *(unsigned*)(dstp + XS(base + (T0 + 1) * 16, tile)) = val.y;
                *(unsigned*)(dstp + XS(base + (T0 + 2) * 16, tile)) = val.z;
                *(unsigned*)(dstp + XS(base + (T0 + 3) * 16, tile)) = val.w;
            }
        }
        #pragma unroll
        for (int p = 0; p < 4; p++) {
            const int8_t* src = wsl + (size_t)(widx * 4 + p) * 65536 + n0 * 256 + c2 * 128;
            char* dstp = smem + 65536 + p * 8192;
            #pragma unroll
            for (int v = 0; v < 2; v++) {
                int chunk = tid + 256 * v;
                int row = chunk >> 3, c16 = chunk & 7;
                uint4 val = *(const uint4*)(src + row * 256 + c16 * 16);
                int nc = row >> 3, kc = c16 >> 1;
                int tile = nc * 4 + kc;
                int g  = c16 & 1;
                int T0 = (row & 7) * 4;
                int base = tile * 256 + g * 4;
                *(unsigned*)(dstp + XS(base + (T0 + 0) * 8, tile)) = val.x;
                *(unsigned*)(dstp + XS(base + (T0 + 1) * 8, tile)) = val.y;
                *(unsigned*)(dstp + XS(base + (T0 + 2) * 8, tile)) = val.z;
                *(unsigned*)(dstp + XS(base + (T0 + 3) * 8, tile)) = val.w;
            }
        }
        __syncthreads();

        for (int sd = 0; sd < 4; sd++) {
            int cfr[2][4][4];
            #pragma unroll
            for (int mi = 0; mi < 2; mi++)
                #pragma unroll
                for (int nj = 0; nj < 4; nj++)
                    #pragma unroll
                    for (int r = 0; r < 4; r++) cfr[mi][nj][r] = 0;

            for (int p = DS[sd]; p < DS[sd + 1]; p++) {
                const char* Ap = smem + PI[p] * 16384;
                const char* Bp = smem + 65536 + PJ[p] * 8192;
                #pragma unroll
                for (int kc = 0; kc < 4; kc++) {
                    unsigned a[2][4], b[4][2];
                    #pragma unroll
                    for (int mi = 0; mi < 2; mi++) {
                        int tile = (2*wm + mi) * 4 + kc;
                        uint4 av = *(const uint4*)(Ap + XS((tile * 32 + lane) * 16, tile));
                        a[mi][0] = av.x; a[mi][1] = av.y; a[mi][2] = av.z; a[mi][3] = av.w;
                    }
                    #pragma unroll
                    for (int nj = 0; nj < 4; nj++) {
                        int tile = (4*wn + nj) * 4 + kc;
                        uint2 bv = *(const uint2*)(Bp + XS((tile * 32 + lane) * 8, tile));
                        b[nj][0] = bv.x; b[nj][1] = bv.y;
                    }
                    #pragma unroll
                    for (int mi = 0; mi < 2; mi++)
                        #pragma unroll
                        for (int nj = 0; nj < 4; nj++)
                            mma_s8(cfr[mi][nj], a[mi], b[nj]);
                }
            }
            int sh = 8 * sd;
            #pragma unroll
            for (int mi = 0; mi < 2; mi++)
                #pragma unroll
                for (int nj = 0; nj < 4; nj++)
                    #pragma unroll
                    for (int r = 0; r < 4; r++)
                        acc[mi][nj][r] += ((long long)cfr[mi][nj][r]) << sh;
        }
    }

    // acc = Z * 2^35; zint = round(acc * 2^-8) -> Z*2^27
    int* Zout = (widx == 0) ? Zq : ((widx == 1) ? Zk : Zv);
    #pragma unroll
    for (int mi = 0; mi < 2; mi++)
        #pragma unroll
        for (int nj = 0; nj < 4; nj++)
            #pragma unroll
            for (int r = 0; r < 4; r++) {
                int row = m0 + 32*wm + 16*mi + (lane >> 2) + 8*(r >> 1);
                int col = n0 + 32*wn + 8*nj + 2*(lane & 3) + (r & 1);
                Zout[(size_t)row * H_ + col] = (int)((acc[mi][nj][r] + 128ll) >> 8);
            }
}

// ===================== proj slice GEMM (IMMA) ===============================
#define PROJ_SMEM (32768 + 4*16384)   // 98304

__global__ void __launch_bounds__(256, 2) gemm_proj_kernel(
    const int8_t* __restrict__ s2, const int8_t* __restrict__ wsl,
    int* __restrict__ Zp)
{
    extern __shared__ char smem[];
    const int tid = threadIdx.x;
    const int nt = blockIdx.x, mt = blockIdx.y;
    const int n0 = nt * 64, m0 = mt * 128;

    {
        const int8_t* src = s2 + (size_t)m0 * 256;
        #pragma unroll
        for (int v = 0; v < 8; v++) {
            int chunk = tid + 256 * v;
            int row = chunk >> 4, c16 = chunk & 15;
            uint4 val = *(const uint4*)(src + row * 256 + c16 * 16);
            int mc = row >> 4, kc = c16 >> 1;
            int tile = mc * 8 + kc;
            int g  = ((c16 & 1) << 1) | ((row >> 3) & 1);
            int T0 = (row & 7) * 4;
            int base = tile * 512 + g * 4;
            *(unsigned*)(smem + XS(base + (T0 + 0) * 16, tile)) = val.x;
            *(unsigned*)(smem + XS(base + (T0 + 1) * 16, tile)) = val.y;
            *(unsigned*)(smem + XS(base + (T0 + 2) * 16, tile)) = val.z;
            *(unsigned*)(smem + XS(base + (T0 + 3) * 16, tile)) = val.w;
        }
    }
    #pragma unroll
    for (int p = 0; p < 4; p++) {
        const int8_t* src = wsl + (size_t)(12 + p) * 65536 + n0 * 256;
        char* dstp = smem + 32768 + p * 16384;
        #pragma unroll
        for (int v = 0; v < 4; v++) {
            int chunk = tid + 256 * v;
            int row = chunk >> 4, c16 = chunk & 15;
            uint4 val = *(const uint4*)(src + row * 256 + c16 * 16);
            int nc = row >> 3, kc = c16 >> 1;
            int tile = nc * 8 + kc;
            int g  = c16 & 1;
            int T0 = (row & 7) * 4;
            int base = tile * 256 + g * 4;
            *(unsigned*)(dstp + XS(base + (T0 + 0) * 8, tile)) = val.x;
            *(unsigned*)(dstp + XS(base + (T0 + 1) * 8, tile)) = val.y;
            *(unsigned*)(dstp + XS(base + (T0 + 2) * 8, tile)) = val.z;
            *(unsigned*)(dstp + XS(base + (T0 + 3) * 8, tile)) = val.w;
        }
    }
    __syncthreads();

    const int warp = tid >> 5, lane = tid & 31;
    const int wm = warp >> 1, wn = warp & 1;

    long long acc[2][4][4];
    #pragma unroll
    for (int mi = 0; mi < 2; mi++)
        #pragma unroll
        for (int nj = 0; nj < 4; nj++)
            #pragma unroll
            for (int r = 0; r < 4; r++) acc[mi][nj][r] = 0ll;

    for (int j = 0; j < 4; j++) {
        int cfr[2][4][4];
        #pragma unroll
        for (int mi = 0; mi < 2; mi++)
            #pragma unroll
            for (int nj = 0; nj < 4; nj++)
                #pragma unroll
                for (int r = 0; r < 4; r++) cfr[mi][nj][r] = 0;

        const char* Bp = smem + 32768 + j * 16384;
        #pragma unroll
        for (int kc = 0; kc < 8; kc++) {
            unsigned a[2][4], b[4][2];
            #pragma unroll
            for (int mi = 0; mi < 2; mi++) {
                int tile = (2*wm + mi) * 8 + kc;
                uint4 av = *(const uint4*)(smem + XS((tile * 32 + lane) * 16, tile));
                a[mi][0] = av.x; a[mi][1] = av.y; a[mi][2] = av.z; a[mi][3] = av.w;
            }
            #pragma unroll
            for (int nj = 0; nj < 4; nj++) {
                int tile = (4*wn + nj) * 8 + kc;
                uint2 bv = *(const uint2*)(Bp + XS((tile * 32 + lane) * 8, tile));
                b[nj][0] = bv.x; b[nj][1] = bv.y;
            }
            #pragma unroll
            for (int mi = 0; mi < 2; mi++)
                #pragma unroll
                for (int nj = 0; nj < 4; nj++)
                    mma_s8(cfr[mi][nj], a[mi], b[nj]);
        }
        int sh = 8 * j;
        #pragma unroll
        for (int mi = 0; mi < 2; mi++)
            #pragma unroll
            for (int nj = 0; nj < 4; nj++)
                #pragma unroll
                for (int r = 0; r < 4; r++)
                    acc[mi][nj][r] += ((long long)cfr[mi][nj][r]) << sh;
    }

    #pragma unroll
    for (int mi = 0; mi < 2; mi++)
        #pragma unroll
        for (int nj = 0; nj < 4; nj++)
            #pragma unroll
            for (int r = 0; r < 4; r++) {
                int row = m0 + 32*wm + 16*mi + (lane >> 2) + 8*(r >> 1);
                int col = n0 + 32*wn + 8*nj + 2*(lane & 3) + (r & 1);
                Zp[(size_t)row * H_ + col] = (int)((acc[mi][nj][r] + 16ll) >> 5);
            }
}

// ===================== fixed-point LN/LIF ===================================
#define EPS_U   1.8014398509481984e11      // 1e-5 * 2^54
#define MAGIC   6755399441055744.0          // 2^52 * 1.5
#define MAGICLL 0x4338000000000000LL
#define P2_58   288230376151711744.0
#define P2_31   2147483648.0
#define TH_Y    2147483648LL

__device__ __forceinline__ double newton_rsqrt(double x)
{
    double r = (double)rsqrtf((float)x);
    return r * (1.5 - 0.5 * x * r * r);
}

__global__ void __launch_bounds__(256, 2) ln_lif_qkv_kernel(
    const int* __restrict__ Zq, const int* __restrict__ Zk,
    const int* __restrict__ Zv,
    const float* __restrict__ qlw, const float* __restrict__ qlb,
    const float* __restrict__ klw, const float* __restrict__ klb,
    const float* __restrict__ vlw, const float* __restrict__ vlb,
    uint32_t* __restrict__ qb, uint32_t* __restrict__ kb, uint8_t* __restrict__ vb)
{
    const int gw = blockIdx.x * 8 + (threadIdx.x >> 5);
    const int lane = threadIdx.x & 31;
    const int br = blockIdx.y;
    const int b = gw / L_, l = gw % L_;
    const int h0 = lane * 8;

    const int* Z = (br == 0) ? Zq : ((br == 1) ? Zk : Zv);
    const float* lwp = (br == 0) ? qlw : ((br == 1) ? klw : vlw);
    const float* lbp = (br == 0) ? qlb : ((br == 1) ? klb : vlb);

    double w58[8];
    long long bint[8];
    {
        float4 w0 = *(const float4*)(lwp + h0), w1 = *(const float4*)(lwp + h0 + 4);
        float4 c0 = *(const float4*)(lbp + h0), c1 = *(const float4*)(lbp + h0 + 4);
        float wa[8] = {w0.x,w0.y,w0.z,w0.w,w1.x,w1.y,w1.z,w1.w};
        float ba[8] = {c0.x,c0.y,c0.z,c0.w,c1.x,c1.y,c1.z,c1.w};
        #pragma unroll
        for (int e = 0; e < 8; e++) {
            w58[e]  = (double)wa[e] * P2_58;
            bint[e] = __double2ll_rn((double)ba[e] * P2_31);
        }
    }

    int zi[4][8];
    #pragma unroll
    for (int t = 0; t < T_; t++) {
        const int* zr = Z + ((size_t)(t * B_ + b) * L_ + l) * H_ + h0;
        int4 p0 = ((const int4*)zr)[0];
        int4 p1 = ((const int4*)zr)[1];
        zi[t][0]=p0.x; zi[t][1]=p0.y; zi[t][2]=p0.z; zi[t][3]=p0.w;
        zi[t][4]=p1.x; zi[t][5]=p1.y; zi[t][6]=p1.z; zi[t][7]=p1.w;
    }

    long long s[4], sq[4];
    #pragma unroll
    for (int t = 0; t < T_; t++) {
        long long a = 0, c = 0;
        #pragma unroll
        for (int e = 0; e < 8; e++) {
            a += zi[t][e];
            c += (long long)zi[t][e] * zi[t][e];
        }
        s[t] = a; sq[t] = c >> 6;
    }
    #pragma unroll
    for (int o = 16; o; o >>= 1) {
        #pragma unroll
        for (int t = 0; t < T_; t++) {
            s[t]  += __shfl_xor_sync(0xffffffffu, s[t],  o);
            sq[t] += __shfl_xor_sync(0xffffffffu, sq[t], o);
        }
    }

    long long vm[8];
    #pragma unroll
    for (int e = 0; e < 8; e++) vm[e] = 0ll;

    #pragma unroll
    for (int t = 0; t < T_; t++) {
        int m_q = (int)((s[t] + 128) >> 8);
        double mean = (double)s[t] * (1.0 / 256.0);
        double var_u = (double)sq[t] * 0.25 - mean * mean;
        double C = newton_rsqrt(var_u + EPS_U);

        unsigned byte = 0, blo = 0, bhi = 0;
        #pragma unroll
        for (int e = 0; e < 8; e++) {
            long long G = __double_as_longlong(fma(C, w58[e], MAGIC)) - MAGICLL;
            int dv = zi[t][e] - m_q;
            long long Y = (((long long)dv * G) >> 27) + bint[e];
            vm[e] = (vm[e] + Y) >> 1;
            bool sp = vm[e] >= TH_Y;
            if (sp) vm[e] = 0ll;
            byte |= (sp ? 1u : 0u) << e;
            if (e < 4) blo |= (sp ? 1u : 0u) << (8 * e);
            else       bhi |= (sp ? 1u : 0u) << (8 * (e - 4));
        }
        if (br < 2) {
            unsigned v = byte << (8 * (lane & 3));
            v |= __shfl_xor_sync(0xffffffffu, v, 1);
            v |= __shfl_xor_sync(0xffffffffu, v, 2);
            if ((lane & 3) == 0) {
                int g = lane >> 2;
                int head = g >> 2, widx = g & 3;
                uint32_t* dst = (br == 0) ? qb : kb;
                dst[(((size_t)(t * B_ + b) * 2 + head) * L_ + l) * 4 + widx] = v;
            }
        } else {
            int head = lane >> 4;
            int d0 = 8 * (lane & 15);
            uint8_t* dst = vb + ((((size_t)(t * B_ + b) * 2 + head) * L_ + l) * 128 + d0);
            *(uint2*)dst = make_uint2(blo, bhi);
        }
    }
}

__global__ void __launch_bounds__(256, 2) proj_ln_lif_kernel(
    const int* __restrict__ Zp, const float* __restrict__ pb,
    const float* __restrict__ lw, const float* __restrict__ lb,
    float* __restrict__ out)
{
    const int gw = blockIdx.x * 8 + (threadIdx.x >> 5);
    const int lane = threadIdx.x & 31;
    const int b = gw / L_, l = gw % L_;
    const int h0 = lane * 8;

    double w58[8];
    long long bint[8];
    int pbq[8];
    {
        float4 w0 = *(const float4*)(lw + h0), w1 = *(const float4*)(lw + h0 + 4);
        float4 c0 = *(const float4*)(lb + h0), c1 = *(const float4*)(lb + h0 + 4);
        float4 p0 = *(const float4*)(pb + h0), p1 = *(const float4*)(pb + h0 + 4);
        float wa[8] = {w0.x,w0.y,w0.z,w0.w,w1.x,w1.y,w1.z,w1.w};
        float ba[8] = {c0.x,c0.y,c0.z,c0.w,c1.x,c1.y,c1.z,c1.w};
        float pa[8] = {p0.x,p0.y,p0.z,p0.w,p1.x,p1.y,p1.z,p1.w};
        #pragma unroll
        for (int e = 0; e < 8; e++) {
            w58[e]  = (double)wa[e] * P2_58;
            bint[e] = __double2ll_rn((double)ba[e] * P2_31);
            pbq[e]  = __double2int_rn((double)pa[e] * 134217728.0);
        }
    }

    int zi[4][8];
    #pragma unroll
    for (int t = 0; t < T_; t++) {
        const int* zr = Zp + ((size_t)(t * B_ + b) * L_ + l) * H_ + h0;
        int4 p0 = ((const int4*)zr)[0];
        int4 p1 = ((const int4*)zr)[1];
        zi[t][0]=p0.x+pbq[0]; zi[t][1]=p0.y+pbq[1]; zi[t][2]=p0.z+pbq[2]; zi[t][3]=p0.w+pbq[3];
        zi[t][4]=p1.x+pbq[4]; zi[t][5]=p1.y+pbq[5]; zi[t][6]=p1.z+pbq[6]; zi[t][7]=p1.w+pbq[7];
    }

    long long s[4], sq[4];
    #pragma unroll
    for (int t = 0; t < T_; t++) {
        long long a = 0, c = 0;
        #pragma unroll
        for (int e = 0; e < 8; e++) {
            a += zi[t][e];
            c += (long long)zi[t][e] * zi[t][e];
        }
        s[t] = a; sq[t] = c >> 6;
    }
    #pragma unroll
    for (int o = 16; o; o >>= 1) {
        #pragma unroll
        for (int t = 0; t < T_; t++) {
            s[t]  += __shfl_xor_sync(0xffffffffu, s[t],  o);
            sq[t] += __shfl_xor_sync(0xffffffffu, sq[t], o);
        }
    }

    long long vm[8];
    #pragma unroll
    for (int e = 0; e < 8; e++) vm[e] = 0ll;

    #pragma unroll
    for (int t = 0; t < T_; t++) {
        int m_q = (int)((s[t] + 128) >> 8);
        double mean = (double)s[t] * (1.0 / 256.0);
        double var_u = (double)sq[t] * 0.25 - mean * mean;
        double C = newton_rsqrt(var_u + EPS_U);
        float spf[8];
        #pragma unroll
        for (int e = 0; e < 8; e++) {
            long long G = __double_as_longlong(fma(C, w58[e], MAGIC)) - MAGICLL;
            int dv = zi[t][e] - m_q;
            long long Y = (((long long)dv * G) >> 27) + bint[e];
            vm[e] = (vm[e] + Y) >> 1;
            bool sp = vm[e] >= TH_Y;
            if (sp) vm[e] = 0ll;
            spf[e] = sp ? 1.f : 0.f;
        }
        float* dst = out + ((size_t)(t * B_ + b) * L_ + l) * H_ + h0;
        *(float4*)(dst)     = make_float4(spf[0], spf[1], spf[2], spf[3]);
        *(float4*)(dst + 4) = make_float4(spf[4], spf[5], spf[6], spf[7]);
    }
}

// ===================== fused attention + attn-LIF ===========================
// block = (b*2+head, nhalf). Iterates t=0..3 rebuilding frag tiles; PV acc
// maps to fixed (l,d) per thread across t -> LIF membrane in registers
// (fp32 exact: dyadic rationals), writes s2 int8 directly.
#define ATT_SA   0                          // 13*7*512 = 46592
#define ATT_SB   46592                      // 8*7*256  = 14336
#define ATT_SV   60928                      // 200*64   = 12800
#define ATT_SKB  73728                      // 200*16   = 3200
#define ATTN_SMEM 76928

__global__ void __launch_bounds__(256, 2) attn_fused_kernel(
    const uint32_t* __restrict__ qb, const uint32_t* __restrict__ kb,
    const uint8_t* __restrict__ vb, int8_t* __restrict__ s2)
{
    extern __shared__ char smem[];
    char*     sA  = smem + ATT_SA;
    char*     sB  = smem + ATT_SB;
    uint8_t*  sV  = (uint8_t*)(smem + ATT_SV);
    uint32_t* skb = (uint32_t*)(smem + ATT_SKB);

    const int bh = blockIdx.x;          // b*2 + head
    const int b = bh >> 1, head = bh & 1;
    const int nhalf = blockIdx.y;       // 0/1 -> d range [nhalf*64, +64)
    const int tid = threadIdx.x;
    const int warp = tid >> 5, lane = tid & 31;

    float vm[2][8][4];
    #pragma unroll
    for (int mi = 0; mi < 2; mi++)
        #pragma unroll
        for (int n = 0; n < 8; n++)
            #pragma unroll
            for (int r = 0; r < 4; r++) vm[mi][n][r] = 0.f;

    for (int t = 0; t < T_; t++) {
        const size_t batch = ((size_t)(t * B_ + b) * 2 + head);
        const uint32_t* qb_b = qb + batch * L_ * 4;
        const uint32_t* kb_b = kb + batch * L_ * 4;
        const uint8_t*  v_b  = vb + batch * L_ * 128 + nhalf * 64;

        // stage v slice [200][64] u8 + k bitmasks
        for (int i = tid; i < L_ * 4; i += 256) {
            int row = i >> 2, q4 = i & 3;
            ((uint4*)(sV + row * 64))[q4] = *(const uint4*)(v_b + (size_t)row * 128 + q4 * 16);
        }
        for (int i = tid; i < L_ * 4; i += 256) skb[i] = kb_b[i];
        __syncthreads();

        // build B frags: n=dloc (64), k=m (pad 224)
        for (int idx = tid; idx < 64 * 56; idx += 256) {
            int dloc = idx / 56, mg = idx % 56;
            int m0 = mg * 4;
            unsigned w = 0;
            #pragma unroll
            for (int e = 0; e < 4; e++) {
                int m = m0 + e;
                unsigned bv = (m < L_) ? (unsigned)sV[m * 64 + dloc] : 0u;
                w |= bv << (8 * e);
            }
            int tile = (dloc >> 3) * 7 + (m0 >> 5);
            int raw = tile * 256 + ((dloc & 7) * 4 + ((m0 >> 2) & 3)) * 8
                    + ((m0 >> 4) & 1) * 4;
            *(unsigned*)(sB + XS(raw, tile)) = w;
        }

        // build A frags: popcount counts (u8), rows r, k=m
        for (int r = warp; r < L_; r += 8) {
            uint32_t q0 = qb_b[r*4+0], q1 = qb_b[r*4+1];
            uint32_t q2 = qb_b[r*4+2], q3 = qb_b[r*4+3];
            for (int g = lane; g < 50; g += 32) {
                int m0 = g * 4;
                unsigned w = 0;
                #pragma unroll
                for (int e = 0; e < 4; e++) {
                    int m = m0 + e;
                    unsigned c = __popc(q0 & skb[m*4+0]) + __popc(q1 & skb[m*4+1])
                               + __popc(q2 & skb[m*4+2]) + __popc(q3 & skb[m*4+3]);
                    w |= c << (8 * e);
                }
                int tile = (r >> 4) * 7 + (m0 >> 5);
                int raw = tile * 512 + ((r & 7) * 4 + ((m0 >> 2) & 3)) * 16
                        + (((m0 >> 4) & 1) * 2 + ((r >> 3) & 1)) * 4;
                *(unsigned*)(sA + XS(raw, tile)) = w;
            }
        }
        __syncthreads();

        // PV + LIF
        #pragma unroll
        for (int mi = 0; mi < 2; mi++) {
            int mt = warp + 8 * mi;
            if (mt >= 13) break;
            for (int ntile = 0; ntile < 8; ntile++) {
                int acc[4] = {0, 0, 0, 0};
                #pragma unroll
                for (int kc = 0; kc < 7; kc++) {
                    unsigned a[4], bo[2];
                    int ta = mt * 7 + kc;
                    uint4 av = *(const uint4*)(sA + XS((ta * 32 + lane) * 16, ta));
                    a[0] = av.x; a[1] = av.y; a[2] = av.z; a[3] = av.w;
                    int tb = ntile * 7 + kc;
                    uint2 bv = *(const uint2*)(sB + XS((tb * 32 + lane) * 8, tb));
                    bo[0] = bv.x; bo[1] = bv.y;
                    mma_u8(acc, a, bo);
                }
                int r0  = mt * 16 + (lane >> 2);
                int col = head * 128 + nhalf * 64 + ntile * 8 + 2 * (lane & 3);
                #pragma unroll
                for (int r = 0; r < 4; r++) {
                    float yv = (float)acc[r] * 0.125f;
                    float v = (vm[mi][ntile][r] + yv) * 0.5f;
                    bool sp = v >= 0.5f;
                    vm[mi][ntile][r] = sp ? 0.f : v;
                    int row = r0 + 8 * (r >> 1);
                    if (row < L_) {
                        s2[((size_t)(t * B_ + b) * L_ + row) * H_ + col + (r & 1)]
                            = sp ? 1 : 0;
                    }
                }
            }
        }
        __syncthreads();
    }
}

// ---------------------------------------------------------------------------
extern "C" void kernel_launch(void* const* d_in, const int* in_sizes, int n_in,
                              void* d_out, int out_size)
{
    const float* x   = (const float*)d_in[0];
    const float* qw  = (const float*)d_in[1];
    const float* qlw = (const float*)d_in[2];
    const float* qlb = (const float*)d_in[3];
    const float* kw  = (const float*)d_in[4];
    const float* klw = (const float*)d_in[5];
    const float* klb = (const float*)d_in[6];
    const float* vw  = (const float*)d_in[7];
    const float* vlw = (const float*)d_in[8];
    const float* vlb = (const float*)d_in[9];
    const float* pw  = (const float*)d_in[10];
    const float* pb  = (const float*)d_in[11];
    const float* plw = (const float*)d_in[12];
    const float* plb = (const float*)d_in[13];
    float* out = (float*)d_out;

    int8_t *asl, *wsl, *s2;
    uint8_t *vbp;
    int *Zq, *Zk, *Zv, *zp;
    uint32_t *qbp, *kbp;
    cudaGetSymbolAddress((void**)&asl, g_asl);
    cudaGetSymbolAddress((void**)&wsl, g_wsl);
    cudaGetSymbolAddress((void**)&s2,  g_s2);
    cudaGetSymbolAddress((void**)&vbp, g_vb);
    cudaGetSymbolAddress((void**)&Zq,  g_Zq);
    cudaGetSymbolAddress((void**)&Zk,  g_Zk);
    cudaGetSymbolAddress((void**)&Zv,  g_Zv);
    cudaGetSymbolAddress((void**)&zp,  g_zp);
    cudaGetSymbolAddress((void**)&qbp, g_qb);
    cudaGetSymbolAddress((void**)&kbp, g_kb);

    cudaFuncSetAttribute(gemm_qkv_kernel, cudaFuncAttributeMaxDynamicSharedMemorySize, QKV_SMEM);
    cudaFuncSetAttribute(gemm_proj_kernel, cudaFuncAttributeMaxDynamicSharedMemorySize, PROJ_SMEM);
    cudaFuncSetAttribute(attn_fused_kernel, cudaFuncAttributeMaxDynamicSharedMemorySize, ATTN_SMEM);

    slice_x_kernel<<<4096, 256>>>(x, asl);
    slice_w_kernel<<<256, 256>>>(qw, kw, vw, pw, wsl);

    dim3 gq(12, 400);
    gemm_qkv_kernel<<<gq, 256, QKV_SMEM>>>(asl, wsl, Zq, Zk, Zv);

    dim3 gl(BLr / 8, 3);
    ln_lif_qkv_kernel<<<gl, 256>>>(Zq, Zk, Zv, qlw, qlb, klw, klb, vlw, vlb,
                                   qbp, kbp, vbp);

    dim3 ga(B_ * 2, 2);
    attn_fused_kernel<<<ga, 256, ATTN_SMEM>>>(qbp, kbp, vbp, s2);

    dim3 gp(4, 400);
    gemm_proj_kernel<<<gp, 256, PROJ_SMEM>>>(s2, wsl, zp);

    proj_ln_lif_kernel<<<BLr / 8, 256>>>(zp, pb, plw, plb, out);
}